// round 1
// baseline (speedup 1.0000x reference)
#include <cuda_runtime.h>
#include <mma.h>

using namespace nvcuda;

// ---------------------------------------------------------------------------
// Problem constants: B=2, S=2048, D=1024, H=16, hd=64
// ---------------------------------------------------------------------------
// Scratch (allocation-free rule: __device__ globals)
__device__ __align__(256) float g_qkv[4096LL * 3072];          // 50.3 MB  [B*S, 3*D] token-major, per-head [q|k|v]
__device__ __align__(256) float g_logits[32LL * 2048 * 2048];  // 512 MB   [B*H, S, S]
__device__ __align__(256) float g_attn[4096LL * 1024];         // 16.8 MB  [B*S, H*hd]

// ---------------------------------------------------------------------------
// Generic strided-batched tf32 GEMM:  C = A @ op(B)
//   TRANS_B=true : B is [N,K] row-major (compute A @ B^T)
//   TRANS_B=false: B is [K,N] row-major (compute A @ B)
// Batch z decomposed as (zb, zh) = (z/H, z%H) with independent strides, so a
// single kernel covers plain GEMMs and per-(batch,head) slices of g_qkv.
// All launches use exactly divisible tiles -> no bounds checks.
// ---------------------------------------------------------------------------
template <int BM, int BN, int BK, int WARPS_M, int WARPS_N, bool TRANS_B>
__global__ void __launch_bounds__(WARPS_M * WARPS_N * 32, 1)
gemm_tf32_kernel(const float* __restrict__ A, const float* __restrict__ B,
                 float* __restrict__ C,
                 int lda, int ldb, int ldc, int K,
                 long long sAb, long long sAh,
                 long long sBb, long long sBh,
                 long long sCb, long long sCh, int H)
{
    constexpr int NT  = WARPS_M * WARPS_N * 32;
    constexpr int BKP = BK + 4;              // +16B pad vs bank conflicts
    constexpr int WM  = BM / WARPS_M;        // rows per warp
    constexpr int WN  = BN / WARPS_N;        // cols per warp
    constexpr int FM  = WM / 16;
    constexpr int FN  = WN / 16;

    __shared__ __align__(16) float As[BM * BKP];
    __shared__ __align__(16) float Bs[BN * BKP];

    const int z  = blockIdx.z;
    const int zb = z / H;
    const int zh = z - zb * H;
    A += zb * sAb + zh * sAh;
    B += zb * sBb + zh * sBh;
    C += zb * sCb + zh * sCh;

    const int tid  = threadIdx.x;
    const int m0   = blockIdx.y * BM;
    const int n0   = blockIdx.x * BN;
    const int warp = tid >> 5;
    const int wm   = warp % WARPS_M;
    const int wn   = warp / WARPS_M;

    wmma::fragment<wmma::accumulator, 16, 16, 8, float> acc[FM][FN];
    #pragma unroll
    for (int i = 0; i < FM; i++)
        #pragma unroll
        for (int j = 0; j < FN; j++)
            wmma::fill_fragment(acc[i][j], 0.0f);

    for (int k0 = 0; k0 < K; k0 += BK) {
        // --- stage A tile [BM x BK] (row-major, float4) ---
        #pragma unroll
        for (int idx = tid; idx < BM * BK / 4; idx += NT) {
            int r = idx / (BK / 4);
            int c = idx % (BK / 4);
            float4 v = *reinterpret_cast<const float4*>(
                A + (long long)(m0 + r) * lda + k0 + c * 4);
            *reinterpret_cast<float4*>(&As[r * BKP + c * 4]) = v;
        }
        // --- stage B tile, always stored as Bs[n][k] ---
        if (TRANS_B) {
            #pragma unroll
            for (int idx = tid; idx < BN * BK / 4; idx += NT) {
                int r = idx / (BK / 4);
                int c = idx % (BK / 4);
                float4 v = *reinterpret_cast<const float4*>(
                    B + (long long)(n0 + r) * ldb + k0 + c * 4);
                *reinterpret_cast<float4*>(&Bs[r * BKP + c * 4]) = v;
            }
        } else {
            #pragma unroll
            for (int idx = tid; idx < BK * BN / 4; idx += NT) {
                int kk = idx / (BN / 4);
                int n4 = idx % (BN / 4);
                float4 v = *reinterpret_cast<const float4*>(
                    B + (long long)(k0 + kk) * ldb + n0 + n4 * 4);
                Bs[(n4 * 4 + 0) * BKP + kk] = v.x;
                Bs[(n4 * 4 + 1) * BKP + kk] = v.y;
                Bs[(n4 * 4 + 2) * BKP + kk] = v.z;
                Bs[(n4 * 4 + 3) * BKP + kk] = v.w;
            }
        }
        __syncthreads();

        #pragma unroll
        for (int ks = 0; ks < BK; ks += 8) {
            wmma::fragment<wmma::matrix_a, 16, 16, 8, wmma::precision::tf32,
                           wmma::row_major> af[FM];
            wmma::fragment<wmma::matrix_b, 16, 16, 8, wmma::precision::tf32,
                           wmma::col_major> bf[FN];
            #pragma unroll
            for (int i = 0; i < FM; i++) {
                wmma::load_matrix_sync(af[i], &As[(wm * WM + i * 16) * BKP + ks], BKP);
                #pragma unroll
                for (int t = 0; t < af[i].num_elements; t++)
                    af[i].x[t] = wmma::__float_to_tf32(af[i].x[t]);
            }
            #pragma unroll
            for (int j = 0; j < FN; j++) {
                wmma::load_matrix_sync(bf[j], &Bs[(wn * WN + j * 16) * BKP + ks], BKP);
                #pragma unroll
                for (int t = 0; t < bf[j].num_elements; t++)
                    bf[j].x[t] = wmma::__float_to_tf32(bf[j].x[t]);
            }
            #pragma unroll
            for (int i = 0; i < FM; i++)
                #pragma unroll
                for (int j = 0; j < FN; j++)
                    wmma::mma_sync(acc[i][j], af[i], bf[j], acc[i][j]);
        }
        __syncthreads();
    }

    #pragma unroll
    for (int i = 0; i < FM; i++)
        #pragma unroll
        for (int j = 0; j < FN; j++)
            wmma::store_matrix_sync(
                C + (long long)(m0 + wm * WM + i * 16) * ldc + n0 + wn * WN + j * 16,
                acc[i][j], ldc, wmma::mem_row_major);
}

// ---------------------------------------------------------------------------
// Row softmax over 2048-wide rows, scale folded in (one block per row).
// ---------------------------------------------------------------------------
__global__ void __launch_bounds__(256)
softmax_rows_kernel(float* __restrict__ logits, float scale)
{
    float* row = logits + (long long)blockIdx.x * 2048;
    const int t = threadIdx.x;
    __shared__ float red[8];
    __shared__ float s_bcast;

    float v[8];
    float m = -1e30f;
    #pragma unroll
    for (int i = 0; i < 8; i++) {
        v[i] = row[t + i * 256] * scale;
        m = fmaxf(m, v[i]);
    }
    #pragma unroll
    for (int o = 16; o; o >>= 1) m = fmaxf(m, __shfl_xor_sync(0xffffffffu, m, o));
    if ((t & 31) == 0) red[t >> 5] = m;
    __syncthreads();
    if (t == 0) {
        float x = red[0];
        #pragma unroll
        for (int w = 1; w < 8; w++) x = fmaxf(x, red[w]);
        s_bcast = x;
    }
    __syncthreads();
    m = s_bcast;

    float s = 0.0f;
    #pragma unroll
    for (int i = 0; i < 8; i++) {
        v[i] = __expf(v[i] - m);
        s += v[i];
    }
    #pragma unroll
    for (int o = 16; o; o >>= 1) s += __shfl_xor_sync(0xffffffffu, s, o);
    __syncthreads();   // red[] reuse guard
    if ((t & 31) == 0) red[t >> 5] = s;
    __syncthreads();
    if (t == 0) {
        float x = 0.0f;
        #pragma unroll
        for (int w = 0; w < 8; w++) x += red[w];
        s_bcast = 1.0f / x;
    }
    __syncthreads();
    const float inv = s_bcast;
    #pragma unroll
    for (int i = 0; i < 8; i++) row[t + i * 256] = v[i] * inv;
}

// ---------------------------------------------------------------------------
// out[m, n] += bias[n]; grid = (N/256, M)
// ---------------------------------------------------------------------------
__global__ void __launch_bounds__(256)
bias_add_kernel(float* __restrict__ out, const float* __restrict__ bias, int N)
{
    const int n = blockIdx.x * 256 + threadIdx.x;
    const long long idx = (long long)blockIdx.y * N + n;
    out[idx] += bias[n];
}

// ---------------------------------------------------------------------------
// Orchestration. Inputs: x, w_qkv, b_qkv, w_o, b_o (all fp32).
// ---------------------------------------------------------------------------
extern "C" void kernel_launch(void* const* d_in, const int* in_sizes, int n_in,
                              void* d_out, int out_size)
{
    (void)in_sizes; (void)n_in; (void)out_size;
    const float* x     = (const float*)d_in[0];
    const float* w_qkv = (const float*)d_in[1];
    const float* b_qkv = (const float*)d_in[2];
    const float* w_o   = (const float*)d_in[3];
    const float* b_o   = (const float*)d_in[4];
    float* out = (float*)d_out;

    float *qkv, *logits, *attn;
    cudaGetSymbolAddress((void**)&qkv,    g_qkv);
    cudaGetSymbolAddress((void**)&logits, g_logits);
    cudaGetSymbolAddress((void**)&attn,   g_attn);

    // 1) qkv = x @ w_qkv^T            [4096,1024] x [3072,1024]^T -> [4096,3072]
    gemm_tf32_kernel<128, 128, 32, 4, 2, true><<<dim3(3072 / 128, 4096 / 128, 1), 256>>>(
        x, w_qkv, qkv, 1024, 1024, 3072, 1024,
        0, 0, 0, 0, 0, 0, 1);
    bias_add_kernel<<<dim3(3072 / 256, 4096), 256>>>(qkv, b_qkv, 3072);

    // 2) logits[bh] = Q_bh @ K_bh^T   per (b,h): [2048,64] x [2048,64]^T
    //    Q at qkv + h*192 + 0, K at qkv + h*192 + 64, token row stride 3072.
    gemm_tf32_kernel<128, 128, 32, 4, 2, true><<<dim3(16, 16, 32), 256>>>(
        qkv, qkv + 64, logits, 3072, 3072, 2048, 64,
        2048LL * 3072, 192,
        2048LL * 3072, 192,
        16LL * 2048 * 2048, 2048LL * 2048, 16);

    // 3) softmax over keys, scale = 1/sqrt(64)
    softmax_rows_kernel<<<32 * 2048, 256>>>(logits, 0.125f);

    // 4) attn[bh] = P_bh @ V_bh       [2048,2048] x [2048,64] (B stored [K,N])
    gemm_tf32_kernel<128, 64, 32, 4, 2, false><<<dim3(1, 16, 32), 256>>>(
        logits, qkv + 128, attn, 2048, 3072, 1024, 2048,
        16LL * 2048 * 2048, 2048LL * 2048,
        2048LL * 3072, 192,
        2048LL * 1024, 64, 16);

    // 5) out = attn @ w_o^T + b_o     [4096,1024] x [1024,1024]^T
    gemm_tf32_kernel<128, 128, 32, 4, 2, true><<<dim3(1024 / 128, 4096 / 128, 1), 256>>>(
        attn, w_o, out, 1024, 1024, 1024, 1024,
        0, 0, 0, 0, 0, 0, 1);
    bias_add_kernel<<<dim3(1024 / 256, 4096), 256>>>(out, b_o, 1024);
}

// round 2
// speedup vs baseline: 1.1435x; 1.1435x over previous
#include <cuda_runtime.h>
#include <mma.h>

using namespace nvcuda;

// ---------------------------------------------------------------------------
// Problem constants: B=2, S=2048, D=1024, H=16, hd=64
// ---------------------------------------------------------------------------
__device__ __align__(256) float g_qkv[4096LL * 3072];   // [B*S, 3*D] token-major, per-head [q|k|v]
__device__ __align__(256) float g_attn[4096LL * 1024];  // [B*S, H*hd]

// ---------------------------------------------------------------------------
// tf32 GEMM with fused column-bias epilogue:  C = A @ B^T + bias
// (B is [N,K] row-major). Bias folded by initializing accumulator fragments
// from a 16-row replicated bias tile in smem.
// ---------------------------------------------------------------------------
template <int BM, int BN, int BK, int WARPS_M, int WARPS_N>
__global__ void __launch_bounds__(WARPS_M * WARPS_N * 32, 1)
gemm_bias_tf32_kernel(const float* __restrict__ A, const float* __restrict__ B,
                      const float* __restrict__ bias, float* __restrict__ C,
                      int lda, int ldb, int ldc, int K)
{
    constexpr int NT  = WARPS_M * WARPS_N * 32;
    constexpr int BKP = BK + 4;
    constexpr int WM  = BM / WARPS_M;
    constexpr int WN  = BN / WARPS_N;
    constexpr int FM  = WM / 16;
    constexpr int FN  = WN / 16;

    __shared__ __align__(16) float As[BM * BKP];
    __shared__ __align__(16) float Bs[BN * BKP];
    __shared__ __align__(16) float biasrep[16 * BN];

    const int tid  = threadIdx.x;
    const int m0   = blockIdx.y * BM;
    const int n0   = blockIdx.x * BN;
    const int warp = tid >> 5;
    const int wm   = warp % WARPS_M;
    const int wn   = warp / WARPS_M;

    // stage replicated bias tile (16 identical rows)
    #pragma unroll
    for (int idx = tid; idx < 16 * BN; idx += NT)
        biasrep[idx] = bias[n0 + (idx % BN)];
    __syncthreads();

    wmma::fragment<wmma::accumulator, 16, 16, 8, float> acc[FM][FN];
    #pragma unroll
    for (int i = 0; i < FM; i++)
        #pragma unroll
        for (int j = 0; j < FN; j++)
            wmma::load_matrix_sync(acc[i][j], &biasrep[wn * WN + j * 16], BN,
                                   wmma::mem_row_major);
    __syncthreads();

    for (int k0 = 0; k0 < K; k0 += BK) {
        #pragma unroll
        for (int idx = tid; idx < BM * BK / 4; idx += NT) {
            int r = idx / (BK / 4);
            int c = idx % (BK / 4);
            float4 v = *reinterpret_cast<const float4*>(
                A + (long long)(m0 + r) * lda + k0 + c * 4);
            *reinterpret_cast<float4*>(&As[r * BKP + c * 4]) = v;
        }
        #pragma unroll
        for (int idx = tid; idx < BN * BK / 4; idx += NT) {
            int r = idx / (BK / 4);
            int c = idx % (BK / 4);
            float4 v = *reinterpret_cast<const float4*>(
                B + (long long)(n0 + r) * ldb + k0 + c * 4);
            *reinterpret_cast<float4*>(&Bs[r * BKP + c * 4]) = v;
        }
        __syncthreads();

        #pragma unroll
        for (int ks = 0; ks < BK; ks += 8) {
            wmma::fragment<wmma::matrix_a, 16, 16, 8, wmma::precision::tf32,
                           wmma::row_major> af[FM];
            wmma::fragment<wmma::matrix_b, 16, 16, 8, wmma::precision::tf32,
                           wmma::col_major> bf[FN];
            #pragma unroll
            for (int i = 0; i < FM; i++) {
                wmma::load_matrix_sync(af[i], &As[(wm * WM + i * 16) * BKP + ks], BKP);
                #pragma unroll
                for (int t = 0; t < af[i].num_elements; t++)
                    af[i].x[t] = wmma::__float_to_tf32(af[i].x[t]);
            }
            #pragma unroll
            for (int j = 0; j < FN; j++) {
                wmma::load_matrix_sync(bf[j], &Bs[(wn * WN + j * 16) * BKP + ks], BKP);
                #pragma unroll
                for (int t = 0; t < bf[j].num_elements; t++)
                    bf[j].x[t] = wmma::__float_to_tf32(bf[j].x[t]);
            }
            #pragma unroll
            for (int i = 0; i < FM; i++)
                #pragma unroll
                for (int j = 0; j < FN; j++)
                    wmma::mma_sync(acc[i][j], af[i], bf[j], acc[i][j]);
        }
        __syncthreads();
    }

    #pragma unroll
    for (int i = 0; i < FM; i++)
        #pragma unroll
        for (int j = 0; j < FN; j++)
            wmma::store_matrix_sync(
                C + (long long)(m0 + wm * WM + i * 16) * ldc + n0 + wn * WN + j * 16,
                acc[i][j], ldc, wmma::mem_row_major);
}

// ---------------------------------------------------------------------------
// Fused flash attention: one CTA per (bh, 128-row q tile).
// Streams 16 K/V tiles of 128 rows; online softmax; everything in smem.
// 512 threads = 16 warps. Scale (1/8) folded into Q load.
// ---------------------------------------------------------------------------
constexpr int QLD = 68;    // 64 + 4 pad
constexpr int SLD = 132;   // 128 + 4 pad

// smem layout (floats):
//   Qs 128*68 | Ks 128*68 | Vs 128*68 | Os 128*68 | Ss 128*132
//   mrow 128 | lrow 128 | arow 128 | pmax 512 | psum 512
constexpr int FA_SMEM_FLOATS = 4 * 128 * QLD + 128 * SLD + 3 * 128 + 2 * 512;
constexpr int FA_SMEM_BYTES  = FA_SMEM_FLOATS * 4;  // 212,480 B

__global__ void __launch_bounds__(512, 1)
flash_attn_kernel(const float* __restrict__ qkv, float* __restrict__ attn)
{
    extern __shared__ float sm[];
    float* Qs   = sm;
    float* Ks   = Qs + 128 * QLD;
    float* Vs   = Ks + 128 * QLD;
    float* Os   = Vs + 128 * QLD;
    float* Ss   = Os + 128 * QLD;
    float* mrow = Ss + 128 * SLD;
    float* lrow = mrow + 128;
    float* arow = lrow + 128;
    float* pmax = arow + 128;
    float* psum = pmax + 512;

    const int tid = threadIdx.x;
    const int bh  = blockIdx.y;
    const int b   = bh >> 4;
    const int h   = bh & 15;
    const int q0  = blockIdx.x * 128;

    const float* base = qkv + (long long)b * 2048 * 3072 + h * 192;

    // load Q tile (scale 1/8 folded in) + init O, stats
    for (int idx = tid; idx < 128 * 16; idx += 512) {
        int r = idx >> 4, c = (idx & 15) * 4;
        float4 v = *reinterpret_cast<const float4*>(
            base + (long long)(q0 + r) * 3072 + c);
        v.x *= 0.125f; v.y *= 0.125f; v.z *= 0.125f; v.w *= 0.125f;
        *reinterpret_cast<float4*>(&Qs[r * QLD + c]) = v;
    }
    for (int idx = tid; idx < 128 * 64; idx += 512)
        Os[(idx >> 6) * QLD + (idx & 63)] = 0.0f;
    if (tid < 128) { mrow[tid] = -1e30f; lrow[tid] = 0.0f; }

    const int warp = tid >> 5;
    const int wm   = warp & 3;   // 0..3 : 32-row slice
    const int wn   = warp >> 2;  // 0..3 : 32-col slice (QK) / 16-col (PV)

    const int r  = tid & 127;    // softmax row
    const int qq = tid >> 7;     // quarter 0..3 (32 cols each)

    for (int kt = 0; kt < 16; kt++) {
        // ---- load K,V tiles ----
        __syncthreads();
        for (int idx = tid; idx < 128 * 16; idx += 512) {
            int rr = idx >> 4, c = (idx & 15) * 4;
            const float* rowp = base + (long long)(kt * 128 + rr) * 3072 + c;
            *reinterpret_cast<float4*>(&Ks[rr * QLD + c]) =
                *reinterpret_cast<const float4*>(rowp + 64);
            *reinterpret_cast<float4*>(&Vs[rr * QLD + c]) =
                *reinterpret_cast<const float4*>(rowp + 128);
        }
        __syncthreads();

        // ---- S = Q @ K^T (each warp 32x32) ----
        {
            wmma::fragment<wmma::accumulator, 16, 16, 8, float> accS[2][2];
            #pragma unroll
            for (int i = 0; i < 2; i++)
                #pragma unroll
                for (int j = 0; j < 2; j++)
                    wmma::fill_fragment(accS[i][j], 0.0f);
            #pragma unroll
            for (int ks = 0; ks < 64; ks += 8) {
                wmma::fragment<wmma::matrix_a, 16, 16, 8, wmma::precision::tf32,
                               wmma::row_major> af[2];
                wmma::fragment<wmma::matrix_b, 16, 16, 8, wmma::precision::tf32,
                               wmma::col_major> bf[2];
                #pragma unroll
                for (int i = 0; i < 2; i++) {
                    wmma::load_matrix_sync(af[i], &Qs[(wm * 32 + i * 16) * QLD + ks], QLD);
                    #pragma unroll
                    for (int t = 0; t < af[i].num_elements; t++)
                        af[i].x[t] = wmma::__float_to_tf32(af[i].x[t]);
                }
                #pragma unroll
                for (int j = 0; j < 2; j++) {
                    wmma::load_matrix_sync(bf[j], &Ks[(wn * 32 + j * 16) * QLD + ks], QLD);
                    #pragma unroll
                    for (int t = 0; t < bf[j].num_elements; t++)
                        bf[j].x[t] = wmma::__float_to_tf32(bf[j].x[t]);
                }
                #pragma unroll
                for (int i = 0; i < 2; i++)
                    #pragma unroll
                    for (int j = 0; j < 2; j++)
                        wmma::mma_sync(accS[i][j], af[i], bf[j], accS[i][j]);
            }
            #pragma unroll
            for (int i = 0; i < 2; i++)
                #pragma unroll
                for (int j = 0; j < 2; j++)
                    wmma::store_matrix_sync(
                        &Ss[(wm * 32 + i * 16) * SLD + wn * 32 + j * 16],
                        accS[i][j], SLD, wmma::mem_row_major);
        }
        __syncthreads();

        // ---- online softmax (already scaled) ----
        float* srow = Ss + r * SLD + qq * 32;
        {
            float mx = -1e30f;
            #pragma unroll
            for (int c = 0; c < 32; c++) mx = fmaxf(mx, srow[c]);
            pmax[qq * 128 + r] = mx;
        }
        __syncthreads();
        const float mold = mrow[r];
        float mnew = fmaxf(fmaxf(pmax[r], pmax[128 + r]),
                           fmaxf(pmax[256 + r], pmax[384 + r]));
        mnew = fmaxf(mold, mnew);
        {
            float s = 0.0f;
            #pragma unroll
            for (int c = 0; c < 32; c++) {
                float p = __expf(srow[c] - mnew);
                srow[c] = p;
                s += p;
            }
            psum[qq * 128 + r] = s;
        }
        __syncthreads();
        if (qq == 0) {
            float alpha = __expf(mold - mnew);
            lrow[r] = lrow[r] * alpha + psum[r] + psum[128 + r] + psum[256 + r] + psum[384 + r];
            mrow[r] = mnew;
            arow[r] = alpha;
        }
        __syncthreads();

        // ---- rescale O accumulator ----
        for (int idx = tid; idx < 128 * 64; idx += 512) {
            int rr = idx >> 6, c = idx & 63;
            Os[rr * QLD + c] *= arow[rr];
        }
        __syncthreads();

        // ---- O += P @ V (each warp 32x16) ----
        {
            wmma::fragment<wmma::accumulator, 16, 16, 8, float> accO[2];
            #pragma unroll
            for (int i = 0; i < 2; i++)
                wmma::load_matrix_sync(accO[i],
                    &Os[(wm * 32 + i * 16) * QLD + wn * 16], QLD,
                    wmma::mem_row_major);
            #pragma unroll
            for (int kk = 0; kk < 128; kk += 8) {
                wmma::fragment<wmma::matrix_a, 16, 16, 8, wmma::precision::tf32,
                               wmma::row_major> af[2];
                wmma::fragment<wmma::matrix_b, 16, 16, 8, wmma::precision::tf32,
                               wmma::row_major> bf;
                #pragma unroll
                for (int i = 0; i < 2; i++) {
                    wmma::load_matrix_sync(af[i], &Ss[(wm * 32 + i * 16) * SLD + kk], SLD);
                    #pragma unroll
                    for (int t = 0; t < af[i].num_elements; t++)
                        af[i].x[t] = wmma::__float_to_tf32(af[i].x[t]);
                }
                wmma::load_matrix_sync(bf, &Vs[kk * QLD + wn * 16], QLD);
                #pragma unroll
                for (int t = 0; t < bf.num_elements; t++)
                    bf.x[t] = wmma::__float_to_tf32(bf.x[t]);
                #pragma unroll
                for (int i = 0; i < 2; i++)
                    wmma::mma_sync(accO[i], af[i], bf, accO[i]);
            }
            #pragma unroll
            for (int i = 0; i < 2; i++)
                wmma::store_matrix_sync(&Os[(wm * 32 + i * 16) * QLD + wn * 16],
                                        accO[i], QLD, wmma::mem_row_major);
        }
        __syncthreads();
    }

    // ---- normalize + write out ----
    for (int idx = tid; idx < 128 * 16; idx += 512) {
        int rr = idx >> 4, c = (idx & 15) * 4;
        float inv = 1.0f / lrow[rr];
        float4 v = *reinterpret_cast<const float4*>(&Os[rr * QLD + c]);
        v.x *= inv; v.y *= inv; v.z *= inv; v.w *= inv;
        *reinterpret_cast<float4*>(
            attn + (long long)(b * 2048 + q0 + rr) * 1024 + h * 64 + c) = v;
    }
}

// ---------------------------------------------------------------------------
// Orchestration. Inputs: x, w_qkv, b_qkv, w_o, b_o (all fp32).
// ---------------------------------------------------------------------------
extern "C" void kernel_launch(void* const* d_in, const int* in_sizes, int n_in,
                              void* d_out, int out_size)
{
    (void)in_sizes; (void)n_in; (void)out_size;
    const float* x     = (const float*)d_in[0];
    const float* w_qkv = (const float*)d_in[1];
    const float* b_qkv = (const float*)d_in[2];
    const float* w_o   = (const float*)d_in[3];
    const float* b_o   = (const float*)d_in[4];
    float* out = (float*)d_out;

    float *qkv, *attn;
    cudaGetSymbolAddress((void**)&qkv,  g_qkv);
    cudaGetSymbolAddress((void**)&attn, g_attn);

    cudaFuncSetAttribute(flash_attn_kernel,
                         cudaFuncAttributeMaxDynamicSharedMemorySize,
                         FA_SMEM_BYTES);

    // 1) qkv = x @ w_qkv^T + b_qkv   [4096,1024]x[3072,1024]^T -> [4096,3072]
    gemm_bias_tf32_kernel<128, 128, 32, 4, 2><<<dim3(24, 32), 256>>>(
        x, w_qkv, b_qkv, qkv, 1024, 1024, 3072, 1024);

    // 2) fused attention -> attn [4096, 1024]
    flash_attn_kernel<<<dim3(16, 32), 512, FA_SMEM_BYTES>>>(qkv, attn);

    // 3) out = attn @ w_o^T + b_o    [4096,1024]x[1024,1024]^T
    gemm_bias_tf32_kernel<128, 128, 32, 4, 2><<<dim3(8, 32), 256>>>(
        attn, w_o, b_o, out, 1024, 1024, 1024, 1024);
}

// round 3
// speedup vs baseline: 1.2295x; 1.0752x over previous
#include <cuda_runtime.h>
#include <mma.h>

using namespace nvcuda;

// ---------------------------------------------------------------------------
// Problem constants: B=2, S=2048, D=1024, H=16, hd=64
// ---------------------------------------------------------------------------
__device__ __align__(256) float g_qkv[4096LL * 3072];   // [B*S, 3*D] per-head [q|k|v]
__device__ __align__(256) float g_attn[4096LL * 1024];  // [B*S, H*hd]

// --- cp.async helpers ---
__device__ __forceinline__ unsigned smem_u32(const void* p) {
    return (unsigned)__cvta_generic_to_shared(p);
}
#define CP_ASYNC16(dst_u32, src_ptr)                                        \
    asm volatile("cp.async.cg.shared.global [%0], [%1], 16;\n" ::           \
                 "r"(dst_u32), "l"(src_ptr))
#define CP_COMMIT() asm volatile("cp.async.commit_group;\n" ::: "memory")
#define CP_WAIT(n)  asm volatile("cp.async.wait_group %0;\n" :: "n"(n) : "memory")

// ---------------------------------------------------------------------------
// tf32 GEMM, C = A @ B^T + bias (B is [N,K] row-major).
// Register-prefetch double-buffered smem pipeline; tf32 conversion done once
// at staging time so the inner loop is pure LDS + HMMA. One sync per k-tile.
// ---------------------------------------------------------------------------
constexpr int GBM = 128, GBN = 128, GBK = 32;
constexpr int GBKP = GBK + 4;
constexpr int GEMM_SMEM = (2 * GBM * GBKP + 2 * GBN * GBKP + 16 * GBN) * 4;  // 81,920 B

__global__ void __launch_bounds__(256, 1)
gemm_bias_tf32_kernel(const float* __restrict__ A, const float* __restrict__ B,
                      const float* __restrict__ bias, float* __restrict__ C,
                      int lda, int ldb, int ldc, int K)
{
    constexpr int NT = 256;
    constexpr int WM = 32, WN = 64;   // warp tile (4x2 warps)
    constexpr int FM = 2,  FN = 4;

    extern __shared__ float gsm[];
    float* As      = gsm;                       // 2 * GBM*GBKP
    float* Bs      = As + 2 * GBM * GBKP;       // 2 * GBN*GBKP
    float* biasrep = Bs + 2 * GBN * GBKP;       // 16 * GBN

    const int tid  = threadIdx.x;
    const int m0   = blockIdx.y * GBM;
    const int n0   = blockIdx.x * GBN;
    const int warp = tid >> 5;
    const int wm   = warp & 3;
    const int wn   = warp >> 2;

    #pragma unroll
    for (int idx = tid; idx < 16 * GBN; idx += NT)
        biasrep[idx] = bias[n0 + (idx % GBN)];
    __syncthreads();

    wmma::fragment<wmma::accumulator, 16, 16, 8, float> acc[FM][FN];
    #pragma unroll
    for (int i = 0; i < FM; i++)
        #pragma unroll
        for (int j = 0; j < FN; j++)
            wmma::load_matrix_sync(acc[i][j], &biasrep[wn * WN + j * 16], GBN,
                                   wmma::mem_row_major);

    // per-thread staging coords: 4 float4 per tile per operand
    float4 ra[4], rb[4];

    auto load_tile = [&](int k0) {
        #pragma unroll
        for (int i = 0; i < 4; i++) {
            int idx = tid + i * NT;
            int r = idx >> 3, c = (idx & 7) * 4;
            ra[i] = *reinterpret_cast<const float4*>(
                A + (long long)(m0 + r) * lda + k0 + c);
            rb[i] = *reinterpret_cast<const float4*>(
                B + (long long)(n0 + r) * ldb + k0 + c);
        }
    };
    auto store_tile = [&](int p) {
        float* Asp = As + p * GBM * GBKP;
        float* Bsp = Bs + p * GBN * GBKP;
        #pragma unroll
        for (int i = 0; i < 4; i++) {
            int idx = tid + i * NT;
            int r = idx >> 3, c = (idx & 7) * 4;
            float4 va = ra[i], vb = rb[i];
            va.x = wmma::__float_to_tf32(va.x); va.y = wmma::__float_to_tf32(va.y);
            va.z = wmma::__float_to_tf32(va.z); va.w = wmma::__float_to_tf32(va.w);
            vb.x = wmma::__float_to_tf32(vb.x); vb.y = wmma::__float_to_tf32(vb.y);
            vb.z = wmma::__float_to_tf32(vb.z); vb.w = wmma::__float_to_tf32(vb.w);
            *reinterpret_cast<float4*>(&Asp[r * GBKP + c]) = va;
            *reinterpret_cast<float4*>(&Bsp[r * GBKP + c]) = vb;
        }
    };

    load_tile(0);
    store_tile(0);
    __syncthreads();

    int p = 0;
    for (int k0 = 0; k0 < K; k0 += GBK) {
        const bool has_next = (k0 + GBK) < K;
        if (has_next) load_tile(k0 + GBK);   // LDGs in flight during mma

        const float* Asp = As + p * GBM * GBKP;
        const float* Bsp = Bs + p * GBN * GBKP;
        #pragma unroll
        for (int ks = 0; ks < GBK; ks += 8) {
            wmma::fragment<wmma::matrix_a, 16, 16, 8, wmma::precision::tf32,
                           wmma::row_major> af[FM];
            wmma::fragment<wmma::matrix_b, 16, 16, 8, wmma::precision::tf32,
                           wmma::col_major> bf[FN];
            #pragma unroll
            for (int i = 0; i < FM; i++)
                wmma::load_matrix_sync(af[i], &Asp[(wm * WM + i * 16) * GBKP + ks], GBKP);
            #pragma unroll
            for (int j = 0; j < FN; j++)
                wmma::load_matrix_sync(bf[j], &Bsp[(wn * WN + j * 16) * GBKP + ks], GBKP);
            #pragma unroll
            for (int i = 0; i < FM; i++)
                #pragma unroll
                for (int j = 0; j < FN; j++)
                    wmma::mma_sync(acc[i][j], af[i], bf[j], acc[i][j]);
        }
        if (has_next) store_tile(p ^ 1);
        __syncthreads();
        p ^= 1;
    }

    #pragma unroll
    for (int i = 0; i < FM; i++)
        #pragma unroll
        for (int j = 0; j < FN; j++)
            wmma::store_matrix_sync(
                C + (long long)(m0 + wm * WM + i * 16) * ldc + n0 + wn * WN + j * 16,
                acc[i][j], ldc, wmma::mem_row_major);
}

// ---------------------------------------------------------------------------
// Fused flash attention. One CTA per (bh, 128-row q tile), 512 threads.
//  - O accumulator lives in registers for all 16 k-tiles (row-index fragment
//    trick recovers per-element rows for rescale/normalize).
//  - cp.async pipeline: V(kt) prefetched during QK^T, K(kt+1) during softmax.
//  - shfl-based online softmax (4 lanes per row), 3 syncthreads per k-tile.
// ---------------------------------------------------------------------------
constexpr int QLD = 68;    // 64 + 4 pad
constexpr int SLD = 132;   // 128 + 4 pad
constexpr int FA_SMEM_FLOATS = 3 * 128 * QLD + 128 * SLD + 3 * 128 + 256;
constexpr int FA_SMEM_BYTES  = FA_SMEM_FLOATS * 4;  // 174,592 B

__global__ void __launch_bounds__(512, 1)
flash_attn_kernel(const float* __restrict__ qkv, float* __restrict__ attn)
{
    extern __shared__ float sm[];
    float* Qs      = sm;                  // 128*QLD
    float* Ks      = Qs + 128 * QLD;
    float* Vs      = Ks + 128 * QLD;
    float* Ss      = Vs + 128 * QLD;      // 128*SLD
    float* mrow    = Ss + 128 * SLD;
    float* lrow    = mrow + 128;
    float* arow    = lrow + 128;
    float* rowinit = arow + 128;          // 16x16

    const int tid = threadIdx.x;
    const int bh  = blockIdx.y;
    const int b   = bh >> 4;
    const int h   = bh & 15;
    const int q0  = blockIdx.x * 128;

    const float* base = qkv + (long long)b * 2048 * 3072 + h * 192;

    // issue K(0) prefetch
    #pragma unroll
    for (int i = 0; i < 4; i++) {
        int idx = tid + i * 512;
        int rr = idx >> 4, c = (idx & 15) * 4;
        CP_ASYNC16(smem_u32(&Ks[rr * QLD + c]),
                   base + (long long)rr * 3072 + 64 + c);
    }
    CP_COMMIT();

    // Q tile (scale folded), stats, row-index tile
    for (int idx = tid; idx < 128 * 16; idx += 512) {
        int r = idx >> 4, c = (idx & 15) * 4;
        float4 v = *reinterpret_cast<const float4*>(
            base + (long long)(q0 + r) * 3072 + c);
        v.x *= 0.125f; v.y *= 0.125f; v.z *= 0.125f; v.w *= 0.125f;
        *reinterpret_cast<float4*>(&Qs[r * QLD + c]) = v;
    }
    if (tid < 128) { mrow[tid] = -1e30f; lrow[tid] = 0.0f; }
    if (tid < 256) rowinit[tid] = (float)(tid >> 4);
    __syncthreads();

    const int warp = tid >> 5;
    const int wm   = warp & 3;    // 32-row slice
    const int wn   = warp >> 2;   // 32-col (QK) / 16-col (PV) slice

    // recover accumulator-fragment row mapping
    wmma::fragment<wmma::accumulator, 16, 16, 8, float> rowf;
    wmma::load_matrix_sync(rowf, rowinit, 16, wmma::mem_row_major);
    int relrow[8];
    #pragma unroll
    for (int t = 0; t < 8; t++) relrow[t] = wm * 32 + (int)rowf.x[t];

    wmma::fragment<wmma::accumulator, 16, 16, 8, float> accO[2];
    #pragma unroll
    for (int i = 0; i < 2; i++) wmma::fill_fragment(accO[i], 0.0f);

    const int srow_r  = tid >> 2;       // softmax row
    const int lane4   = tid & 3;        // 32-col chunk within row

    for (int kt = 0; kt < 16; kt++) {
        CP_WAIT(0);          // K(kt) resident
        __syncthreads();     // also: Vs free (prev PV done), Ss free

        // prefetch V(kt) during QK
        #pragma unroll
        for (int i = 0; i < 4; i++) {
            int idx = tid + i * 512;
            int rr = idx >> 4, c = (idx & 15) * 4;
            CP_ASYNC16(smem_u32(&Vs[rr * QLD + c]),
                       base + (long long)(kt * 128 + rr) * 3072 + 128 + c);
        }
        CP_COMMIT();   // group: V

        // ---- S = Q @ K^T (warp: 32x32) ----
        {
            wmma::fragment<wmma::accumulator, 16, 16, 8, float> accS[2][2];
            #pragma unroll
            for (int i = 0; i < 2; i++)
                #pragma unroll
                for (int j = 0; j < 2; j++)
                    wmma::fill_fragment(accS[i][j], 0.0f);
            #pragma unroll
            for (int ks = 0; ks < 64; ks += 8) {
                wmma::fragment<wmma::matrix_a, 16, 16, 8, wmma::precision::tf32,
                               wmma::row_major> af[2];
                wmma::fragment<wmma::matrix_b, 16, 16, 8, wmma::precision::tf32,
                               wmma::col_major> bf[2];
                #pragma unroll
                for (int i = 0; i < 2; i++) {
                    wmma::load_matrix_sync(af[i], &Qs[(wm * 32 + i * 16) * QLD + ks], QLD);
                    #pragma unroll
                    for (int t = 0; t < af[i].num_elements; t++)
                        af[i].x[t] = wmma::__float_to_tf32(af[i].x[t]);
                }
                #pragma unroll
                for (int j = 0; j < 2; j++) {
                    wmma::load_matrix_sync(bf[j], &Ks[(wn * 32 + j * 16) * QLD + ks], QLD);
                    #pragma unroll
                    for (int t = 0; t < bf[j].num_elements; t++)
                        bf[j].x[t] = wmma::__float_to_tf32(bf[j].x[t]);
                }
                #pragma unroll
                for (int i = 0; i < 2; i++)
                    #pragma unroll
                    for (int j = 0; j < 2; j++)
                        wmma::mma_sync(accS[i][j], af[i], bf[j], accS[i][j]);
            }
            #pragma unroll
            for (int i = 0; i < 2; i++)
                #pragma unroll
                for (int j = 0; j < 2; j++)
                    wmma::store_matrix_sync(
                        &Ss[(wm * 32 + i * 16) * SLD + wn * 32 + j * 16],
                        accS[i][j], SLD, wmma::mem_row_major);
        }
        __syncthreads();   // S visible to softmax; Ks free for prefetch

        // prefetch K(kt+1) during softmax
        if (kt < 15) {
            #pragma unroll
            for (int i = 0; i < 4; i++) {
                int idx = tid + i * 512;
                int rr = idx >> 4, c = (idx & 15) * 4;
                CP_ASYNC16(smem_u32(&Ks[rr * QLD + c]),
                           base + (long long)((kt + 1) * 128 + rr) * 3072 + 64 + c);
            }
        }
        CP_COMMIT();   // group: K (possibly empty on kt==15)

        // ---- online softmax: 4 lanes per row, shfl reductions ----
        {
            float* srow = Ss + srow_r * SLD + lane4 * 32;
            const float mold = mrow[srow_r];
            float mx = -1e30f;
            #pragma unroll
            for (int c = 0; c < 32; c++) mx = fmaxf(mx, srow[c]);
            mx = fmaxf(mx, __shfl_xor_sync(0xffffffffu, mx, 1));
            mx = fmaxf(mx, __shfl_xor_sync(0xffffffffu, mx, 2));
            const float mnew = fmaxf(mold, mx);
            float s = 0.0f;
            #pragma unroll
            for (int c = 0; c < 32; c++) {
                float pv = __expf(srow[c] - mnew);
                srow[c] = pv;
                s += pv;
            }
            s += __shfl_xor_sync(0xffffffffu, s, 1);
            s += __shfl_xor_sync(0xffffffffu, s, 2);
            if (lane4 == 0) {
                float al = __expf(mold - mnew);
                arow[srow_r] = al;
                lrow[srow_r] = lrow[srow_r] * al + s;
                mrow[srow_r] = mnew;
            }
        }
        CP_WAIT(1);        // V(kt) done (K(kt+1) may remain in flight)
        __syncthreads();   // P + arow visible; Vs ready

        // ---- rescale O (registers) then O += P @ V (warp: 32x16) ----
        #pragma unroll
        for (int i = 0; i < 2; i++)
            #pragma unroll
            for (int t = 0; t < 8; t++)
                accO[i].x[t] *= arow[relrow[t] + i * 16];
        #pragma unroll
        for (int kk = 0; kk < 128; kk += 8) {
            wmma::fragment<wmma::matrix_a, 16, 16, 8, wmma::precision::tf32,
                           wmma::row_major> af[2];
            wmma::fragment<wmma::matrix_b, 16, 16, 8, wmma::precision::tf32,
                           wmma::row_major> bf;
            #pragma unroll
            for (int i = 0; i < 2; i++) {
                wmma::load_matrix_sync(af[i], &Ss[(wm * 32 + i * 16) * SLD + kk], SLD);
                #pragma unroll
                for (int t = 0; t < af[i].num_elements; t++)
                    af[i].x[t] = wmma::__float_to_tf32(af[i].x[t]);
            }
            wmma::load_matrix_sync(bf, &Vs[kk * QLD + wn * 16], QLD);
            #pragma unroll
            for (int t = 0; t < bf.num_elements; t++)
                bf.x[t] = wmma::__float_to_tf32(bf.x[t]);
            #pragma unroll
            for (int i = 0; i < 2; i++)
                wmma::mma_sync(accO[i], af[i], bf, accO[i]);
        }
    }

    __syncthreads();   // all PV reads of Ss complete before staging reuse

    // normalize in registers, stage through Ss, write out
    #pragma unroll
    for (int i = 0; i < 2; i++) {
        #pragma unroll
        for (int t = 0; t < 8; t++)
            accO[i].x[t] *= __frcp_rn(lrow[relrow[t] + i * 16]);
        wmma::store_matrix_sync(&Ss[(wm * 32 + i * 16) * SLD + wn * 16],
                                accO[i], SLD, wmma::mem_row_major);
    }
    __syncthreads();
    for (int idx = tid; idx < 128 * 16; idx += 512) {
        int rr = idx >> 4, c = (idx & 15) * 4;
        float4 v = *reinterpret_cast<const float4*>(&Ss[rr * SLD + c]);
        *reinterpret_cast<float4*>(
            attn + (long long)(b * 2048 + q0 + rr) * 1024 + h * 64 + c) = v;
    }
}

// ---------------------------------------------------------------------------
// Orchestration. Inputs: x, w_qkv, b_qkv, w_o, b_o (all fp32).
// ---------------------------------------------------------------------------
extern "C" void kernel_launch(void* const* d_in, const int* in_sizes, int n_in,
                              void* d_out, int out_size)
{
    (void)in_sizes; (void)n_in; (void)out_size;
    const float* x     = (const float*)d_in[0];
    const float* w_qkv = (const float*)d_in[1];
    const float* b_qkv = (const float*)d_in[2];
    const float* w_o   = (const float*)d_in[3];
    const float* b_o   = (const float*)d_in[4];
    float* out = (float*)d_out;

    float *qkv, *attn;
    cudaGetSymbolAddress((void**)&qkv,  g_qkv);
    cudaGetSymbolAddress((void**)&attn, g_attn);

    cudaFuncSetAttribute(gemm_bias_tf32_kernel,
                         cudaFuncAttributeMaxDynamicSharedMemorySize, GEMM_SMEM);
    cudaFuncSetAttribute(flash_attn_kernel,
                         cudaFuncAttributeMaxDynamicSharedMemorySize, FA_SMEM_BYTES);

    // 1) qkv = x @ w_qkv^T + b_qkv   [4096,1024]x[3072,1024]^T
    gemm_bias_tf32_kernel<<<dim3(24, 32), 256, GEMM_SMEM>>>(
        x, w_qkv, b_qkv, qkv, 1024, 1024, 3072, 1024);

    // 2) fused attention -> attn [4096, 1024]
    flash_attn_kernel<<<dim3(16, 32), 512, FA_SMEM_BYTES>>>(qkv, attn);

    // 3) out = attn @ w_o^T + b_o    [4096,1024]x[1024,1024]^T
    gemm_bias_tf32_kernel<<<dim3(8, 32), 256, GEMM_SMEM>>>(
        attn, w_o, b_o, out, 1024, 1024, 1024, 1024);
}

// round 5
// speedup vs baseline: 1.4516x; 1.1807x over previous
#include <cuda_runtime.h>
#include <cuda_fp16.h>
#include <mma.h>

using namespace nvcuda;

// ---------------------------------------------------------------------------
// Problem constants: B=2, S=2048, D=1024, H=16, hd=64
// ---------------------------------------------------------------------------
__device__ __align__(256) float g_qkv[4096LL * 3072];   // [B*S, 3*D] per-head [q|k|v]
__device__ __align__(256) float g_attn[4096LL * 1024];  // [B*S, H*hd]

__device__ __forceinline__ float fexp2(float x) {
    float r;
    asm("ex2.approx.ftz.f32 %0, %1;" : "=f"(r) : "f"(x));
    return r;
}

// ---------------------------------------------------------------------------
// tf32 GEMM, C = A @ B^T + bias (B is [N,K] row-major). 512 threads,
// 32x32 warp tiles (16 warps), double-buffered smem, tf32 conversion done
// once at staging -> inner loop is pure LDS + HMMA.
// ---------------------------------------------------------------------------
constexpr int GBM = 128, GBN = 128, GBK = 32;
constexpr int GBKP = GBK + 4;
constexpr int GEMM_SMEM = (2 * GBM * GBKP + 2 * GBN * GBKP + 16 * GBN) * 4;  // 81,920 B

__global__ void __launch_bounds__(512, 1)
gemm_bias_tf32_kernel(const float* __restrict__ A, const float* __restrict__ B,
                      const float* __restrict__ bias, float* __restrict__ C,
                      int lda, int ldb, int ldc, int K)
{
    constexpr int NT = 512;
    constexpr int FM = 2, FN = 2;   // 32x32 warp tile

    extern __shared__ float gsm[];
    float* As      = gsm;
    float* Bs      = As + 2 * GBM * GBKP;
    float* biasrep = Bs + 2 * GBN * GBKP;

    const int tid  = threadIdx.x;
    const int m0   = blockIdx.y * GBM;
    const int n0   = blockIdx.x * GBN;
    const int warp = tid >> 5;
    const int wm   = warp & 3;    // 0..3
    const int wn   = warp >> 2;   // 0..3

    #pragma unroll
    for (int idx = tid; idx < 16 * GBN; idx += NT)
        biasrep[idx] = bias[n0 + (idx % GBN)];
    __syncthreads();

    wmma::fragment<wmma::accumulator, 16, 16, 8, float> acc[FM][FN];
    #pragma unroll
    for (int i = 0; i < FM; i++)
        #pragma unroll
        for (int j = 0; j < FN; j++)
            wmma::load_matrix_sync(acc[i][j], &biasrep[wn * 32 + j * 16], GBN,
                                   wmma::mem_row_major);

    float4 ra[2], rb[2];   // 2 float4 per operand per thread (128x32 tile)

    auto load_tile = [&](int k0) {
        #pragma unroll
        for (int i = 0; i < 2; i++) {
            int idx = tid + i * NT;
            int r = idx >> 3, c = (idx & 7) * 4;
            ra[i] = *reinterpret_cast<const float4*>(
                A + (long long)(m0 + r) * lda + k0 + c);
            rb[i] = *reinterpret_cast<const float4*>(
                B + (long long)(n0 + r) * ldb + k0 + c);
        }
    };
    auto store_tile = [&](int p) {
        float* Asp = As + p * GBM * GBKP;
        float* Bsp = Bs + p * GBN * GBKP;
        #pragma unroll
        for (int i = 0; i < 2; i++) {
            int idx = tid + i * NT;
            int r = idx >> 3, c = (idx & 7) * 4;
            float4 va = ra[i], vb = rb[i];
            va.x = wmma::__float_to_tf32(va.x); va.y = wmma::__float_to_tf32(va.y);
            va.z = wmma::__float_to_tf32(va.z); va.w = wmma::__float_to_tf32(va.w);
            vb.x = wmma::__float_to_tf32(vb.x); vb.y = wmma::__float_to_tf32(vb.y);
            vb.z = wmma::__float_to_tf32(vb.z); vb.w = wmma::__float_to_tf32(vb.w);
            *reinterpret_cast<float4*>(&Asp[r * GBKP + c]) = va;
            *reinterpret_cast<float4*>(&Bsp[r * GBKP + c]) = vb;
        }
    };

    load_tile(0);
    store_tile(0);
    __syncthreads();

    int p = 0;
    for (int k0 = 0; k0 < K; k0 += GBK) {
        const bool has_next = (k0 + GBK) < K;
        if (has_next) load_tile(k0 + GBK);

        const float* Asp = As + p * GBM * GBKP;
        const float* Bsp = Bs + p * GBN * GBKP;
        #pragma unroll
        for (int ks = 0; ks < GBK; ks += 8) {
            wmma::fragment<wmma::matrix_a, 16, 16, 8, wmma::precision::tf32,
                           wmma::row_major> af[FM];
            wmma::fragment<wmma::matrix_b, 16, 16, 8, wmma::precision::tf32,
                           wmma::col_major> bf[FN];
            #pragma unroll
            for (int i = 0; i < FM; i++)
                wmma::load_matrix_sync(af[i], &Asp[(wm * 32 + i * 16) * GBKP + ks], GBKP);
            #pragma unroll
            for (int j = 0; j < FN; j++)
                wmma::load_matrix_sync(bf[j], &Bsp[(wn * 32 + j * 16) * GBKP + ks], GBKP);
            #pragma unroll
            for (int i = 0; i < FM; i++)
                #pragma unroll
                for (int j = 0; j < FN; j++)
                    wmma::mma_sync(acc[i][j], af[i], bf[j], acc[i][j]);
        }
        if (has_next) store_tile(p ^ 1);
        __syncthreads();
        p ^= 1;
    }

    #pragma unroll
    for (int i = 0; i < FM; i++)
        #pragma unroll
        for (int j = 0; j < FN; j++)
            wmma::store_matrix_sync(
                C + (long long)(m0 + wm * 32 + i * 16) * ldc + n0 + wn * 32 + j * 16,
                acc[i][j], ldc, wmma::mem_row_major);
}

// ---------------------------------------------------------------------------
// Fused flash attention. One CTA per (bh, 128-row q tile), 512 threads.
//  - Q/K pre-converted to tf32 in smem (no inner-loop cvt). Scale*log2e
//    folded into Q; softmax uses ex2 directly.
//  - P written as fp16; V staged as fp16; PV uses m16n16k16 fp16 MMA.
//  - O accumulator in registers (row-index fragment trick for rescale).
//  - LDG->reg->STS overlap: V(kt) loads during QK, K(kt+1) during softmax/PV.
// ---------------------------------------------------------------------------
constexpr int QLD  = 68;    // f32, 64 + 4 pad
constexpr int SLD  = 132;   // f32, 128 + 4 pad
constexpr int SHLD = 136;   // f16, 128 + 8 pad
constexpr int VHLD = 72;    // f16, 64 + 8 pad

constexpr int FA_F32  = 2 * 128 * QLD + 128 * SLD + 3 * 128 + 256;  // 34,944 floats
constexpr int FA_F16  = 128 * SHLD + 128 * VHLD;                    // 26,624 halves
constexpr int FA_SMEM_BYTES = FA_F32 * 4 + FA_F16 * 2;              // 193,024 B

__global__ void __launch_bounds__(512, 1)
flash_attn_kernel(const float* __restrict__ qkv, float* __restrict__ attn)
{
    extern __shared__ float sm[];
    float* Qs      = sm;                 // 128*QLD  (tf32)
    float* Ks      = Qs + 128 * QLD;     // 128*QLD  (tf32)
    float* Ss      = Ks + 128 * QLD;     // 128*SLD  (f32 logits)
    float* mrow    = Ss + 128 * SLD;
    float* lrow    = mrow + 128;
    float* arow    = lrow + 128;
    float* rowinit = arow + 128;         // 16x16
    __half* Sh = reinterpret_cast<__half*>(sm + FA_F32);   // 128*SHLD (P, f16)
    __half* Vh = Sh + 128 * SHLD;                          // 128*VHLD (V, f16)

    const int tid = threadIdx.x;
    const int bh  = blockIdx.y;
    const int b   = bh >> 4;
    const int h   = bh & 15;
    const int q0  = blockIdx.x * 128;

    const float QSCALE = 0.125f * 1.44269504f;   // 1/sqrt(64) * log2(e)

    const float* base = qkv + (long long)b * 2048 * 3072 + h * 192;

    float4 kreg[4], vreg[4];

    // prologue: LDG K(0), load+convert Q, init stats
    #pragma unroll
    for (int i = 0; i < 4; i++) {
        int idx = tid + i * 512;
        int rr = idx >> 4, c = (idx & 15) * 4;
        kreg[i] = *reinterpret_cast<const float4*>(
            base + (long long)rr * 3072 + 64 + c);
    }
    for (int idx = tid; idx < 128 * 16; idx += 512) {
        int r = idx >> 4, c = (idx & 15) * 4;
        float4 v = *reinterpret_cast<const float4*>(
            base + (long long)(q0 + r) * 3072 + c);
        v.x = wmma::__float_to_tf32(v.x * QSCALE);
        v.y = wmma::__float_to_tf32(v.y * QSCALE);
        v.z = wmma::__float_to_tf32(v.z * QSCALE);
        v.w = wmma::__float_to_tf32(v.w * QSCALE);
        *reinterpret_cast<float4*>(&Qs[r * QLD + c]) = v;
    }
    if (tid < 128) { mrow[tid] = -1e30f; lrow[tid] = 0.0f; }
    if (tid < 256) rowinit[tid] = (float)(tid >> 4);
    #pragma unroll
    for (int i = 0; i < 4; i++) {
        int idx = tid + i * 512;
        int rr = idx >> 4, c = (idx & 15) * 4;
        float4 v = kreg[i];
        v.x = wmma::__float_to_tf32(v.x); v.y = wmma::__float_to_tf32(v.y);
        v.z = wmma::__float_to_tf32(v.z); v.w = wmma::__float_to_tf32(v.w);
        *reinterpret_cast<float4*>(&Ks[rr * QLD + c]) = v;
    }
    __syncthreads();

    const int warp = tid >> 5;
    const int wm   = warp & 3;    // 32-row slice
    const int wn   = warp >> 2;   // 32-col (QK) / 16-col (PV) slice

    // accumulator-fragment row mapping (fp16 k16 acc has same m16n16 layout)
    wmma::fragment<wmma::accumulator, 16, 16, 16, float> rowf;
    wmma::load_matrix_sync(rowf, rowinit, 16, wmma::mem_row_major);
    int relrow[8];
    #pragma unroll
    for (int t = 0; t < 8; t++) relrow[t] = wm * 32 + (int)rowf.x[t];

    wmma::fragment<wmma::accumulator, 16, 16, 16, float> accO[2];
    #pragma unroll
    for (int i = 0; i < 2; i++) wmma::fill_fragment(accO[i], 0.0f);

    const int srow_r = tid >> 2;   // softmax row
    const int lane4  = tid & 3;    // 32-col chunk within row

    for (int kt = 0; kt < 16; kt++) {
        // LDG V(kt) (consumed after next sync; hidden behind QK)
        #pragma unroll
        for (int i = 0; i < 4; i++) {
            int idx = tid + i * 512;
            int rr = idx >> 4, c = (idx & 15) * 4;
            vreg[i] = *reinterpret_cast<const float4*>(
                base + (long long)(kt * 128 + rr) * 3072 + 128 + c);
        }

        // ---- S = Q @ K^T (warp: 32x32), pure LDS+HMMA ----
        {
            wmma::fragment<wmma::accumulator, 16, 16, 8, float> accS[2][2];
            #pragma unroll
            for (int i = 0; i < 2; i++)
                #pragma unroll
                for (int j = 0; j < 2; j++)
                    wmma::fill_fragment(accS[i][j], 0.0f);
            #pragma unroll
            for (int ks = 0; ks < 64; ks += 8) {
                wmma::fragment<wmma::matrix_a, 16, 16, 8, wmma::precision::tf32,
                               wmma::row_major> af[2];
                wmma::fragment<wmma::matrix_b, 16, 16, 8, wmma::precision::tf32,
                               wmma::col_major> bf[2];
                #pragma unroll
                for (int i = 0; i < 2; i++)
                    wmma::load_matrix_sync(af[i], &Qs[(wm * 32 + i * 16) * QLD + ks], QLD);
                #pragma unroll
                for (int j = 0; j < 2; j++)
                    wmma::load_matrix_sync(bf[j], &Ks[(wn * 32 + j * 16) * QLD + ks], QLD);
                #pragma unroll
                for (int i = 0; i < 2; i++)
                    #pragma unroll
                    for (int j = 0; j < 2; j++)
                        wmma::mma_sync(accS[i][j], af[i], bf[j], accS[i][j]);
            }
            #pragma unroll
            for (int i = 0; i < 2; i++)
                #pragma unroll
                for (int j = 0; j < 2; j++)
                    wmma::store_matrix_sync(
                        &Ss[(wm * 32 + i * 16) * SLD + wn * 32 + j * 16],
                        accS[i][j], SLD, wmma::mem_row_major);
        }
        __syncthreads();   // Ss visible; Ks consumed; Vh free

        // LDG K(kt+1) (consumed at end of iteration)
        if (kt < 15) {
            #pragma unroll
            for (int i = 0; i < 4; i++) {
                int idx = tid + i * 512;
                int rr = idx >> 4, c = (idx & 15) * 4;
                kreg[i] = *reinterpret_cast<const float4*>(
                    base + (long long)((kt + 1) * 128 + rr) * 3072 + 64 + c);
            }
        }

        // STS V(kt) as fp16
        #pragma unroll
        for (int i = 0; i < 4; i++) {
            int idx = tid + i * 512;
            int rr = idx >> 4, c = (idx & 15) * 4;
            __half2 h0 = __floats2half2_rn(vreg[i].x, vreg[i].y);
            __half2 h1 = __floats2half2_rn(vreg[i].z, vreg[i].w);
            *reinterpret_cast<__half2*>(&Vh[rr * VHLD + c])     = h0;
            *reinterpret_cast<__half2*>(&Vh[rr * VHLD + c + 2]) = h1;
        }

        // ---- online softmax (log2 domain): 4 lanes/row, shfl reductions ----
        {
            float* srow = Ss + srow_r * SLD + lane4 * 32;
            const float mold = mrow[srow_r];
            float mx = -1e30f;
            #pragma unroll
            for (int c4 = 0; c4 < 8; c4++) {
                float4 v = *reinterpret_cast<const float4*>(&srow[c4 * 4]);
                mx = fmaxf(mx, fmaxf(fmaxf(v.x, v.y), fmaxf(v.z, v.w)));
            }
            mx = fmaxf(mx, __shfl_xor_sync(0xffffffffu, mx, 1));
            mx = fmaxf(mx, __shfl_xor_sync(0xffffffffu, mx, 2));
            const float mnew = fmaxf(mold, mx);
            float s = 0.0f;
            __half* shrow = Sh + srow_r * SHLD + lane4 * 32;
            #pragma unroll
            for (int c2 = 0; c2 < 16; c2++) {
                float2 sv = *reinterpret_cast<const float2*>(&srow[c2 * 2]);
                float p0 = fexp2(sv.x - mnew);
                float p1 = fexp2(sv.y - mnew);
                s += p0 + p1;
                *reinterpret_cast<__half2*>(&shrow[c2 * 2]) = __floats2half2_rn(p0, p1);
            }
            s += __shfl_xor_sync(0xffffffffu, s, 1);
            s += __shfl_xor_sync(0xffffffffu, s, 2);
            if (lane4 == 0) {
                float al = fexp2(mold - mnew);
                arow[srow_r] = al;
                lrow[srow_r] = lrow[srow_r] * al + s;
                mrow[srow_r] = mnew;
            }
        }
        __syncthreads();   // Sh, Vh, arow visible

        // ---- rescale O (registers), O += P @ V in fp16 (warp: 32x16) ----
        #pragma unroll
        for (int i = 0; i < 2; i++)
            #pragma unroll
            for (int t = 0; t < 8; t++)
                accO[i].x[t] *= arow[relrow[t] + i * 16];
        #pragma unroll
        for (int kk = 0; kk < 128; kk += 16) {
            wmma::fragment<wmma::matrix_a, 16, 16, 16, __half, wmma::row_major> af[2];
            wmma::fragment<wmma::matrix_b, 16, 16, 16, __half, wmma::row_major> bf;
            #pragma unroll
            for (int i = 0; i < 2; i++)
                wmma::load_matrix_sync(af[i], &Sh[(wm * 32 + i * 16) * SHLD + kk], SHLD);
            wmma::load_matrix_sync(bf, &Vh[kk * VHLD + wn * 16], VHLD);
            #pragma unroll
            for (int i = 0; i < 2; i++)
                wmma::mma_sync(accO[i], af[i], bf, accO[i]);
        }

        // STS K(kt+1) (tf32)
        if (kt < 15) {
            #pragma unroll
            for (int i = 0; i < 4; i++) {
                int idx = tid + i * 512;
                int rr = idx >> 4, c = (idx & 15) * 4;
                float4 v = kreg[i];
                v.x = wmma::__float_to_tf32(v.x); v.y = wmma::__float_to_tf32(v.y);
                v.z = wmma::__float_to_tf32(v.z); v.w = wmma::__float_to_tf32(v.w);
                *reinterpret_cast<float4*>(&Ks[rr * QLD + c]) = v;
            }
        }
        __syncthreads();   // Ks(kt+1) visible; Ss/Sh free
    }

    // normalize in registers, stage through Ss, write out
    #pragma unroll
    for (int i = 0; i < 2; i++) {
        #pragma unroll
        for (int t = 0; t < 8; t++)
            accO[i].x[t] *= __frcp_rn(lrow[relrow[t] + i * 16]);
        wmma::store_matrix_sync(&Ss[(wm * 32 + i * 16) * SLD + wn * 16],
                                accO[i], SLD, wmma::mem_row_major);
    }
    __syncthreads();
    for (int idx = tid; idx < 128 * 16; idx += 512) {
        int rr = idx >> 4, c = (idx & 15) * 4;
        float4 v = *reinterpret_cast<const float4*>(&Ss[rr * SLD + c]);
        *reinterpret_cast<float4*>(
            attn + (long long)(b * 2048 + q0 + rr) * 1024 + h * 64 + c) = v;
    }
}

// ---------------------------------------------------------------------------
// Orchestration. Inputs: x, w_qkv, b_qkv, w_o, b_o (all fp32).
// ---------------------------------------------------------------------------
extern "C" void kernel_launch(void* const* d_in, const int* in_sizes, int n_in,
                              void* d_out, int out_size)
{
    (void)in_sizes; (void)n_in; (void)out_size;
    const float* x     = (const float*)d_in[0];
    const float* w_qkv = (const float*)d_in[1];
    const float* b_qkv = (const float*)d_in[2];
    const float* w_o   = (const float*)d_in[3];
    const float* b_o   = (const float*)d_in[4];
    float* out = (float*)d_out;

    float *qkv, *attn;
    cudaGetSymbolAddress((void**)&qkv,  g_qkv);
    cudaGetSymbolAddress((void**)&attn, g_attn);

    cudaFuncSetAttribute(gemm_bias_tf32_kernel,
                         cudaFuncAttributeMaxDynamicSharedMemorySize, GEMM_SMEM);
    cudaFuncSetAttribute(flash_attn_kernel,
                         cudaFuncAttributeMaxDynamicSharedMemorySize, FA_SMEM_BYTES);

    // 1) qkv = x @ w_qkv^T + b_qkv   [4096,1024]x[3072,1024]^T
    gemm_bias_tf32_kernel<<<dim3(24, 32), 512, GEMM_SMEM>>>(
        x, w_qkv, b_qkv, qkv, 1024, 1024, 3072, 1024);

    // 2) fused attention -> attn [4096, 1024]
    flash_attn_kernel<<<dim3(16, 32), 512, FA_SMEM_BYTES>>>(qkv, attn);

    // 3) out = attn @ w_o^T + b_o    [4096,1024]x[1024,1024]^T
    gemm_bias_tf32_kernel<<<dim3(8, 32), 512, GEMM_SMEM>>>(
        attn, w_o, b_o, out, 1024, 1024, 1024, 1024);
}

// round 7
// speedup vs baseline: 3.7431x; 2.5785x over previous
#include <cuda_runtime.h>
#include <cuda_fp16.h>
#include <mma.h>

using namespace nvcuda;

// ---------------------------------------------------------------------------
// B=2, S=2048, D=1024, H=16, hd=64.  Whole datapath fp16 (10 mantissa bits,
// same as tf32), fp32 accumulate everywhere.
// ---------------------------------------------------------------------------
__device__ __align__(256) __half g_xh[4096LL * 1024];
__device__ __align__(256) __half g_wqkvh[3072LL * 1024];
__device__ __align__(256) __half g_woh[1024LL * 1024];
__device__ __align__(256) __half g_qkvh[4096LL * 3072];   // [B*S, 3*D] per-head [q|k|v]
__device__ __align__(256) __half g_attnh[4096LL * 1024];

__device__ __forceinline__ unsigned h2_as_u32(__half2 h) {
    return *reinterpret_cast<unsigned*>(&h);
}
__device__ __forceinline__ float fexp2(float x) {
    float r;
    asm("ex2.approx.ftz.f32 %0, %1;" : "=f"(r) : "f"(x));
    return r;
}
__device__ __forceinline__ unsigned smem_u32(const void* p) {
    return (unsigned)__cvta_generic_to_shared(p);
}
#define CP_ASYNC16(dst_u32, src_ptr)                                        \
    asm volatile("cp.async.cg.shared.global [%0], [%1], 16;\n" ::           \
                 "r"(dst_u32), "l"(src_ptr))
#define CP_COMMIT() asm volatile("cp.async.commit_group;\n" ::: "memory")
#define CP_WAIT(n)  asm volatile("cp.async.wait_group %0;\n" :: "n"(n) : "memory")

// ---------------------------------------------------------------------------
// fp32 -> fp16 convert (memory bound)
// ---------------------------------------------------------------------------
__global__ void __launch_bounds__(256)
f32_to_f16_kernel(const float* __restrict__ in, __half* __restrict__ out)
{
    long long i = ((long long)blockIdx.x * 256 + threadIdx.x) * 8;
    float4 a = *reinterpret_cast<const float4*>(in + i);
    float4 b = *reinterpret_cast<const float4*>(in + i + 4);
    __half2* o = reinterpret_cast<__half2*>(out + i);
    o[0] = __floats2half2_rn(a.x, a.y);
    o[1] = __floats2half2_rn(a.z, a.w);
    o[2] = __floats2half2_rn(b.x, b.y);
    o[3] = __floats2half2_rn(b.z, b.w);
}

// ---------------------------------------------------------------------------
// fp16 GEMM, C = A @ B^T + bias (A [M,K], B [N,K] row-major, fp16).
// 512 threads, 32x32 warp tiles, cp.async double-buffered GBK=64 tiles,
// m16n16k16 mma (LDSM loads), fp32 accum. OUT_HALF selects fp16/fp32 C.
// ---------------------------------------------------------------------------
constexpr int GBK  = 64;
constexpr int BKH  = 72;                 // 64 + 8 pad (halves); row = 144 B
constexpr int TILEH = 128 * BKH;
constexpr int GEMM_SMEM = 2 * TILEH * 2 * 2 + 16 * 128 * 4;   // 81,920 B
constexpr int SLDE = 132;                // fp32 staging ld for fp16 output

template <bool OUT_HALF>
__global__ void __launch_bounds__(512, 2)
gemm_bias_f16_kernel(const __half* __restrict__ A, const __half* __restrict__ B,
                     const float* __restrict__ bias, void* __restrict__ Cv,
                     int lda, int ldb, int ldc, int K)
{
    extern __shared__ char gsm[];
    __half* As      = reinterpret_cast<__half*>(gsm);          // 2*TILEH
    __half* Bs      = As + 2 * TILEH;                          // 2*TILEH
    float*  biasrep = reinterpret_cast<float*>(Bs + 2 * TILEH);// 16*128

    const int tid  = threadIdx.x;
    const int m0   = blockIdx.y * 128;
    const int n0   = blockIdx.x * 128;
    const int warp = tid >> 5;
    const int wm   = warp & 3;
    const int wn   = warp >> 2;

    for (int idx = tid; idx < 16 * 128; idx += 512)
        biasrep[idx] = bias[n0 + (idx & 127)];
    __syncthreads();

    wmma::fragment<wmma::accumulator, 16, 16, 16, float> acc[2][2];
    #pragma unroll
    for (int i = 0; i < 2; i++)
        #pragma unroll
        for (int j = 0; j < 2; j++)
            wmma::load_matrix_sync(acc[i][j], &biasrep[wn * 32 + j * 16], 128,
                                   wmma::mem_row_major);

    auto load_tile = [&](int k0, int p) {
        #pragma unroll
        for (int i = 0; i < 2; i++) {
            int idx = tid + i * 512;
            int r = idx >> 3, c = (idx & 7) * 8;
            CP_ASYNC16(smem_u32(&As[p * TILEH + r * BKH + c]),
                       A + (long long)(m0 + r) * lda + k0 + c);
            CP_ASYNC16(smem_u32(&Bs[p * TILEH + r * BKH + c]),
                       B + (long long)(n0 + r) * ldb + k0 + c);
        }
    };

    load_tile(0, 0);
    CP_COMMIT();

    int p = 0;
    for (int k0 = 0; k0 < K; k0 += GBK) {
        CP_WAIT(0);
        __syncthreads();
        if (k0 + GBK < K) load_tile(k0 + GBK, p ^ 1);
        CP_COMMIT();

        const __half* Asp = As + p * TILEH;
        const __half* Bsp = Bs + p * TILEH;
        #pragma unroll
        for (int ks = 0; ks < GBK; ks += 16) {
            wmma::fragment<wmma::matrix_a, 16, 16, 16, __half, wmma::row_major> af[2];
            wmma::fragment<wmma::matrix_b, 16, 16, 16, __half, wmma::col_major> bf[2];
            #pragma unroll
            for (int i = 0; i < 2; i++)
                wmma::load_matrix_sync(af[i], &Asp[(wm * 32 + i * 16) * BKH + ks], BKH);
            #pragma unroll
            for (int j = 0; j < 2; j++)
                wmma::load_matrix_sync(bf[j], &Bsp[(wn * 32 + j * 16) * BKH + ks], BKH);
            #pragma unroll
            for (int i = 0; i < 2; i++)
                #pragma unroll
                for (int j = 0; j < 2; j++)
                    wmma::mma_sync(acc[i][j], af[i], bf[j], acc[i][j]);
        }
        p ^= 1;
    }

    if (OUT_HALF) {
        // stage fp32 in smem (reuses tile buffers), convert, vector-store fp16
        __syncthreads();
        float* stage = reinterpret_cast<float*>(gsm);   // 128*SLDE floats
        #pragma unroll
        for (int i = 0; i < 2; i++)
            #pragma unroll
            for (int j = 0; j < 2; j++)
                wmma::store_matrix_sync(
                    &stage[(wm * 32 + i * 16) * SLDE + wn * 32 + j * 16],
                    acc[i][j], SLDE, wmma::mem_row_major);
        __syncthreads();
        __half* C = reinterpret_cast<__half*>(Cv);
        #pragma unroll
        for (int i = 0; i < 8; i++) {
            int idx = tid + i * 512;
            int r = idx >> 5, c = (idx & 31) * 4;
            float4 v = *reinterpret_cast<const float4*>(&stage[r * SLDE + c]);
            uint2 h;
            h.x = h2_as_u32(__floats2half2_rn(v.x, v.y));
            h.y = h2_as_u32(__floats2half2_rn(v.z, v.w));
            *reinterpret_cast<uint2*>(C + (long long)(m0 + r) * ldc + n0 + c) = h;
        }
    } else {
        float* C = reinterpret_cast<float*>(Cv);
        #pragma unroll
        for (int i = 0; i < 2; i++)
            #pragma unroll
            for (int j = 0; j < 2; j++)
                wmma::store_matrix_sync(
                    C + (long long)(m0 + wm * 32 + i * 16) * ldc + n0 + wn * 32 + j * 16,
                    acc[i][j], ldc, wmma::mem_row_major);
    }
}

// ---------------------------------------------------------------------------
// Flash attention, all-fp16 operands, fp32 accum/softmax.
// One CTA per (bh, 128-row q tile), 512 threads. cp.async pipeline:
// V(kt) loads during QK, K(kt+1) during softmax. Scale applied as FMA in
// softmax (log2 domain). O in registers. Output fp16.
// ---------------------------------------------------------------------------
constexpr int KLDH = 72;    // fp16 64 + 8 pad
constexpr int SLD  = 132;   // fp32 logits 128 + 4 pad
constexpr int SHLD = 136;   // fp16 P 128 + 8 pad
constexpr int FA_F32B  = (128 * SLD + 3 * 128 + 256) * 4;              // 70,144 B
constexpr int FA_SMEM_BYTES = FA_F32B + (3 * 128 * KLDH + 128 * SHLD) * 2;  // 160,256 B

__global__ void __launch_bounds__(512, 1)
flash_attn_kernel(const __half* __restrict__ qkv, __half* __restrict__ attn)
{
    extern __shared__ float sm[];
    float* Ss      = sm;                  // 128*SLD
    float* mrow    = Ss + 128 * SLD;
    float* lrow    = mrow + 128;
    float* arow    = lrow + 128;
    float* rowinit = arow + 128;          // 256
    __half* Qs = reinterpret_cast<__half*>(reinterpret_cast<char*>(sm) + FA_F32B);
    __half* Ks = Qs + 128 * KLDH;
    __half* Vh = Ks + 128 * KLDH;
    __half* Sh = Vh + 128 * KLDH;         // 128*SHLD

    const int tid = threadIdx.x;
    const int bh  = blockIdx.y;
    const int b   = bh >> 4;
    const int h   = bh & 15;
    const int q0  = blockIdx.x * 128;

    const float QSCALE = 0.125f * 1.44269504f;   // 1/sqrt(64) * log2(e)
    const __half* base = qkv + (long long)b * 2048 * 3072 + h * 192;

    // prologue: cp.async Q + K(0), init stats
    #pragma unroll
    for (int i = 0; i < 2; i++) {
        int idx = tid + i * 512;
        int r = idx >> 3, c = (idx & 7) * 8;
        CP_ASYNC16(smem_u32(&Qs[r * KLDH + c]),
                   base + (long long)(q0 + r) * 3072 + c);
        CP_ASYNC16(smem_u32(&Ks[r * KLDH + c]),
                   base + (long long)r * 3072 + 64 + c);
    }
    CP_COMMIT();
    if (tid < 128) { mrow[tid] = -1e30f; lrow[tid] = 0.0f; }
    if (tid < 256) rowinit[tid] = (float)(tid >> 4);
    CP_WAIT(0);
    __syncthreads();

    const int warp = tid >> 5;
    const int wm   = warp & 3;
    const int wn   = warp >> 2;

    wmma::fragment<wmma::accumulator, 16, 16, 16, float> rowf;
    wmma::load_matrix_sync(rowf, rowinit, 16, wmma::mem_row_major);
    int relrow[8];
    #pragma unroll
    for (int t = 0; t < 8; t++) relrow[t] = wm * 32 + (int)rowf.x[t];

    wmma::fragment<wmma::accumulator, 16, 16, 16, float> accO[2];
    #pragma unroll
    for (int i = 0; i < 2; i++) wmma::fill_fragment(accO[i], 0.0f);

    const int srow_r = tid >> 2;
    const int lane4  = tid & 3;

    for (int kt = 0; kt < 16; kt++) {
        // issue V(kt) (lands during QK)
        #pragma unroll
        for (int i = 0; i < 2; i++) {
            int idx = tid + i * 512;
            int r = idx >> 3, c = (idx & 7) * 8;
            CP_ASYNC16(smem_u32(&Vh[r * KLDH + c]),
                       base + (long long)(kt * 128 + r) * 3072 + 128 + c);
        }
        CP_COMMIT();   // group V

        // ---- S = Q @ K^T, fp16 m16n16k16 (warp: 32x32) ----
        {
            wmma::fragment<wmma::accumulator, 16, 16, 16, float> accS[2][2];
            #pragma unroll
            for (int i = 0; i < 2; i++)
                #pragma unroll
                for (int j = 0; j < 2; j++)
                    wmma::fill_fragment(accS[i][j], 0.0f);
            #pragma unroll
            for (int ks = 0; ks < 64; ks += 16) {
                wmma::fragment<wmma::matrix_a, 16, 16, 16, __half, wmma::row_major> af[2];
                wmma::fragment<wmma::matrix_b, 16, 16, 16, __half, wmma::col_major> bf[2];
                #pragma unroll
                for (int i = 0; i < 2; i++)
                    wmma::load_matrix_sync(af[i], &Qs[(wm * 32 + i * 16) * KLDH + ks], KLDH);
                #pragma unroll
                for (int j = 0; j < 2; j++)
                    wmma::load_matrix_sync(bf[j], &Ks[(wn * 32 + j * 16) * KLDH + ks], KLDH);
                #pragma unroll
                for (int i = 0; i < 2; i++)
                    #pragma unroll
                    for (int j = 0; j < 2; j++)
                        wmma::mma_sync(accS[i][j], af[i], bf[j], accS[i][j]);
            }
            #pragma unroll
            for (int i = 0; i < 2; i++)
                #pragma unroll
                for (int j = 0; j < 2; j++)
                    wmma::store_matrix_sync(
                        &Ss[(wm * 32 + i * 16) * SLD + wn * 32 + j * 16],
                        accS[i][j], SLD, wmma::mem_row_major);
        }
        __syncthreads();   // Ss visible; Ks consumed

        // issue K(kt+1) (lands during softmax/PV)
        if (kt < 15) {
            #pragma unroll
            for (int i = 0; i < 2; i++) {
                int idx = tid + i * 512;
                int r = idx >> 3, c = (idx & 7) * 8;
                CP_ASYNC16(smem_u32(&Ks[r * KLDH + c]),
                           base + (long long)((kt + 1) * 128 + r) * 3072 + 64 + c);
            }
        }
        CP_COMMIT();   // group K'

        // ---- online softmax (scale folded as FMA; log2 domain) ----
        {
            float* srow = Ss + srow_r * SLD + lane4 * 32;
            const float mold = mrow[srow_r];
            float mx = -1e30f;
            #pragma unroll
            for (int c4 = 0; c4 < 8; c4++) {
                float4 v = *reinterpret_cast<const float4*>(&srow[c4 * 4]);
                mx = fmaxf(mx, fmaxf(fmaxf(v.x, v.y), fmaxf(v.z, v.w)));
            }
            mx = fmaxf(mx, __shfl_xor_sync(0xffffffffu, mx, 1));
            mx = fmaxf(mx, __shfl_xor_sync(0xffffffffu, mx, 2));
            const float mnew = fmaxf(mold, mx * QSCALE);
            float s = 0.0f;
            __half* shrow = Sh + srow_r * SHLD + lane4 * 32;
            #pragma unroll
            for (int c2 = 0; c2 < 16; c2++) {
                float2 sv = *reinterpret_cast<const float2*>(&srow[c2 * 2]);
                float p0 = fexp2(__fmaf_rn(sv.x, QSCALE, -mnew));
                float p1 = fexp2(__fmaf_rn(sv.y, QSCALE, -mnew));
                s += p0 + p1;
                *reinterpret_cast<__half2*>(&shrow[c2 * 2]) = __floats2half2_rn(p0, p1);
            }
            s += __shfl_xor_sync(0xffffffffu, s, 1);
            s += __shfl_xor_sync(0xffffffffu, s, 2);
            if (lane4 == 0) {
                float al = fexp2(mold - mnew);
                arow[srow_r] = al;
                lrow[srow_r] = lrow[srow_r] * al + s;
                mrow[srow_r] = mnew;
            }
        }
        CP_WAIT(1);        // V(kt) resident (K' may still be in flight)
        __syncthreads();   // Sh, Vh, arow visible

        // ---- rescale O, O += P @ V (warp: 32x16) ----
        #pragma unroll
        for (int i = 0; i < 2; i++)
            #pragma unroll
            for (int t = 0; t < 8; t++)
                accO[i].x[t] *= arow[relrow[t] + i * 16];
        #pragma unroll
        for (int kk = 0; kk < 128; kk += 16) {
            wmma::fragment<wmma::matrix_a, 16, 16, 16, __half, wmma::row_major> af[2];
            wmma::fragment<wmma::matrix_b, 16, 16, 16, __half, wmma::row_major> bf;
            #pragma unroll
            for (int i = 0; i < 2; i++)
                wmma::load_matrix_sync(af[i], &Sh[(wm * 32 + i * 16) * SHLD + kk], SHLD);
            wmma::load_matrix_sync(bf, &Vh[kk * KLDH + wn * 16], KLDH);
            #pragma unroll
            for (int i = 0; i < 2; i++)
                wmma::mma_sync(accO[i], af[i], bf, accO[i]);
        }
        CP_WAIT(0);        // K(kt+1) resident
        __syncthreads();   // PV done -> Vh/Sh reusable next iter
    }

    // normalize, stage fp32, convert+store fp16
    #pragma unroll
    for (int i = 0; i < 2; i++) {
        #pragma unroll
        for (int t = 0; t < 8; t++)
            accO[i].x[t] *= __frcp_rn(lrow[relrow[t] + i * 16]);
        wmma::store_matrix_sync(&Ss[(wm * 32 + i * 16) * SLD + wn * 16],
                                accO[i], SLD, wmma::mem_row_major);
    }
    __syncthreads();
    #pragma unroll
    for (int i = 0; i < 4; i++) {
        int idx = tid + i * 512;
        int r = idx >> 4, c = (idx & 15) * 4;
        float4 v = *reinterpret_cast<const float4*>(&Ss[r * SLD + c]);
        uint2 hh;
        hh.x = h2_as_u32(__floats2half2_rn(v.x, v.y));
        hh.y = h2_as_u32(__floats2half2_rn(v.z, v.w));
        *reinterpret_cast<uint2*>(
            attn + (long long)(b * 2048 + q0 + r) * 1024 + h * 64 + c) = hh;
    }
}

// ---------------------------------------------------------------------------
// Orchestration. Inputs: x, w_qkv, b_qkv, w_o, b_o (all fp32).
// ---------------------------------------------------------------------------
extern "C" void kernel_launch(void* const* d_in, const int* in_sizes, int n_in,
                              void* d_out, int out_size)
{
    (void)in_sizes; (void)n_in; (void)out_size;
    const float* x     = (const float*)d_in[0];
    const float* w_qkv = (const float*)d_in[1];
    const float* b_qkv = (const float*)d_in[2];
    const float* w_o   = (const float*)d_in[3];
    const float* b_o   = (const float*)d_in[4];
    float* out = (float*)d_out;

    __half *xh, *wqkvh, *woh, *qkvh, *attnh;
    cudaGetSymbolAddress((void**)&xh,    g_xh);
    cudaGetSymbolAddress((void**)&wqkvh, g_wqkvh);
    cudaGetSymbolAddress((void**)&woh,   g_woh);
    cudaGetSymbolAddress((void**)&qkvh,  g_qkvh);
    cudaGetSymbolAddress((void**)&attnh, g_attnh);

    cudaFuncSetAttribute(gemm_bias_f16_kernel<true>,
                         cudaFuncAttributeMaxDynamicSharedMemorySize, GEMM_SMEM);
    cudaFuncSetAttribute(gemm_bias_f16_kernel<false>,
                         cudaFuncAttributeMaxDynamicSharedMemorySize, GEMM_SMEM);
    cudaFuncSetAttribute(flash_attn_kernel,
                         cudaFuncAttributeMaxDynamicSharedMemorySize, FA_SMEM_BYTES);

    // 0) fp32 -> fp16 converts
    f32_to_f16_kernel<<<4096LL * 1024 / 2048, 256>>>(x, xh);
    f32_to_f16_kernel<<<3072LL * 1024 / 2048, 256>>>(w_qkv, wqkvh);
    f32_to_f16_kernel<<<1024LL * 1024 / 2048, 256>>>(w_o, woh);

    // 1) qkvh = xh @ wqkvh^T + b_qkv   (fp16 out)
    gemm_bias_f16_kernel<true><<<dim3(24, 32), 512, GEMM_SMEM>>>(
        xh, wqkvh, b_qkv, qkvh, 1024, 1024, 3072, 1024);

    // 2) fused attention -> attnh (fp16)
    flash_attn_kernel<<<dim3(16, 32), 512, FA_SMEM_BYTES>>>(qkvh, attnh);

    // 3) out = attnh @ woh^T + b_o     (fp32 out)
    gemm_bias_f16_kernel<false><<<dim3(8, 32), 512, GEMM_SMEM>>>(
        attnh, woh, b_o, out, 1024, 1024, 1024, 1024);
}

// round 10
// speedup vs baseline: 6.8019x; 1.8172x over previous
#include <cuda_runtime.h>
#include <cuda_fp16.h>
#include <mma.h>

using namespace nvcuda;

// ---------------------------------------------------------------------------
// B=2, S=2048, D=1024, H=16, hd=64. fp16 datapath, fp32 accumulate.
// ---------------------------------------------------------------------------
__device__ __align__(256) __half g_xh[4096LL * 1024];
__device__ __align__(256) __half g_wqkvh[3072LL * 1024];
__device__ __align__(256) __half g_woh[1024LL * 1024];
__device__ __align__(256) __half g_qkvh[4096LL * 3072];   // per-head [q|k|v]
__device__ __align__(256) __half g_attnh[4096LL * 1024];

__device__ __forceinline__ unsigned h2_as_u32(__half2 h) {
    return *reinterpret_cast<unsigned*>(&h);
}
__device__ __forceinline__ float fexp2(float x) {
    float r;
    asm("ex2.approx.ftz.f32 %0, %1;" : "=f"(r) : "f"(x));
    return r;
}
__device__ __forceinline__ unsigned smem_u32(const void* p) {
    return (unsigned)__cvta_generic_to_shared(p);
}
#define CP_ASYNC16(dst_u32, src_ptr)                                        \
    asm volatile("cp.async.cg.shared.global [%0], [%1], 16;\n" ::           \
                 "r"(dst_u32), "l"(src_ptr))
#define CP_COMMIT() asm volatile("cp.async.commit_group;\n" ::: "memory")
#define CP_WAIT(n)  asm volatile("cp.async.wait_group %0;\n" :: "n"(n) : "memory")

#define LDSM_X4(r0, r1, r2, r3, a)                                           \
    asm volatile("ldmatrix.sync.aligned.m8n8.x4.shared.b16 {%0,%1,%2,%3}, [%4];" \
                 : "=r"(r0), "=r"(r1), "=r"(r2), "=r"(r3) : "r"(a))
#define LDSM_X4_T(r0, r1, r2, r3, a)                                         \
    asm volatile("ldmatrix.sync.aligned.m8n8.x4.trans.shared.b16 {%0,%1,%2,%3}, [%4];" \
                 : "=r"(r0), "=r"(r1), "=r"(r2), "=r"(r3) : "r"(a))
#define MMA16816(c, a0, a1, a2, a3, b0, b1)                                  \
    asm volatile("mma.sync.aligned.m16n8k16.row.col.f32.f16.f16.f32 "        \
                 "{%0,%1,%2,%3},{%4,%5,%6,%7},{%8,%9},{%0,%1,%2,%3};"        \
                 : "+f"((c)[0]), "+f"((c)[1]), "+f"((c)[2]), "+f"((c)[3])    \
                 : "r"(a0), "r"(a1), "r"(a2), "r"(a3), "r"(b0), "r"(b1))

// ---------------------------------------------------------------------------
// fp32 -> fp16 convert
// ---------------------------------------------------------------------------
__global__ void __launch_bounds__(256)
f32_to_f16_kernel(const float* __restrict__ in, __half* __restrict__ out)
{
    long long i = ((long long)blockIdx.x * 256 + threadIdx.x) * 8;
    float4 a = *reinterpret_cast<const float4*>(in + i);
    float4 b = *reinterpret_cast<const float4*>(in + i + 4);
    __half2* o = reinterpret_cast<__half2*>(out + i);
    o[0] = __floats2half2_rn(a.x, a.y);
    o[1] = __floats2half2_rn(a.z, a.w);
    o[2] = __floats2half2_rn(b.x, b.y);
    o[3] = __floats2half2_rn(b.z, b.w);
}

// ---------------------------------------------------------------------------
// fp16 GEMM: C = A @ B^T + bias, cp.async double-buffer (R7, unchanged).
// ---------------------------------------------------------------------------
constexpr int GBK  = 64;
constexpr int BKH  = 72;
constexpr int TILEH = 128 * BKH;
constexpr int GEMM_SMEM = 2 * TILEH * 2 * 2 + 16 * 128 * 4;
constexpr int SLDE = 132;

template <bool OUT_HALF>
__global__ void __launch_bounds__(512, 2)
gemm_bias_f16_kernel(const __half* __restrict__ A, const __half* __restrict__ B,
                     const float* __restrict__ bias, void* __restrict__ Cv,
                     int lda, int ldb, int ldc, int K)
{
    extern __shared__ char gsm[];
    __half* As      = reinterpret_cast<__half*>(gsm);
    __half* Bs      = As + 2 * TILEH;
    float*  biasrep = reinterpret_cast<float*>(Bs + 2 * TILEH);

    const int tid  = threadIdx.x;
    const int m0   = blockIdx.y * 128;
    const int n0   = blockIdx.x * 128;
    const int warp = tid >> 5;
    const int wm   = warp & 3;
    const int wn   = warp >> 2;

    for (int idx = tid; idx < 16 * 128; idx += 512)
        biasrep[idx] = bias[n0 + (idx & 127)];
    __syncthreads();

    wmma::fragment<wmma::accumulator, 16, 16, 16, float> acc[2][2];
    #pragma unroll
    for (int i = 0; i < 2; i++)
        #pragma unroll
        for (int j = 0; j < 2; j++)
            wmma::load_matrix_sync(acc[i][j], &biasrep[wn * 32 + j * 16], 128,
                                   wmma::mem_row_major);

    auto load_tile = [&](int k0, int p) {
        #pragma unroll
        for (int i = 0; i < 2; i++) {
            int idx = tid + i * 512;
            int r = idx >> 3, c = (idx & 7) * 8;
            CP_ASYNC16(smem_u32(&As[p * TILEH + r * BKH + c]),
                       A + (long long)(m0 + r) * lda + k0 + c);
            CP_ASYNC16(smem_u32(&Bs[p * TILEH + r * BKH + c]),
                       B + (long long)(n0 + r) * ldb + k0 + c);
        }
    };

    load_tile(0, 0);
    CP_COMMIT();

    int p = 0;
    for (int k0 = 0; k0 < K; k0 += GBK) {
        CP_WAIT(0);
        __syncthreads();
        if (k0 + GBK < K) load_tile(k0 + GBK, p ^ 1);
        CP_COMMIT();

        const __half* Asp = As + p * TILEH;
        const __half* Bsp = Bs + p * TILEH;
        #pragma unroll
        for (int ks = 0; ks < GBK; ks += 16) {
            wmma::fragment<wmma::matrix_a, 16, 16, 16, __half, wmma::row_major> af[2];
            wmma::fragment<wmma::matrix_b, 16, 16, 16, __half, wmma::col_major> bf[2];
            #pragma unroll
            for (int i = 0; i < 2; i++)
                wmma::load_matrix_sync(af[i], &Asp[(wm * 32 + i * 16) * BKH + ks], BKH);
            #pragma unroll
            for (int j = 0; j < 2; j++)
                wmma::load_matrix_sync(bf[j], &Bsp[(wn * 32 + j * 16) * BKH + ks], BKH);
            #pragma unroll
            for (int i = 0; i < 2; i++)
                #pragma unroll
                for (int j = 0; j < 2; j++)
                    wmma::mma_sync(acc[i][j], af[i], bf[j], acc[i][j]);
        }
        p ^= 1;
    }

    if (OUT_HALF) {
        __syncthreads();
        float* stage = reinterpret_cast<float*>(gsm);
        #pragma unroll
        for (int i = 0; i < 2; i++)
            #pragma unroll
            for (int j = 0; j < 2; j++)
                wmma::store_matrix_sync(
                    &stage[(wm * 32 + i * 16) * SLDE + wn * 32 + j * 16],
                    acc[i][j], SLDE, wmma::mem_row_major);
        __syncthreads();
        __half* C = reinterpret_cast<__half*>(Cv);
        #pragma unroll
        for (int i = 0; i < 8; i++) {
            int idx = tid + i * 512;
            int r = idx >> 5, c = (idx & 31) * 4;
            float4 v = *reinterpret_cast<const float4*>(&stage[r * SLDE + c]);
            uint2 h;
            h.x = h2_as_u32(__floats2half2_rn(v.x, v.y));
            h.y = h2_as_u32(__floats2half2_rn(v.z, v.w));
            *reinterpret_cast<uint2*>(C + (long long)(m0 + r) * ldc + n0 + c) = h;
        }
    } else {
        float* C = reinterpret_cast<float*>(Cv);
        #pragma unroll
        for (int i = 0; i < 2; i++)
            #pragma unroll
            for (int j = 0; j < 2; j++)
                wmma::store_matrix_sync(
                    C + (long long)(m0 + wm * 32 + i * 16) * ldc + n0 + wn * 32 + j * 16,
                    acc[i][j], ldc, wmma::mem_row_major);
    }
}

// ---------------------------------------------------------------------------
// Flash attention, FA2-style register pipeline (raw mma.m16n8k16).
// CTA = 128 threads (4 warps), q-tile 128 rows, warp owns 32 rows x ALL cols.
// S never leaves registers (C-frag of QK == A-frag of PV). Warp-local
// softmax; one barrier per k-tile; K/V double-buffered cp.async; Q resident
// in registers.
// ---------------------------------------------------------------------------
constexpr int QSP = 72;                                 // padded row (halves)
constexpr int FA_Q_BYTES  = 128 * QSP * 2;              // 18,432
constexpr int FA_KV_BYTES = 64 * QSP * 2;               // 9,216 per buffer
constexpr int FA_SMEM_BYTES = FA_Q_BYTES + 4 * FA_KV_BYTES;  // 55,296

__global__ void __launch_bounds__(128)
flash_attn_kernel(const __half* __restrict__ qkv, __half* __restrict__ attn)
{
    extern __shared__ char fsm[];
    __half* Qs  = reinterpret_cast<__half*>(fsm);         // 128 x QSP
    __half* Kb0 = Qs + 128 * QSP;                         // 64 x QSP
    __half* Kb1 = Kb0 + 64 * QSP;
    __half* Vb0 = Kb1 + 64 * QSP;
    __half* Vb1 = Vb0 + 64 * QSP;

    const int tid  = threadIdx.x;
    const int lane = tid & 31;
    const int warp = tid >> 5;          // 0..3
    const int wr   = warp * 32;         // warp's first q-row in tile
    const int g    = lane >> 2;
    const int t    = lane & 3;

    const int bh = blockIdx.y;
    const int b  = bh >> 4;
    const int h  = bh & 15;
    const int q0 = blockIdx.x * 128;

    const float QSCALE = 0.125f * 1.44269504f;   // 1/sqrt(64) * log2(e)
    const __half* base = qkv + (long long)b * 2048 * 3072 + h * 192;

    // ---- prologue: cp.async Q + tiles 0,1 ----
    #pragma unroll
    for (int i = 0; i < 8; i++) {              // Q: 128 rows x 8 chunks
        int idx = tid + i * 128;
        int r = idx >> 3, c = (idx & 7) * 8;
        CP_ASYNC16(smem_u32(&Qs[r * QSP + c]),
                   base + (long long)(q0 + r) * 3072 + c);
    }
    #pragma unroll
    for (int i = 0; i < 4; i++) {              // K0/V0: 64 rows x 8 chunks
        int idx = tid + i * 128;
        int r = idx >> 3, c = (idx & 7) * 8;
        CP_ASYNC16(smem_u32(&Kb0[r * QSP + c]), base + (long long)r * 3072 + 64 + c);
        CP_ASYNC16(smem_u32(&Vb0[r * QSP + c]), base + (long long)r * 3072 + 128 + c);
    }
    CP_COMMIT();                               // group: Q,K0,V0
    #pragma unroll
    for (int i = 0; i < 4; i++) {
        int idx = tid + i * 128;
        int r = idx >> 3, c = (idx & 7) * 8;
        CP_ASYNC16(smem_u32(&Kb1[r * QSP + c]),
                   base + (long long)(64 + r) * 3072 + 64 + c);
        CP_ASYNC16(smem_u32(&Vb1[r * QSP + c]),
                   base + (long long)(64 + r) * 3072 + 128 + c);
    }
    CP_COMMIT();                               // group: K1,V1
    CP_WAIT(1);                                // Q,K0,V0 resident
    __syncthreads();

    // ---- Q fragments to registers (whole kernel) ----
    unsigned qf[2][4][4];
    {
        int lrow = ((lane >> 3) & 1) * 8 + (lane & 7);
        int lcol = (lane >> 4) * 8;
        #pragma unroll
        for (int mi = 0; mi < 2; mi++)
            #pragma unroll
            for (int kc = 0; kc < 4; kc++) {
                unsigned a = smem_u32(&Qs[(wr + mi * 16 + lrow) * QSP + kc * 16 + lcol]);
                LDSM_X4(qf[mi][kc][0], qf[mi][kc][1], qf[mi][kc][2], qf[mi][kc][3], a);
            }
    }

    float of[2][8][4];
    #pragma unroll
    for (int mi = 0; mi < 2; mi++)
        #pragma unroll
        for (int v = 0; v < 8; v++)
            #pragma unroll
            for (int e = 0; e < 4; e++) of[mi][v][e] = 0.0f;
    float mreg[2][2] = {{-1e30f, -1e30f}, {-1e30f, -1e30f}};
    float lreg[2][2] = {{0.0f, 0.0f}, {0.0f, 0.0f}};

    // ldmatrix lane-address components
    const int kb_row = ((lane >> 4) & 1) * 8 + (lane & 7);   // K frags
    const int kb_col = ((lane >> 3) & 1) * 8;
    const int vb_row = ((lane >> 3) & 1) * 8 + (lane & 7);   // V frags (trans)
    const int vb_col = ((lane >> 4) & 1) * 8;

    for (int kt = 0; kt < 32; kt++) {
        const int pb = kt & 1;
        const __half* Ksp = pb ? Kb1 : Kb0;
        const __half* Vsp = pb ? Vb1 : Vb0;

        // prefetch tile kt+1 into the buffer freed by last iteration's sync
        if (kt >= 1 && kt + 1 < 32) {
            __half* Kd = pb ? Kb0 : Kb1;
            __half* Vd = pb ? Vb0 : Vb1;
            #pragma unroll
            for (int i = 0; i < 4; i++) {
                int idx = tid + i * 128;
                int r = idx >> 3, c = (idx & 7) * 8;
                const __half* src = base + (long long)((kt + 1) * 64 + r) * 3072;
                CP_ASYNC16(smem_u32(&Kd[r * QSP + c]), src + 64 + c);
                CP_ASYNC16(smem_u32(&Vd[r * QSP + c]), src + 128 + c);
            }
        }
        CP_COMMIT();

        // ---- S = Q @ K^T : accumulators in registers ----
        float sf[2][8][4];
        #pragma unroll
        for (int mi = 0; mi < 2; mi++)
            #pragma unroll
            for (int n = 0; n < 8; n++)
                #pragma unroll
                for (int e = 0; e < 4; e++) sf[mi][n][e] = 0.0f;

        #pragma unroll
        for (int kc = 0; kc < 4; kc++)
            #pragma unroll
            for (int njp = 0; njp < 4; njp++) {
                unsigned r0, r1, r2, r3;
                unsigned a = smem_u32(&Ksp[(njp * 16 + kb_row) * QSP + kc * 16 + kb_col]);
                LDSM_X4(r0, r1, r2, r3, a);
                #pragma unroll
                for (int mi = 0; mi < 2; mi++) {
                    MMA16816(sf[mi][2 * njp],
                             qf[mi][kc][0], qf[mi][kc][1], qf[mi][kc][2], qf[mi][kc][3],
                             r0, r1);
                    MMA16816(sf[mi][2 * njp + 1],
                             qf[mi][kc][0], qf[mi][kc][1], qf[mi][kc][2], qf[mi][kc][3],
                             r2, r3);
                }
            }

        // ---- warp-local online softmax (log2 domain, scale folded) ----
        unsigned ph[2][8][2];
        #pragma unroll
        for (int mi = 0; mi < 2; mi++)
            #pragma unroll
            for (int rp = 0; rp < 2; rp++) {
                float mold = mreg[mi][rp];
                float mx = -1e30f;
                #pragma unroll
                for (int n = 0; n < 8; n++)
                    mx = fmaxf(mx, fmaxf(sf[mi][n][2 * rp], sf[mi][n][2 * rp + 1]));
                mx = fmaxf(mx, __shfl_xor_sync(0xffffffffu, mx, 1));
                mx = fmaxf(mx, __shfl_xor_sync(0xffffffffu, mx, 2));
                float mnew = fmaxf(mold, mx * QSCALE);
                float s = 0.0f;
                #pragma unroll
                for (int n = 0; n < 8; n++) {
                    float p0 = fexp2(__fmaf_rn(sf[mi][n][2 * rp], QSCALE, -mnew));
                    float p1 = fexp2(__fmaf_rn(sf[mi][n][2 * rp + 1], QSCALE, -mnew));
                    s += p0 + p1;
                    ph[mi][n][rp] = h2_as_u32(__floats2half2_rn(p0, p1));
                }
                s += __shfl_xor_sync(0xffffffffu, s, 1);
                s += __shfl_xor_sync(0xffffffffu, s, 2);
                float alpha = fexp2(mold - mnew);
                lreg[mi][rp] = lreg[mi][rp] * alpha + s;
                mreg[mi][rp] = mnew;
                #pragma unroll
                for (int v = 0; v < 8; v++) {
                    of[mi][v][2 * rp]     *= alpha;
                    of[mi][v][2 * rp + 1] *= alpha;
                }
            }

        // ---- O += P @ V : P-frags straight from registers ----
        #pragma unroll
        for (int kc = 0; kc < 4; kc++)
            #pragma unroll
            for (int vjp = 0; vjp < 4; vjp++) {
                unsigned r0, r1, r2, r3;
                unsigned a = smem_u32(&Vsp[(kc * 16 + vb_row) * QSP + vjp * 16 + vb_col]);
                LDSM_X4_T(r0, r1, r2, r3, a);
                #pragma unroll
                for (int mi = 0; mi < 2; mi++) {
                    MMA16816(of[mi][2 * vjp],
                             ph[mi][2 * kc][0], ph[mi][2 * kc][1],
                             ph[mi][2 * kc + 1][0], ph[mi][2 * kc + 1][1],
                             r0, r1);
                    MMA16816(of[mi][2 * vjp + 1],
                             ph[mi][2 * kc][0], ph[mi][2 * kc][1],
                             ph[mi][2 * kc + 1][0], ph[mi][2 * kc + 1][1],
                             r2, r3);
                }
            }

        CP_WAIT(0);        // tile kt+1 resident
        __syncthreads();   // visible to all; buffers safe to swap
    }

    // ---- epilogue: normalize and store fp16 ----
    #pragma unroll
    for (int mi = 0; mi < 2; mi++)
        #pragma unroll
        for (int rp = 0; rp < 2; rp++) {
            float inv = __frcp_rn(lreg[mi][rp]);
            int row = q0 + wr + mi * 16 + g + rp * 8;
            __half* dst = attn + (long long)(b * 2048 + row) * 1024 + h * 64;
            #pragma unroll
            for (int v = 0; v < 8; v++) {
                __half2 hv = __floats2half2_rn(of[mi][v][2 * rp] * inv,
                                               of[mi][v][2 * rp + 1] * inv);
                *reinterpret_cast<unsigned*>(dst + v * 8 + 2 * t) = h2_as_u32(hv);
            }
        }
}

// ---------------------------------------------------------------------------
// Orchestration.
// ---------------------------------------------------------------------------
extern "C" void kernel_launch(void* const* d_in, const int* in_sizes, int n_in,
                              void* d_out, int out_size)
{
    (void)in_sizes; (void)n_in; (void)out_size;
    const float* x     = (const float*)d_in[0];
    const float* w_qkv = (const float*)d_in[1];
    const float* b_qkv = (const float*)d_in[2];
    const float* w_o   = (const float*)d_in[3];
    const float* b_o   = (const float*)d_in[4];
    float* out = (float*)d_out;

    __half *xh, *wqkvh, *woh, *qkvh, *attnh;
    cudaGetSymbolAddress((void**)&xh,    g_xh);
    cudaGetSymbolAddress((void**)&wqkvh, g_wqkvh);
    cudaGetSymbolAddress((void**)&woh,   g_woh);
    cudaGetSymbolAddress((void**)&qkvh,  g_qkvh);
    cudaGetSymbolAddress((void**)&attnh, g_attnh);

    cudaFuncSetAttribute(gemm_bias_f16_kernel<true>,
                         cudaFuncAttributeMaxDynamicSharedMemorySize, GEMM_SMEM);
    cudaFuncSetAttribute(gemm_bias_f16_kernel<false>,
                         cudaFuncAttributeMaxDynamicSharedMemorySize, GEMM_SMEM);
    cudaFuncSetAttribute(flash_attn_kernel,
                         cudaFuncAttributeMaxDynamicSharedMemorySize, FA_SMEM_BYTES);

    f32_to_f16_kernel<<<4096LL * 1024 / 2048, 256>>>(x, xh);
    f32_to_f16_kernel<<<3072LL * 1024 / 2048, 256>>>(w_qkv, wqkvh);
    f32_to_f16_kernel<<<1024LL * 1024 / 2048, 256>>>(w_o, woh);

    gemm_bias_f16_kernel<true><<<dim3(24, 32), 512, GEMM_SMEM>>>(
        xh, wqkvh, b_qkv, qkvh, 1024, 1024, 3072, 1024);

    flash_attn_kernel<<<dim3(16, 32), 128, FA_SMEM_BYTES>>>(qkvh, attnh);

    gemm_bias_f16_kernel<false><<<dim3(8, 32), 512, GEMM_SMEM>>>(
        attnh, woh, b_o, out, 1024, 1024, 1024, 1024);
}

// round 11
// speedup vs baseline: 6.8947x; 1.0136x over previous
#include <cuda_runtime.h>
#include <cuda_fp16.h>

// ---------------------------------------------------------------------------
// B=2, S=2048, D=1024, H=16, hd=64. fp16 datapath, fp32 accumulate.
// ---------------------------------------------------------------------------
__device__ __align__(256) __half g_xh[4096LL * 1024];
__device__ __align__(256) __half g_wqkvh[3072LL * 1024];
__device__ __align__(256) __half g_woh[1024LL * 1024];
__device__ __align__(256) __half g_qkvh[4096LL * 3072];   // per-head [q|k|v]
__device__ __align__(256) __half g_attnh[4096LL * 1024];

__device__ __forceinline__ unsigned h2_as_u32(__half2 h) {
    return *reinterpret_cast<unsigned*>(&h);
}
__device__ __forceinline__ float fexp2(float x) {
    float r;
    asm("ex2.approx.ftz.f32 %0, %1;" : "=f"(r) : "f"(x));
    return r;
}
__device__ __forceinline__ unsigned smem_u32(const void* p) {
    return (unsigned)__cvta_generic_to_shared(p);
}
#define CP_ASYNC16(dst_u32, src_ptr)                                        \
    asm volatile("cp.async.cg.shared.global [%0], [%1], 16;\n" ::           \
                 "r"(dst_u32), "l"(src_ptr))
#define CP_COMMIT() asm volatile("cp.async.commit_group;\n" ::: "memory")
#define CP_WAIT(n)  asm volatile("cp.async.wait_group %0;\n" :: "n"(n) : "memory")

#define LDSM_X4(r0, r1, r2, r3, a)                                           \
    asm volatile("ldmatrix.sync.aligned.m8n8.x4.shared.b16 {%0,%1,%2,%3}, [%4];" \
                 : "=r"(r0), "=r"(r1), "=r"(r2), "=r"(r3) : "r"(a))
#define LDSM_X4_T(r0, r1, r2, r3, a)                                         \
    asm volatile("ldmatrix.sync.aligned.m8n8.x4.trans.shared.b16 {%0,%1,%2,%3}, [%4];" \
                 : "=r"(r0), "=r"(r1), "=r"(r2), "=r"(r3) : "r"(a))
#define MMA16816(c, a0, a1, a2, a3, b0, b1)                                  \
    asm volatile("mma.sync.aligned.m16n8k16.row.col.f32.f16.f16.f32 "        \
                 "{%0,%1,%2,%3},{%4,%5,%6,%7},{%8,%9},{%0,%1,%2,%3};"        \
                 : "+f"((c)[0]), "+f"((c)[1]), "+f"((c)[2]), "+f"((c)[3])    \
                 : "r"(a0), "r"(a1), "r"(a2), "r"(a3), "r"(b0), "r"(b1))

// ---------------------------------------------------------------------------
// fp32 -> fp16 convert
// ---------------------------------------------------------------------------
__global__ void __launch_bounds__(256)
f32_to_f16_kernel(const float* __restrict__ in, __half* __restrict__ out)
{
    long long i = ((long long)blockIdx.x * 256 + threadIdx.x) * 8;
    float4 a = *reinterpret_cast<const float4*>(in + i);
    float4 b = *reinterpret_cast<const float4*>(in + i + 4);
    __half2* o = reinterpret_cast<__half2*>(out + i);
    o[0] = __floats2half2_rn(a.x, a.y);
    o[1] = __floats2half2_rn(a.z, a.w);
    o[2] = __floats2half2_rn(b.x, b.y);
    o[3] = __floats2half2_rn(b.z, b.w);
}

// ---------------------------------------------------------------------------
// fp16 GEMM, raw mma.m16n8k16: C = A @ B^T + bias.
// 256 threads (8 warps, 4M x 2N), block 256x128, warp tile 64x64, K-tile 64,
// 3-stage cp.async pipeline. 128 B smem traffic per HMMA (vs 256 for wmma
// 32x32). Bias added in epilogue from registers; direct stores (no staging).
// ---------------------------------------------------------------------------
constexpr int GBM = 256, GBN = 128, BKH = 72;      // padded k-row (halves)
constexpr int A_ST = GBM * BKH;                    // halves per A stage
constexpr int B_ST = GBN * BKH;
constexpr int STG  = A_ST + B_ST;                  // 27,648 halves = 55,296 B
constexpr int GEMM_SMEM = 3 * STG * 2;             // 165,888 B

template <bool OUT_HALF>
__global__ void __launch_bounds__(256, 1)
gemm_bias_f16_kernel(const __half* __restrict__ A, const __half* __restrict__ B,
                     const float* __restrict__ bias, void* __restrict__ Cv,
                     int lda, int ldb, int ldc, int K)
{
    extern __shared__ __half gsm[];

    const int tid  = threadIdx.x;
    const int lane = tid & 31;
    const int warp = tid >> 5;
    const int wm   = warp & 3;        // 0..3 -> 64-row slice
    const int wn   = warp >> 2;       // 0..1 -> 64-col slice
    const int m0   = blockIdx.y * GBM;
    const int n0   = blockIdx.x * GBN;
    const int g    = lane >> 2;
    const int t    = lane & 3;

    const int NT = K / 64;            // k-tiles

    auto load_tile = [&](int kt, int s) {
        __half* As = gsm + s * STG;
        __half* Bs = As + A_ST;
        const int k0 = kt * 64;
        #pragma unroll
        for (int i = 0; i < 8; i++) {                   // A: 256 x 64
            int idx = tid + i * 256;
            int r = idx >> 3, c = (idx & 7) * 8;
            CP_ASYNC16(smem_u32(&As[r * BKH + c]),
                       A + (long long)(m0 + r) * lda + k0 + c);
        }
        #pragma unroll
        for (int i = 0; i < 4; i++) {                   // B: 128 x 64
            int idx = tid + i * 256;
            int r = idx >> 3, c = (idx & 7) * 8;
            CP_ASYNC16(smem_u32(&Bs[r * BKH + c]),
                       B + (long long)(n0 + r) * ldb + k0 + c);
        }
    };

    // ldmatrix lane-address components (validated in flash kernel)
    const int a_row = ((lane >> 3) & 1) * 8 + (lane & 7);
    const int a_col = (lane >> 4) * 8;
    const int b_row = ((lane >> 4) & 1) * 8 + (lane & 7);
    const int b_col = ((lane >> 3) & 1) * 8;

    float acc[4][8][4];
    #pragma unroll
    for (int mi = 0; mi < 4; mi++)
        #pragma unroll
        for (int nj = 0; nj < 8; nj++)
            #pragma unroll
            for (int e = 0; e < 4; e++) acc[mi][nj][e] = 0.0f;

    load_tile(0, 0);
    CP_COMMIT();
    load_tile(1, 1);
    CP_COMMIT();

    for (int kt = 0; kt < NT; kt++) {
        CP_WAIT(1);            // tile kt resident (kt+1 may be in flight)
        __syncthreads();       // all warps done reading stage (kt+2)%3's old data

        if (kt + 2 < NT) load_tile(kt + 2, (kt + 2) % 3);
        CP_COMMIT();

        const __half* Asp = gsm + (kt % 3) * STG;
        const __half* Bsp = Asp + A_ST;

        #pragma unroll
        for (int kc = 0; kc < 4; kc++) {
            unsigned af[4][4], bf[4][4];
            #pragma unroll
            for (int mi = 0; mi < 4; mi++) {
                unsigned a = smem_u32(&Asp[(wm * 64 + mi * 16 + a_row) * BKH + kc * 16 + a_col]);
                LDSM_X4(af[mi][0], af[mi][1], af[mi][2], af[mi][3], a);
            }
            #pragma unroll
            for (int njp = 0; njp < 4; njp++) {
                unsigned a = smem_u32(&Bsp[(wn * 64 + njp * 16 + b_row) * BKH + kc * 16 + b_col]);
                LDSM_X4(bf[njp][0], bf[njp][1], bf[njp][2], bf[njp][3], a);
            }
            #pragma unroll
            for (int mi = 0; mi < 4; mi++)
                #pragma unroll
                for (int njp = 0; njp < 4; njp++) {
                    MMA16816(acc[mi][2 * njp],
                             af[mi][0], af[mi][1], af[mi][2], af[mi][3],
                             bf[njp][0], bf[njp][1]);
                    MMA16816(acc[mi][2 * njp + 1],
                             af[mi][0], af[mi][1], af[mi][2], af[mi][3],
                             bf[njp][2], bf[njp][3]);
                }
        }
    }

    // ---- epilogue: bias + direct store from registers ----
    #pragma unroll
    for (int mi = 0; mi < 4; mi++)
        #pragma unroll
        for (int rp = 0; rp < 2; rp++) {
            int row = m0 + wm * 64 + mi * 16 + g + rp * 8;
            #pragma unroll
            for (int nj = 0; nj < 8; nj++) {
                int col = n0 + wn * 64 + nj * 8 + 2 * t;
                float c0 = acc[mi][nj][2 * rp]     + __ldg(bias + col);
                float c1 = acc[mi][nj][2 * rp + 1] + __ldg(bias + col + 1);
                if (OUT_HALF) {
                    __half* C = reinterpret_cast<__half*>(Cv);
                    *reinterpret_cast<unsigned*>(C + (long long)row * ldc + col) =
                        h2_as_u32(__floats2half2_rn(c0, c1));
                } else {
                    float* C = reinterpret_cast<float*>(Cv);
                    float2 v = make_float2(c0, c1);
                    *reinterpret_cast<float2*>(C + (long long)row * ldc + col) = v;
                }
            }
        }
}

// ---------------------------------------------------------------------------
// Flash attention, FA2-style register pipeline (UNCHANGED from R10 pass).
// ---------------------------------------------------------------------------
constexpr int QSP = 72;
constexpr int FA_Q_BYTES  = 128 * QSP * 2;
constexpr int FA_KV_BYTES = 64 * QSP * 2;
constexpr int FA_SMEM_BYTES = FA_Q_BYTES + 4 * FA_KV_BYTES;  // 55,296

__global__ void __launch_bounds__(128)
flash_attn_kernel(const __half* __restrict__ qkv, __half* __restrict__ attn)
{
    extern __shared__ char fsm[];
    __half* Qs  = reinterpret_cast<__half*>(fsm);
    __half* Kb0 = Qs + 128 * QSP;
    __half* Kb1 = Kb0 + 64 * QSP;
    __half* Vb0 = Kb1 + 64 * QSP;
    __half* Vb1 = Vb0 + 64 * QSP;

    const int tid  = threadIdx.x;
    const int lane = tid & 31;
    const int warp = tid >> 5;
    const int wr   = warp * 32;
    const int g    = lane >> 2;
    const int t    = lane & 3;

    const int bh = blockIdx.y;
    const int b  = bh >> 4;
    const int h  = bh & 15;
    const int q0 = blockIdx.x * 128;

    const float QSCALE = 0.125f * 1.44269504f;
    const __half* base = qkv + (long long)b * 2048 * 3072 + h * 192;

    #pragma unroll
    for (int i = 0; i < 8; i++) {
        int idx = tid + i * 128;
        int r = idx >> 3, c = (idx & 7) * 8;
        CP_ASYNC16(smem_u32(&Qs[r * QSP + c]),
                   base + (long long)(q0 + r) * 3072 + c);
    }
    #pragma unroll
    for (int i = 0; i < 4; i++) {
        int idx = tid + i * 128;
        int r = idx >> 3, c = (idx & 7) * 8;
        CP_ASYNC16(smem_u32(&Kb0[r * QSP + c]), base + (long long)r * 3072 + 64 + c);
        CP_ASYNC16(smem_u32(&Vb0[r * QSP + c]), base + (long long)r * 3072 + 128 + c);
    }
    CP_COMMIT();
    #pragma unroll
    for (int i = 0; i < 4; i++) {
        int idx = tid + i * 128;
        int r = idx >> 3, c = (idx & 7) * 8;
        CP_ASYNC16(smem_u32(&Kb1[r * QSP + c]),
                   base + (long long)(64 + r) * 3072 + 64 + c);
        CP_ASYNC16(smem_u32(&Vb1[r * QSP + c]),
                   base + (long long)(64 + r) * 3072 + 128 + c);
    }
    CP_COMMIT();
    CP_WAIT(1);
    __syncthreads();

    unsigned qf[2][4][4];
    {
        int lrow = ((lane >> 3) & 1) * 8 + (lane & 7);
        int lcol = (lane >> 4) * 8;
        #pragma unroll
        for (int mi = 0; mi < 2; mi++)
            #pragma unroll
            for (int kc = 0; kc < 4; kc++) {
                unsigned a = smem_u32(&Qs[(wr + mi * 16 + lrow) * QSP + kc * 16 + lcol]);
                LDSM_X4(qf[mi][kc][0], qf[mi][kc][1], qf[mi][kc][2], qf[mi][kc][3], a);
            }
    }

    float of[2][8][4];
    #pragma unroll
    for (int mi = 0; mi < 2; mi++)
        #pragma unroll
        for (int v = 0; v < 8; v++)
            #pragma unroll
            for (int e = 0; e < 4; e++) of[mi][v][e] = 0.0f;
    float mreg[2][2] = {{-1e30f, -1e30f}, {-1e30f, -1e30f}};
    float lreg[2][2] = {{0.0f, 0.0f}, {0.0f, 0.0f}};

    const int kb_row = ((lane >> 4) & 1) * 8 + (lane & 7);
    const int kb_col = ((lane >> 3) & 1) * 8;
    const int vb_row = ((lane >> 3) & 1) * 8 + (lane & 7);
    const int vb_col = ((lane >> 4) & 1) * 8;

    for (int kt = 0; kt < 32; kt++) {
        const int pb = kt & 1;
        const __half* Ksp = pb ? Kb1 : Kb0;
        const __half* Vsp = pb ? Vb1 : Vb0;

        if (kt >= 1 && kt + 1 < 32) {
            __half* Kd = pb ? Kb0 : Kb1;
            __half* Vd = pb ? Vb0 : Vb1;
            #pragma unroll
            for (int i = 0; i < 4; i++) {
                int idx = tid + i * 128;
                int r = idx >> 3, c = (idx & 7) * 8;
                const __half* src = base + (long long)((kt + 1) * 64 + r) * 3072;
                CP_ASYNC16(smem_u32(&Kd[r * QSP + c]), src + 64 + c);
                CP_ASYNC16(smem_u32(&Vd[r * QSP + c]), src + 128 + c);
            }
        }
        CP_COMMIT();

        float sf[2][8][4];
        #pragma unroll
        for (int mi = 0; mi < 2; mi++)
            #pragma unroll
            for (int n = 0; n < 8; n++)
                #pragma unroll
                for (int e = 0; e < 4; e++) sf[mi][n][e] = 0.0f;

        #pragma unroll
        for (int kc = 0; kc < 4; kc++)
            #pragma unroll
            for (int njp = 0; njp < 4; njp++) {
                unsigned r0, r1, r2, r3;
                unsigned a = smem_u32(&Ksp[(njp * 16 + kb_row) * QSP + kc * 16 + kb_col]);
                LDSM_X4(r0, r1, r2, r3, a);
                #pragma unroll
                for (int mi = 0; mi < 2; mi++) {
                    MMA16816(sf[mi][2 * njp],
                             qf[mi][kc][0], qf[mi][kc][1], qf[mi][kc][2], qf[mi][kc][3],
                             r0, r1);
                    MMA16816(sf[mi][2 * njp + 1],
                             qf[mi][kc][0], qf[mi][kc][1], qf[mi][kc][2], qf[mi][kc][3],
                             r2, r3);
                }
            }

        unsigned ph[2][8][2];
        #pragma unroll
        for (int mi = 0; mi < 2; mi++)
            #pragma unroll
            for (int rp = 0; rp < 2; rp++) {
                float mold = mreg[mi][rp];
                float mx = -1e30f;
                #pragma unroll
                for (int n = 0; n < 8; n++)
                    mx = fmaxf(mx, fmaxf(sf[mi][n][2 * rp], sf[mi][n][2 * rp + 1]));
                mx = fmaxf(mx, __shfl_xor_sync(0xffffffffu, mx, 1));
                mx = fmaxf(mx, __shfl_xor_sync(0xffffffffu, mx, 2));
                float mnew = fmaxf(mold, mx * QSCALE);
                float s = 0.0f;
                #pragma unroll
                for (int n = 0; n < 8; n++) {
                    float p0 = fexp2(__fmaf_rn(sf[mi][n][2 * rp], QSCALE, -mnew));
                    float p1 = fexp2(__fmaf_rn(sf[mi][n][2 * rp + 1], QSCALE, -mnew));
                    s += p0 + p1;
                    ph[mi][n][rp] = h2_as_u32(__floats2half2_rn(p0, p1));
                }
                s += __shfl_xor_sync(0xffffffffu, s, 1);
                s += __shfl_xor_sync(0xffffffffu, s, 2);
                float alpha = fexp2(mold - mnew);
                lreg[mi][rp] = lreg[mi][rp] * alpha + s;
                mreg[mi][rp] = mnew;
                #pragma unroll
                for (int v = 0; v < 8; v++) {
                    of[mi][v][2 * rp]     *= alpha;
                    of[mi][v][2 * rp + 1] *= alpha;
                }
            }

        #pragma unroll
        for (int kc = 0; kc < 4; kc++)
            #pragma unroll
            for (int vjp = 0; vjp < 4; vjp++) {
                unsigned r0, r1, r2, r3;
                unsigned a = smem_u32(&Vsp[(kc * 16 + vb_row) * QSP + vjp * 16 + vb_col]);
                LDSM_X4_T(r0, r1, r2, r3, a);
                #pragma unroll
                for (int mi = 0; mi < 2; mi++) {
                    MMA16816(of[mi][2 * vjp],
                             ph[mi][2 * kc][0], ph[mi][2 * kc][1],
                             ph[mi][2 * kc + 1][0], ph[mi][2 * kc + 1][1],
                             r0, r1);
                    MMA16816(of[mi][2 * vjp + 1],
                             ph[mi][2 * kc][0], ph[mi][2 * kc][1],
                             ph[mi][2 * kc + 1][0], ph[mi][2 * kc + 1][1],
                             r2, r3);
                }
            }

        CP_WAIT(0);
        __syncthreads();
    }

    #pragma unroll
    for (int mi = 0; mi < 2; mi++)
        #pragma unroll
        for (int rp = 0; rp < 2; rp++) {
            float inv = __frcp_rn(lreg[mi][rp]);
            int row = q0 + wr + mi * 16 + g + rp * 8;
            __half* dst = attn + (long long)(b * 2048 + row) * 1024 + h * 64;
            #pragma unroll
            for (int v = 0; v < 8; v++) {
                __half2 hv = __floats2half2_rn(of[mi][v][2 * rp] * inv,
                                               of[mi][v][2 * rp + 1] * inv);
                *reinterpret_cast<unsigned*>(dst + v * 8 + 2 * t) = h2_as_u32(hv);
            }
        }
}

// ---------------------------------------------------------------------------
// Orchestration.
// ---------------------------------------------------------------------------
extern "C" void kernel_launch(void* const* d_in, const int* in_sizes, int n_in,
                              void* d_out, int out_size)
{
    (void)in_sizes; (void)n_in; (void)out_size;
    const float* x     = (const float*)d_in[0];
    const float* w_qkv = (const float*)d_in[1];
    const float* b_qkv = (const float*)d_in[2];
    const float* w_o   = (const float*)d_in[3];
    const float* b_o   = (const float*)d_in[4];
    float* out = (float*)d_out;

    __half *xh, *wqkvh, *woh, *qkvh, *attnh;
    cudaGetSymbolAddress((void**)&xh,    g_xh);
    cudaGetSymbolAddress((void**)&wqkvh, g_wqkvh);
    cudaGetSymbolAddress((void**)&woh,   g_woh);
    cudaGetSymbolAddress((void**)&qkvh,  g_qkvh);
    cudaGetSymbolAddress((void**)&attnh, g_attnh);

    cudaFuncSetAttribute(gemm_bias_f16_kernel<true>,
                         cudaFuncAttributeMaxDynamicSharedMemorySize, GEMM_SMEM);
    cudaFuncSetAttribute(gemm_bias_f16_kernel<false>,
                         cudaFuncAttributeMaxDynamicSharedMemorySize, GEMM_SMEM);
    cudaFuncSetAttribute(flash_attn_kernel,
                         cudaFuncAttributeMaxDynamicSharedMemorySize, FA_SMEM_BYTES);

    f32_to_f16_kernel<<<4096LL * 1024 / 2048, 256>>>(x, xh);
    f32_to_f16_kernel<<<3072LL * 1024 / 2048, 256>>>(w_qkv, wqkvh);
    f32_to_f16_kernel<<<1024LL * 1024 / 2048, 256>>>(w_o, woh);

    // 1) qkvh = xh @ wqkvh^T + b_qkv   (fp16 out)   grid (3072/128, 4096/256)
    gemm_bias_f16_kernel<true><<<dim3(24, 16), 256, GEMM_SMEM>>>(
        xh, wqkvh, b_qkv, qkvh, 1024, 1024, 3072, 1024);

    // 2) fused attention -> attnh (fp16)
    flash_attn_kernel<<<dim3(16, 32), 128, FA_SMEM_BYTES>>>(qkvh, attnh);

    // 3) out = attnh @ woh^T + b_o     (fp32 out)   grid (1024/128, 4096/256)
    gemm_bias_f16_kernel<false><<<dim3(8, 16), 256, GEMM_SMEM>>>(
        attnh, woh, b_o, out, 1024, 1024, 1024, 1024);
}

// round 13
// speedup vs baseline: 7.0404x; 1.0211x over previous
#include <cuda_runtime.h>
#include <cuda_fp16.h>

// ---------------------------------------------------------------------------
// B=2, S=2048, D=1024, H=16, hd=64. fp16 datapath, fp32 accumulate.
// ---------------------------------------------------------------------------
__device__ __align__(256) __half g_xh[4096LL * 1024];
__device__ __align__(256) __half g_wqkvh[3072LL * 1024];
__device__ __align__(256) __half g_woh[1024LL * 1024];
__device__ __align__(256) __half g_qkvh[4096LL * 3072];   // per-head [q|k|v]
__device__ __align__(256) __half g_attnh[4096LL * 1024];

__device__ __forceinline__ unsigned h2_as_u32(__half2 h) {
    return *reinterpret_cast<unsigned*>(&h);
}
__device__ __forceinline__ float fexp2(float x) {
    float r;
    asm("ex2.approx.ftz.f32 %0, %1;" : "=f"(r) : "f"(x));
    return r;
}
__device__ __forceinline__ unsigned smem_u32(const void* p) {
    return (unsigned)__cvta_generic_to_shared(p);
}
#define CP_ASYNC16(dst_u32, src_ptr)                                        \
    asm volatile("cp.async.cg.shared.global [%0], [%1], 16;\n" ::           \
                 "r"(dst_u32), "l"(src_ptr))
#define CP_COMMIT() asm volatile("cp.async.commit_group;\n" ::: "memory")
#define CP_WAIT(n)  asm volatile("cp.async.wait_group %0;\n" :: "n"(n) : "memory")

#define LDSM_X4(r0, r1, r2, r3, a)                                           \
    asm volatile("ldmatrix.sync.aligned.m8n8.x4.shared.b16 {%0,%1,%2,%3}, [%4];" \
                 : "=r"(r0), "=r"(r1), "=r"(r2), "=r"(r3) : "r"(a))
#define LDSM_X4_T(r0, r1, r2, r3, a)                                         \
    asm volatile("ldmatrix.sync.aligned.m8n8.x4.trans.shared.b16 {%0,%1,%2,%3}, [%4];" \
                 : "=r"(r0), "=r"(r1), "=r"(r2), "=r"(r3) : "r"(a))
#define MMA16816(c, a0, a1, a2, a3, b0, b1)                                  \
    asm volatile("mma.sync.aligned.m16n8k16.row.col.f32.f16.f16.f32 "        \
                 "{%0,%1,%2,%3},{%4,%5,%6,%7},{%8,%9},{%0,%1,%2,%3};"        \
                 : "+f"((c)[0]), "+f"((c)[1]), "+f"((c)[2]), "+f"((c)[3])    \
                 : "r"(a0), "r"(a1), "r"(a2), "r"(a3), "r"(b0), "r"(b1))

// ---------------------------------------------------------------------------
// Fused fp32 -> fp16 convert for x (2048 blk), w_qkv (1536 blk), w_o (512 blk)
// ---------------------------------------------------------------------------
__global__ void __launch_bounds__(256)
convert_all_kernel(const float* __restrict__ x,     __half* __restrict__ xh,
                   const float* __restrict__ wqkv,  __half* __restrict__ wqkvh,
                   const float* __restrict__ wo,    __half* __restrict__ woh)
{
    const float* in;
    __half* out;
    long long blk = blockIdx.x;
    if (blk < 2048)       { in = x;    out = xh; }
    else if (blk < 3584)  { in = wqkv; out = wqkvh; blk -= 2048; }
    else                  { in = wo;   out = woh;   blk -= 3584; }
    long long i = (blk * 256 + threadIdx.x) * 8;
    float4 a = *reinterpret_cast<const float4*>(in + i);
    float4 b = *reinterpret_cast<const float4*>(in + i + 4);
    __half2* o = reinterpret_cast<__half2*>(out + i);
    o[0] = __floats2half2_rn(a.x, a.y);
    o[1] = __floats2half2_rn(a.z, a.w);
    o[2] = __floats2half2_rn(b.x, b.y);
    o[3] = __floats2half2_rn(b.z, b.w);
}

// ---------------------------------------------------------------------------
// fp16 GEMM, raw mma.m16n8k16 (UNCHANGED from passing R11): C = A @ B^T + bias.
// 256 threads (8 warps, 4M x 2N), block 256x128, warp tile 64x64, K-tile 64,
// 3-stage cp.async pipeline.
// ---------------------------------------------------------------------------
constexpr int GBM = 256, GBN = 128, BKH = 72;
constexpr int A_ST = GBM * BKH;
constexpr int B_ST = GBN * BKH;
constexpr int STG  = A_ST + B_ST;
constexpr int GEMM_SMEM = 3 * STG * 2;             // 165,888 B

template <bool OUT_HALF>
__global__ void __launch_bounds__(256, 1)
gemm_bias_f16_kernel(const __half* __restrict__ A, const __half* __restrict__ B,
                     const float* __restrict__ bias, void* __restrict__ Cv,
                     int lda, int ldb, int ldc, int K)
{
    extern __shared__ __half gsm[];

    const int tid  = threadIdx.x;
    const int lane = tid & 31;
    const int warp = tid >> 5;
    const int wm   = warp & 3;
    const int wn   = warp >> 2;
    const int m0   = blockIdx.y * GBM;
    const int n0   = blockIdx.x * GBN;
    const int g    = lane >> 2;
    const int t    = lane & 3;

    const int NT = K / 64;

    auto load_tile = [&](int kt, int s) {
        __half* As = gsm + s * STG;
        __half* Bs = As + A_ST;
        const int k0 = kt * 64;
        #pragma unroll
        for (int i = 0; i < 8; i++) {
            int idx = tid + i * 256;
            int r = idx >> 3, c = (idx & 7) * 8;
            CP_ASYNC16(smem_u32(&As[r * BKH + c]),
                       A + (long long)(m0 + r) * lda + k0 + c);
        }
        #pragma unroll
        for (int i = 0; i < 4; i++) {
            int idx = tid + i * 256;
            int r = idx >> 3, c = (idx & 7) * 8;
            CP_ASYNC16(smem_u32(&Bs[r * BKH + c]),
                       B + (long long)(n0 + r) * ldb + k0 + c);
        }
    };

    const int a_row = ((lane >> 3) & 1) * 8 + (lane & 7);
    const int a_col = (lane >> 4) * 8;
    const int b_row = ((lane >> 4) & 1) * 8 + (lane & 7);
    const int b_col = ((lane >> 3) & 1) * 8;

    float acc[4][8][4];
    #pragma unroll
    for (int mi = 0; mi < 4; mi++)
        #pragma unroll
        for (int nj = 0; nj < 8; nj++)
            #pragma unroll
            for (int e = 0; e < 4; e++) acc[mi][nj][e] = 0.0f;

    load_tile(0, 0);
    CP_COMMIT();
    load_tile(1, 1);
    CP_COMMIT();

    for (int kt = 0; kt < NT; kt++) {
        CP_WAIT(1);
        __syncthreads();

        if (kt + 2 < NT) load_tile(kt + 2, (kt + 2) % 3);
        CP_COMMIT();

        const __half* Asp = gsm + (kt % 3) * STG;
        const __half* Bsp = Asp + A_ST;

        #pragma unroll
        for (int kc = 0; kc < 4; kc++) {
            unsigned af[4][4], bf[4][4];
            #pragma unroll
            for (int mi = 0; mi < 4; mi++) {
                unsigned a = smem_u32(&Asp[(wm * 64 + mi * 16 + a_row) * BKH + kc * 16 + a_col]);
                LDSM_X4(af[mi][0], af[mi][1], af[mi][2], af[mi][3], a);
            }
            #pragma unroll
            for (int njp = 0; njp < 4; njp++) {
                unsigned a = smem_u32(&Bsp[(wn * 64 + njp * 16 + b_row) * BKH + kc * 16 + b_col]);
                LDSM_X4(bf[njp][0], bf[njp][1], bf[njp][2], bf[njp][3], a);
            }
            #pragma unroll
            for (int mi = 0; mi < 4; mi++)
                #pragma unroll
                for (int njp = 0; njp < 4; njp++) {
                    MMA16816(acc[mi][2 * njp],
                             af[mi][0], af[mi][1], af[mi][2], af[mi][3],
                             bf[njp][0], bf[njp][1]);
                    MMA16816(acc[mi][2 * njp + 1],
                             af[mi][0], af[mi][1], af[mi][2], af[mi][3],
                             bf[njp][2], bf[njp][3]);
                }
        }
    }

    #pragma unroll
    for (int mi = 0; mi < 4; mi++)
        #pragma unroll
        for (int rp = 0; rp < 2; rp++) {
            int row = m0 + wm * 64 + mi * 16 + g + rp * 8;
            #pragma unroll
            for (int nj = 0; nj < 8; nj++) {
                int col = n0 + wn * 64 + nj * 8 + 2 * t;
                float c0 = acc[mi][nj][2 * rp]     + __ldg(bias + col);
                float c1 = acc[mi][nj][2 * rp + 1] + __ldg(bias + col + 1);
                if (OUT_HALF) {
                    __half* C = reinterpret_cast<__half*>(Cv);
                    *reinterpret_cast<unsigned*>(C + (long long)row * ldc + col) =
                        h2_as_u32(__floats2half2_rn(c0, c1));
                } else {
                    float* C = reinterpret_cast<float*>(Cv);
                    float2 v = make_float2(c0, c1);
                    *reinterpret_cast<float2*>(C + (long long)row * ldc + col) = v;
                }
            }
        }
}

// ---------------------------------------------------------------------------
// Flash attention, FA2-style register pipeline. q-tile 64 rows (warp owns 16
// rows x all cols) -> ~150 regs, 46 KB smem, ~3 CTAs/SM, 1024 CTAs.
// Same validated instruction stream as the 128-row version minus the mi loop.
// ---------------------------------------------------------------------------
constexpr int QSP = 72;
constexpr int FA_SMEM_BYTES = 5 * 64 * QSP * 2;    // Q + 2K + 2V = 46,080 B

__global__ void __launch_bounds__(128)
flash_attn_kernel(const __half* __restrict__ qkv, __half* __restrict__ attn)
{
    extern __shared__ char fsm[];
    __half* Qs  = reinterpret_cast<__half*>(fsm);         // 64 x QSP
    __half* Kb0 = Qs + 64 * QSP;
    __half* Kb1 = Kb0 + 64 * QSP;
    __half* Vb0 = Kb1 + 64 * QSP;
    __half* Vb1 = Vb0 + 64 * QSP;

    const int tid  = threadIdx.x;
    const int lane = tid & 31;
    const int warp = tid >> 5;
    const int wr   = warp * 16;         // warp's first q-row in 64-row tile
    const int g    = lane >> 2;
    const int t    = lane & 3;

    const int bh = blockIdx.y;
    const int b  = bh >> 4;
    const int h  = bh & 15;
    const int q0 = blockIdx.x * 64;

    const float QSCALE = 0.125f * 1.44269504f;
    const __half* base = qkv + (long long)b * 2048 * 3072 + h * 192;

    // ---- prologue: Q + tiles 0,1 ----
    #pragma unroll
    for (int i = 0; i < 4; i++) {              // Q: 64 rows x 8 chunks
        int idx = tid + i * 128;
        int r = idx >> 3, c = (idx & 7) * 8;
        CP_ASYNC16(smem_u32(&Qs[r * QSP + c]),
                   base + (long long)(q0 + r) * 3072 + c);
    }
    #pragma unroll
    for (int i = 0; i < 4; i++) {
        int idx = tid + i * 128;
        int r = idx >> 3, c = (idx & 7) * 8;
        CP_ASYNC16(smem_u32(&Kb0[r * QSP + c]), base + (long long)r * 3072 + 64 + c);
        CP_ASYNC16(smem_u32(&Vb0[r * QSP + c]), base + (long long)r * 3072 + 128 + c);
    }
    CP_COMMIT();
    #pragma unroll
    for (int i = 0; i < 4; i++) {
        int idx = tid + i * 128;
        int r = idx >> 3, c = (idx & 7) * 8;
        CP_ASYNC16(smem_u32(&Kb1[r * QSP + c]),
                   base + (long long)(64 + r) * 3072 + 64 + c);
        CP_ASYNC16(smem_u32(&Vb1[r * QSP + c]),
                   base + (long long)(64 + r) * 3072 + 128 + c);
    }
    CP_COMMIT();
    CP_WAIT(1);
    __syncthreads();

    // ---- Q fragments (16 rows per warp) ----
    unsigned qf[4][4];
    {
        int lrow = ((lane >> 3) & 1) * 8 + (lane & 7);
        int lcol = (lane >> 4) * 8;
        #pragma unroll
        for (int kc = 0; kc < 4; kc++) {
            unsigned a = smem_u32(&Qs[(wr + lrow) * QSP + kc * 16 + lcol]);
            LDSM_X4(qf[kc][0], qf[kc][1], qf[kc][2], qf[kc][3], a);
        }
    }

    float of[8][4];
    #pragma unroll
    for (int v = 0; v < 8; v++)
        #pragma unroll
        for (int e = 0; e < 4; e++) of[v][e] = 0.0f;
    float mreg[2] = {-1e30f, -1e30f};
    float lreg[2] = {0.0f, 0.0f};

    const int kb_row = ((lane >> 4) & 1) * 8 + (lane & 7);
    const int kb_col = ((lane >> 3) & 1) * 8;
    const int vb_row = ((lane >> 3) & 1) * 8 + (lane & 7);
    const int vb_col = ((lane >> 4) & 1) * 8;

    for (int kt = 0; kt < 32; kt++) {
        const int pb = kt & 1;
        const __half* Ksp = pb ? Kb1 : Kb0;
        const __half* Vsp = pb ? Vb1 : Vb0;

        if (kt >= 1 && kt + 1 < 32) {
            __half* Kd = pb ? Kb0 : Kb1;
            __half* Vd = pb ? Vb0 : Vb1;
            #pragma unroll
            for (int i = 0; i < 4; i++) {
                int idx = tid + i * 128;
                int r = idx >> 3, c = (idx & 7) * 8;
                const __half* src = base + (long long)((kt + 1) * 64 + r) * 3072;
                CP_ASYNC16(smem_u32(&Kd[r * QSP + c]), src + 64 + c);
                CP_ASYNC16(smem_u32(&Vd[r * QSP + c]), src + 128 + c);
            }
        }
        CP_COMMIT();

        // ---- S = Q @ K^T ----
        float sf[8][4];
        #pragma unroll
        for (int n = 0; n < 8; n++)
            #pragma unroll
            for (int e = 0; e < 4; e++) sf[n][e] = 0.0f;

        #pragma unroll
        for (int kc = 0; kc < 4; kc++)
            #pragma unroll
            for (int njp = 0; njp < 4; njp++) {
                unsigned r0, r1, r2, r3;
                unsigned a = smem_u32(&Ksp[(njp * 16 + kb_row) * QSP + kc * 16 + kb_col]);
                LDSM_X4(r0, r1, r2, r3, a);
                MMA16816(sf[2 * njp],     qf[kc][0], qf[kc][1], qf[kc][2], qf[kc][3], r0, r1);
                MMA16816(sf[2 * njp + 1], qf[kc][0], qf[kc][1], qf[kc][2], qf[kc][3], r2, r3);
            }

        // ---- warp-local online softmax ----
        unsigned ph[8][2];
        #pragma unroll
        for (int rp = 0; rp < 2; rp++) {
            float mold = mreg[rp];
            float mx = -1e30f;
            #pragma unroll
            for (int n = 0; n < 8; n++)
                mx = fmaxf(mx, fmaxf(sf[n][2 * rp], sf[n][2 * rp + 1]));
            mx = fmaxf(mx, __shfl_xor_sync(0xffffffffu, mx, 1));
            mx = fmaxf(mx, __shfl_xor_sync(0xffffffffu, mx, 2));
            float mnew = fmaxf(mold, mx * QSCALE);
            float s = 0.0f;
            #pragma unroll
            for (int n = 0; n < 8; n++) {
                float p0 = fexp2(__fmaf_rn(sf[n][2 * rp], QSCALE, -mnew));
                float p1 = fexp2(__fmaf_rn(sf[n][2 * rp + 1], QSCALE, -mnew));
                s += p0 + p1;
                ph[n][rp] = h2_as_u32(__floats2half2_rn(p0, p1));
            }
            s += __shfl_xor_sync(0xffffffffu, s, 1);
            s += __shfl_xor_sync(0xffffffffu, s, 2);
            float alpha = fexp2(mold - mnew);
            lreg[rp] = lreg[rp] * alpha + s;
            mreg[rp] = mnew;
            #pragma unroll
            for (int v = 0; v < 8; v++) {
                of[v][2 * rp]     *= alpha;
                of[v][2 * rp + 1] *= alpha;
            }
        }

        // ---- O += P @ V ----
        #pragma unroll
        for (int kc = 0; kc < 4; kc++)
            #pragma unroll
            for (int vjp = 0; vjp < 4; vjp++) {
                unsigned r0, r1, r2, r3;
                unsigned a = smem_u32(&Vsp[(kc * 16 + vb_row) * QSP + vjp * 16 + vb_col]);
                LDSM_X4_T(r0, r1, r2, r3, a);
                MMA16816(of[2 * vjp],
                         ph[2 * kc][0], ph[2 * kc][1],
                         ph[2 * kc + 1][0], ph[2 * kc + 1][1], r0, r1);
                MMA16816(of[2 * vjp + 1],
                         ph[2 * kc][0], ph[2 * kc][1],
                         ph[2 * kc + 1][0], ph[2 * kc + 1][1], r2, r3);
            }

        CP_WAIT(0);
        __syncthreads();
    }

    // ---- epilogue ----
    #pragma unroll
    for (int rp = 0; rp < 2; rp++) {
        float inv = __frcp_rn(lreg[rp]);
        int row = q0 + wr + g + rp * 8;
        __half* dst = attn + (long long)(b * 2048 + row) * 1024 + h * 64;
        #pragma unroll
        for (int v = 0; v < 8; v++) {
            __half2 hv = __floats2half2_rn(of[v][2 * rp] * inv,
                                           of[v][2 * rp + 1] * inv);
            *reinterpret_cast<unsigned*>(dst + v * 8 + 2 * t) = h2_as_u32(hv);
        }
    }
}

// ---------------------------------------------------------------------------
// Orchestration.
// ---------------------------------------------------------------------------
extern "C" void kernel_launch(void* const* d_in, const int* in_sizes, int n_in,
                              void* d_out, int out_size)
{
    (void)in_sizes; (void)n_in; (void)out_size;
    const float* x     = (const float*)d_in[0];
    const float* w_qkv = (const float*)d_in[1];
    const float* b_qkv = (const float*)d_in[2];
    const float* w_o   = (const float*)d_in[3];
    const float* b_o   = (const float*)d_in[4];
    float* out = (float*)d_out;

    __half *xh, *wqkvh, *woh, *qkvh, *attnh;
    cudaGetSymbolAddress((void**)&xh,    g_xh);
    cudaGetSymbolAddress((void**)&wqkvh, g_wqkvh);
    cudaGetSymbolAddress((void**)&woh,   g_woh);
    cudaGetSymbolAddress((void**)&qkvh,  g_qkvh);
    cudaGetSymbolAddress((void**)&attnh, g_attnh);

    cudaFuncSetAttribute(gemm_bias_f16_kernel<true>,
                         cudaFuncAttributeMaxDynamicSharedMemorySize, GEMM_SMEM);
    cudaFuncSetAttribute(gemm_bias_f16_kernel<false>,
                         cudaFuncAttributeMaxDynamicSharedMemorySize, GEMM_SMEM);
    cudaFuncSetAttribute(flash_attn_kernel,
                         cudaFuncAttributeMaxDynamicSharedMemorySize, FA_SMEM_BYTES);

    // 0) fused fp32->fp16 converts (x: 2048 blocks, w_qkv: 1536, w_o: 512)
    convert_all_kernel<<<4096, 256>>>(x, xh, w_qkv, wqkvh, w_o, woh);

    // 1) qkvh = xh @ wqkvh^T + b_qkv   (fp16 out)  grid (3072/128, 4096/256)
    gemm_bias_f16_kernel<true><<<dim3(24, 16), 256, GEMM_SMEM>>>(
        xh, wqkvh, b_qkv, qkvh, 1024, 1024, 3072, 1024);

    // 2) fused attention -> attnh (fp16)  grid (2048/64, B*H)
    flash_attn_kernel<<<dim3(32, 32), 128, FA_SMEM_BYTES>>>(qkvh, attnh);

    // 3) out = attnh @ woh^T + b_o     (fp32 out)  grid (1024/128, 4096/256)
    gemm_bias_f16_kernel<false><<<dim3(8, 16), 256, GEMM_SMEM>>>(
        attnh, woh, b_o, out, 1024, 1024, 1024, 1024);
}

// round 14
// speedup vs baseline: 7.3347x; 1.0418x over previous
#include <cuda_runtime.h>
#include <cuda_fp16.h>

// ---------------------------------------------------------------------------
// B=2, S=2048, D=1024, H=16, hd=64. fp16 datapath, fp32 accumulate.
// ---------------------------------------------------------------------------
__device__ __align__(256) __half g_xh[4096LL * 1024];
__device__ __align__(256) __half g_wqkvh[3072LL * 1024];
__device__ __align__(256) __half g_woh[1024LL * 1024];
__device__ __align__(256) __half g_qkvh[4096LL * 3072];   // per-head [q|k|v]
__device__ __align__(256) __half g_attnh[4096LL * 1024];

__device__ __forceinline__ unsigned h2_as_u32(__half2 h) {
    return *reinterpret_cast<unsigned*>(&h);
}
__device__ __forceinline__ float fexp2(float x) {
    float r;
    asm("ex2.approx.ftz.f32 %0, %1;" : "=f"(r) : "f"(x));
    return r;
}
__device__ __forceinline__ unsigned smem_u32(const void* p) {
    return (unsigned)__cvta_generic_to_shared(p);
}
#define CP_ASYNC16(dst_u32, src_ptr)                                        \
    asm volatile("cp.async.cg.shared.global [%0], [%1], 16;\n" ::           \
                 "r"(dst_u32), "l"(src_ptr))
#define CP_COMMIT() asm volatile("cp.async.commit_group;\n" ::: "memory")
#define CP_WAIT(n)  asm volatile("cp.async.wait_group %0;\n" :: "n"(n) : "memory")

#define LDSM_X4(r0, r1, r2, r3, a)                                           \
    asm volatile("ldmatrix.sync.aligned.m8n8.x4.shared.b16 {%0,%1,%2,%3}, [%4];" \
                 : "=r"(r0), "=r"(r1), "=r"(r2), "=r"(r3) : "r"(a))
#define LDSM_X4_T(r0, r1, r2, r3, a)                                         \
    asm volatile("ldmatrix.sync.aligned.m8n8.x4.trans.shared.b16 {%0,%1,%2,%3}, [%4];" \
                 : "=r"(r0), "=r"(r1), "=r"(r2), "=r"(r3) : "r"(a))
#define MMA16816(c, a0, a1, a2, a3, b0, b1)                                  \
    asm volatile("mma.sync.aligned.m16n8k16.row.col.f32.f16.f16.f32 "        \
                 "{%0,%1,%2,%3},{%4,%5,%6,%7},{%8,%9},{%0,%1,%2,%3};"        \
                 : "+f"((c)[0]), "+f"((c)[1]), "+f"((c)[2]), "+f"((c)[3])    \
                 : "r"(a0), "r"(a1), "r"(a2), "r"(a3), "r"(b0), "r"(b1))

// ---------------------------------------------------------------------------
// Fused fp32 -> fp16 convert for x (2048 blk), w_qkv (1536 blk), w_o (512 blk)
// ---------------------------------------------------------------------------
__global__ void __launch_bounds__(256)
convert_all_kernel(const float* __restrict__ x,     __half* __restrict__ xh,
                   const float* __restrict__ wqkv,  __half* __restrict__ wqkvh,
                   const float* __restrict__ wo,    __half* __restrict__ woh)
{
    const float* in;
    __half* out;
    long long blk = blockIdx.x;
    if (blk < 2048)       { in = x;    out = xh; }
    else if (blk < 3584)  { in = wqkv; out = wqkvh; blk -= 2048; }
    else                  { in = wo;   out = woh;   blk -= 3584; }
    long long i = (blk * 256 + threadIdx.x) * 8;
    float4 a = *reinterpret_cast<const float4*>(in + i);
    float4 b = *reinterpret_cast<const float4*>(in + i + 4);
    __half2* o = reinterpret_cast<__half2*>(out + i);
    o[0] = __floats2half2_rn(a.x, a.y);
    o[1] = __floats2half2_rn(a.z, a.w);
    o[2] = __floats2half2_rn(b.x, b.y);
    o[3] = __floats2half2_rn(b.z, b.w);
}

// ---------------------------------------------------------------------------
// fp16 GEMM, raw mma.m16n8k16: C = A @ B^T + bias.
// CTA tile 128x128, 128 threads (4 warps, 2M x 2N, warp tile 64x64 — same
// validated inner loop as R11). 2-stage cp.async, 2 CTAs/SM (72 KB smem,
// <=256 regs) so barriers stall only half the SM's warps.
// ---------------------------------------------------------------------------
constexpr int BKH = 72;
constexpr int A_ST = 128 * BKH;
constexpr int B_ST = 128 * BKH;
constexpr int STG  = A_ST + B_ST;                  // 18,432 halves
constexpr int GEMM_SMEM = 2 * STG * 2;             // 73,728 B

template <bool OUT_HALF>
__global__ void __launch_bounds__(128, 2)
gemm_bias_f16_kernel(const __half* __restrict__ A, const __half* __restrict__ B,
                     const float* __restrict__ bias, void* __restrict__ Cv,
                     int lda, int ldb, int ldc, int K)
{
    extern __shared__ __half gsm[];

    const int tid  = threadIdx.x;
    const int lane = tid & 31;
    const int warp = tid >> 5;
    const int wm   = warp & 1;        // 0..1 -> 64-row slice
    const int wn   = warp >> 1;       // 0..1 -> 64-col slice
    const int m0   = blockIdx.y * 128;
    const int n0   = blockIdx.x * 128;
    const int g    = lane >> 2;
    const int t    = lane & 3;

    const int NT = K / 64;

    auto load_tile = [&](int kt, int s) {
        __half* As = gsm + s * STG;
        __half* Bs = As + A_ST;
        const int k0 = kt * 64;
        #pragma unroll
        for (int i = 0; i < 8; i++) {                   // A: 128 x 64
            int idx = tid + i * 128;
            int r = idx >> 3, c = (idx & 7) * 8;
            CP_ASYNC16(smem_u32(&As[r * BKH + c]),
                       A + (long long)(m0 + r) * lda + k0 + c);
        }
        #pragma unroll
        for (int i = 0; i < 8; i++) {                   // B: 128 x 64
            int idx = tid + i * 128;
            int r = idx >> 3, c = (idx & 7) * 8;
            CP_ASYNC16(smem_u32(&Bs[r * BKH + c]),
                       B + (long long)(n0 + r) * ldb + k0 + c);
        }
    };

    const int a_row = ((lane >> 3) & 1) * 8 + (lane & 7);
    const int a_col = (lane >> 4) * 8;
    const int b_row = ((lane >> 4) & 1) * 8 + (lane & 7);
    const int b_col = ((lane >> 3) & 1) * 8;

    float acc[4][8][4];
    #pragma unroll
    for (int mi = 0; mi < 4; mi++)
        #pragma unroll
        for (int nj = 0; nj < 8; nj++)
            #pragma unroll
            for (int e = 0; e < 4; e++) acc[mi][nj][e] = 0.0f;

    load_tile(0, 0);
    CP_COMMIT();

    for (int kt = 0; kt < NT; kt++) {
        CP_WAIT(0);            // tile kt resident
        __syncthreads();       // prior mma reads of the other buffer done
        if (kt + 1 < NT) load_tile(kt + 1, (kt + 1) & 1);
        CP_COMMIT();

        const __half* Asp = gsm + (kt & 1) * STG;
        const __half* Bsp = Asp + A_ST;

        #pragma unroll
        for (int kc = 0; kc < 4; kc++) {
            unsigned af[4][4], bf[4][4];
            #pragma unroll
            for (int mi = 0; mi < 4; mi++) {
                unsigned a = smem_u32(&Asp[(wm * 64 + mi * 16 + a_row) * BKH + kc * 16 + a_col]);
                LDSM_X4(af[mi][0], af[mi][1], af[mi][2], af[mi][3], a);
            }
            #pragma unroll
            for (int njp = 0; njp < 4; njp++) {
                unsigned a = smem_u32(&Bsp[(wn * 64 + njp * 16 + b_row) * BKH + kc * 16 + b_col]);
                LDSM_X4(bf[njp][0], bf[njp][1], bf[njp][2], bf[njp][3], a);
            }
            #pragma unroll
            for (int mi = 0; mi < 4; mi++)
                #pragma unroll
                for (int njp = 0; njp < 4; njp++) {
                    MMA16816(acc[mi][2 * njp],
                             af[mi][0], af[mi][1], af[mi][2], af[mi][3],
                             bf[njp][0], bf[njp][1]);
                    MMA16816(acc[mi][2 * njp + 1],
                             af[mi][0], af[mi][1], af[mi][2], af[mi][3],
                             bf[njp][2], bf[njp][3]);
                }
        }
    }

    // ---- epilogue: bias + direct store from registers ----
    #pragma unroll
    for (int mi = 0; mi < 4; mi++)
        #pragma unroll
        for (int rp = 0; rp < 2; rp++) {
            int row = m0 + wm * 64 + mi * 16 + g + rp * 8;
            #pragma unroll
            for (int nj = 0; nj < 8; nj++) {
                int col = n0 + wn * 64 + nj * 8 + 2 * t;
                float c0 = acc[mi][nj][2 * rp]     + __ldg(bias + col);
                float c1 = acc[mi][nj][2 * rp + 1] + __ldg(bias + col + 1);
                if (OUT_HALF) {
                    __half* C = reinterpret_cast<__half*>(Cv);
                    *reinterpret_cast<unsigned*>(C + (long long)row * ldc + col) =
                        h2_as_u32(__floats2half2_rn(c0, c1));
                } else {
                    float* C = reinterpret_cast<float*>(Cv);
                    float2 v = make_float2(c0, c1);
                    *reinterpret_cast<float2*>(C + (long long)row * ldc + col) = v;
                }
            }
        }
}

// ---------------------------------------------------------------------------
// Flash attention, FA2-style register pipeline, q-tile 64 (UNCHANGED, passing).
// ---------------------------------------------------------------------------
constexpr int QSP = 72;
constexpr int FA_SMEM_BYTES = 5 * 64 * QSP * 2;    // 46,080 B

__global__ void __launch_bounds__(128)
flash_attn_kernel(const __half* __restrict__ qkv, __half* __restrict__ attn)
{
    extern __shared__ char fsm[];
    __half* Qs  = reinterpret_cast<__half*>(fsm);
    __half* Kb0 = Qs + 64 * QSP;
    __half* Kb1 = Kb0 + 64 * QSP;
    __half* Vb0 = Kb1 + 64 * QSP;
    __half* Vb1 = Vb0 + 64 * QSP;

    const int tid  = threadIdx.x;
    const int lane = tid & 31;
    const int warp = tid >> 5;
    const int wr   = warp * 16;
    const int g    = lane >> 2;
    const int t    = lane & 3;

    const int bh = blockIdx.y;
    const int b  = bh >> 4;
    const int h  = bh & 15;
    const int q0 = blockIdx.x * 64;

    const float QSCALE = 0.125f * 1.44269504f;
    const __half* base = qkv + (long long)b * 2048 * 3072 + h * 192;

    #pragma unroll
    for (int i = 0; i < 4; i++) {
        int idx = tid + i * 128;
        int r = idx >> 3, c = (idx & 7) * 8;
        CP_ASYNC16(smem_u32(&Qs[r * QSP + c]),
                   base + (long long)(q0 + r) * 3072 + c);
    }
    #pragma unroll
    for (int i = 0; i < 4; i++) {
        int idx = tid + i * 128;
        int r = idx >> 3, c = (idx & 7) * 8;
        CP_ASYNC16(smem_u32(&Kb0[r * QSP + c]), base + (long long)r * 3072 + 64 + c);
        CP_ASYNC16(smem_u32(&Vb0[r * QSP + c]), base + (long long)r * 3072 + 128 + c);
    }
    CP_COMMIT();
    #pragma unroll
    for (int i = 0; i < 4; i++) {
        int idx = tid + i * 128;
        int r = idx >> 3, c = (idx & 7) * 8;
        CP_ASYNC16(smem_u32(&Kb1[r * QSP + c]),
                   base + (long long)(64 + r) * 3072 + 64 + c);
        CP_ASYNC16(smem_u32(&Vb1[r * QSP + c]),
                   base + (long long)(64 + r) * 3072 + 128 + c);
    }
    CP_COMMIT();
    CP_WAIT(1);
    __syncthreads();

    unsigned qf[4][4];
    {
        int lrow = ((lane >> 3) & 1) * 8 + (lane & 7);
        int lcol = (lane >> 4) * 8;
        #pragma unroll
        for (int kc = 0; kc < 4; kc++) {
            unsigned a = smem_u32(&Qs[(wr + lrow) * QSP + kc * 16 + lcol]);
            LDSM_X4(qf[kc][0], qf[kc][1], qf[kc][2], qf[kc][3], a);
        }
    }

    float of[8][4];
    #pragma unroll
    for (int v = 0; v < 8; v++)
        #pragma unroll
        for (int e = 0; e < 4; e++) of[v][e] = 0.0f;
    float mreg[2] = {-1e30f, -1e30f};
    float lreg[2] = {0.0f, 0.0f};

    const int kb_row = ((lane >> 4) & 1) * 8 + (lane & 7);
    const int kb_col = ((lane >> 3) & 1) * 8;
    const int vb_row = ((lane >> 3) & 1) * 8 + (lane & 7);
    const int vb_col = ((lane >> 4) & 1) * 8;

    for (int kt = 0; kt < 32; kt++) {
        const int pb = kt & 1;
        const __half* Ksp = pb ? Kb1 : Kb0;
        const __half* Vsp = pb ? Vb1 : Vb0;

        if (kt >= 1 && kt + 1 < 32) {
            __half* Kd = pb ? Kb0 : Kb1;
            __half* Vd = pb ? Vb0 : Vb1;
            #pragma unroll
            for (int i = 0; i < 4; i++) {
                int idx = tid + i * 128;
                int r = idx >> 3, c = (idx & 7) * 8;
                const __half* src = base + (long long)((kt + 1) * 64 + r) * 3072;
                CP_ASYNC16(smem_u32(&Kd[r * QSP + c]), src + 64 + c);
                CP_ASYNC16(smem_u32(&Vd[r * QSP + c]), src + 128 + c);
            }
        }
        CP_COMMIT();

        float sf[8][4];
        #pragma unroll
        for (int n = 0; n < 8; n++)
            #pragma unroll
            for (int e = 0; e < 4; e++) sf[n][e] = 0.0f;

        #pragma unroll
        for (int kc = 0; kc < 4; kc++)
            #pragma unroll
            for (int njp = 0; njp < 4; njp++) {
                unsigned r0, r1, r2, r3;
                unsigned a = smem_u32(&Ksp[(njp * 16 + kb_row) * QSP + kc * 16 + kb_col]);
                LDSM_X4(r0, r1, r2, r3, a);
                MMA16816(sf[2 * njp],     qf[kc][0], qf[kc][1], qf[kc][2], qf[kc][3], r0, r1);
                MMA16816(sf[2 * njp + 1], qf[kc][0], qf[kc][1], qf[kc][2], qf[kc][3], r2, r3);
            }

        unsigned ph[8][2];
        #pragma unroll
        for (int rp = 0; rp < 2; rp++) {
            float mold = mreg[rp];
            float mx = -1e30f;
            #pragma unroll
            for (int n = 0; n < 8; n++)
                mx = fmaxf(mx, fmaxf(sf[n][2 * rp], sf[n][2 * rp + 1]));
            mx = fmaxf(mx, __shfl_xor_sync(0xffffffffu, mx, 1));
            mx = fmaxf(mx, __shfl_xor_sync(0xffffffffu, mx, 2));
            float mnew = fmaxf(mold, mx * QSCALE);
            float s = 0.0f;
            #pragma unroll
            for (int n = 0; n < 8; n++) {
                float p0 = fexp2(__fmaf_rn(sf[n][2 * rp], QSCALE, -mnew));
                float p1 = fexp2(__fmaf_rn(sf[n][2 * rp + 1], QSCALE, -mnew));
                s += p0 + p1;
                ph[n][rp] = h2_as_u32(__floats2half2_rn(p0, p1));
            }
            s += __shfl_xor_sync(0xffffffffu, s, 1);
            s += __shfl_xor_sync(0xffffffffu, s, 2);
            float alpha = fexp2(mold - mnew);
            lreg[rp] = lreg[rp] * alpha + s;
            mreg[rp] = mnew;
            #pragma unroll
            for (int v = 0; v < 8; v++) {
                of[v][2 * rp]     *= alpha;
                of[v][2 * rp + 1] *= alpha;
            }
        }

        #pragma unroll
        for (int kc = 0; kc < 4; kc++)
            #pragma unroll
            for (int vjp = 0; vjp < 4; vjp++) {
                unsigned r0, r1, r2, r3;
                unsigned a = smem_u32(&Vsp[(kc * 16 + vb_row) * QSP + vjp * 16 + vb_col]);
                LDSM_X4_T(r0, r1, r2, r3, a);
                MMA16816(of[2 * vjp],
                         ph[2 * kc][0], ph[2 * kc][1],
                         ph[2 * kc + 1][0], ph[2 * kc + 1][1], r0, r1);
                MMA16816(of[2 * vjp + 1],
                         ph[2 * kc][0], ph[2 * kc][1],
                         ph[2 * kc + 1][0], ph[2 * kc + 1][1], r2, r3);
            }

        CP_WAIT(0);
        __syncthreads();
    }

    #pragma unroll
    for (int rp = 0; rp < 2; rp++) {
        float inv = __frcp_rn(lreg[rp]);
        int row = q0 + wr + g + rp * 8;
        __half* dst = attn + (long long)(b * 2048 + row) * 1024 + h * 64;
        #pragma unroll
        for (int v = 0; v < 8; v++) {
            __half2 hv = __floats2half2_rn(of[v][2 * rp] * inv,
                                           of[v][2 * rp + 1] * inv);
            *reinterpret_cast<unsigned*>(dst + v * 8 + 2 * t) = h2_as_u32(hv);
        }
    }
}

// ---------------------------------------------------------------------------
// Orchestration.
// ---------------------------------------------------------------------------
extern "C" void kernel_launch(void* const* d_in, const int* in_sizes, int n_in,
                              void* d_out, int out_size)
{
    (void)in_sizes; (void)n_in; (void)out_size;
    const float* x     = (const float*)d_in[0];
    const float* w_qkv = (const float*)d_in[1];
    const float* b_qkv = (const float*)d_in[2];
    const float* w_o   = (const float*)d_in[3];
    const float* b_o   = (const float*)d_in[4];
    float* out = (float*)d_out;

    __half *xh, *wqkvh, *woh, *qkvh, *attnh;
    cudaGetSymbolAddress((void**)&xh,    g_xh);
    cudaGetSymbolAddress((void**)&wqkvh, g_wqkvh);
    cudaGetSymbolAddress((void**)&woh,   g_woh);
    cudaGetSymbolAddress((void**)&qkvh,  g_qkvh);
    cudaGetSymbolAddress((void**)&attnh, g_attnh);

    cudaFuncSetAttribute(gemm_bias_f16_kernel<true>,
                         cudaFuncAttributeMaxDynamicSharedMemorySize, GEMM_SMEM);
    cudaFuncSetAttribute(gemm_bias_f16_kernel<false>,
                         cudaFuncAttributeMaxDynamicSharedMemorySize, GEMM_SMEM);
    cudaFuncSetAttribute(flash_attn_kernel,
                         cudaFuncAttributeMaxDynamicSharedMemorySize, FA_SMEM_BYTES);

    // 0) fused fp32->fp16 converts
    convert_all_kernel<<<4096, 256>>>(x, xh, w_qkv, wqkvh, w_o, woh);

    // 1) qkvh = xh @ wqkvh^T + b_qkv   (fp16 out)  grid (3072/128, 4096/128)
    gemm_bias_f16_kernel<true><<<dim3(24, 32), 128, GEMM_SMEM>>>(
        xh, wqkvh, b_qkv, qkvh, 1024, 1024, 3072, 1024);

    // 2) fused attention -> attnh (fp16)  grid (2048/64, B*H)
    flash_attn_kernel<<<dim3(32, 32), 128, FA_SMEM_BYTES>>>(qkvh, attnh);

    // 3) out = attnh @ woh^T + b_o     (fp32 out)  grid (1024/128, 4096/128)
    gemm_bias_f16_kernel<false><<<dim3(8, 32), 128, GEMM_SMEM>>>(
        attnh, woh, b_o, out, 1024, 1024, 1024, 1024);
}

// round 15
// speedup vs baseline: 7.3374x; 1.0004x over previous
#include <cuda_runtime.h>
#include <cuda_fp16.h>

// ---------------------------------------------------------------------------
// B=2, S=2048, D=1024, H=16, hd=64. fp16 datapath, fp32 accumulate.
// ---------------------------------------------------------------------------
__device__ __align__(256) __half g_xh[4096LL * 1024];
__device__ __align__(256) __half g_wqkvh[3072LL * 1024];
__device__ __align__(256) __half g_woh[1024LL * 1024];
__device__ __align__(256) __half g_qkvh[4096LL * 3072];   // per-head [q|k|v]
__device__ __align__(256) __half g_attnh[4096LL * 1024];

__device__ __forceinline__ unsigned h2_as_u32(__half2 h) {
    return *reinterpret_cast<unsigned*>(&h);
}
__device__ __forceinline__ float fexp2(float x) {
    float r;
    asm("ex2.approx.ftz.f32 %0, %1;" : "=f"(r) : "f"(x));
    return r;
}
__device__ __forceinline__ unsigned smem_u32(const void* p) {
    return (unsigned)__cvta_generic_to_shared(p);
}
#define CP_ASYNC16(dst_u32, src_ptr)                                        \
    asm volatile("cp.async.cg.shared.global [%0], [%1], 16;\n" ::           \
                 "r"(dst_u32), "l"(src_ptr))
#define CP_COMMIT() asm volatile("cp.async.commit_group;\n" ::: "memory")
#define CP_WAIT(n)  asm volatile("cp.async.wait_group %0;\n" :: "n"(n) : "memory")

#define LDSM_X4(r0, r1, r2, r3, a)                                           \
    asm volatile("ldmatrix.sync.aligned.m8n8.x4.shared.b16 {%0,%1,%2,%3}, [%4];" \
                 : "=r"(r0), "=r"(r1), "=r"(r2), "=r"(r3) : "r"(a))
#define LDSM_X2(r0, r1, a)                                                   \
    asm volatile("ldmatrix.sync.aligned.m8n8.x2.shared.b16 {%0,%1}, [%2];"   \
                 : "=r"(r0), "=r"(r1) : "r"(a))
#define LDSM_X4_T(r0, r1, r2, r3, a)                                         \
    asm volatile("ldmatrix.sync.aligned.m8n8.x4.trans.shared.b16 {%0,%1,%2,%3}, [%4];" \
                 : "=r"(r0), "=r"(r1), "=r"(r2), "=r"(r3) : "r"(a))
#define MMA16816(c, a0, a1, a2, a3, b0, b1)                                  \
    asm volatile("mma.sync.aligned.m16n8k16.row.col.f32.f16.f16.f32 "        \
                 "{%0,%1,%2,%3},{%4,%5,%6,%7},{%8,%9},{%0,%1,%2,%3};"        \
                 : "+f"((c)[0]), "+f"((c)[1]), "+f"((c)[2]), "+f"((c)[3])    \
                 : "r"(a0), "r"(a1), "r"(a2), "r"(a3), "r"(b0), "r"(b1))

// ---------------------------------------------------------------------------
// Fused fp32 -> fp16 convert for x (2048 blk), w_qkv (1536 blk), w_o (512 blk)
// ---------------------------------------------------------------------------
__global__ void __launch_bounds__(256)
convert_all_kernel(const float* __restrict__ x,     __half* __restrict__ xh,
                   const float* __restrict__ wqkv,  __half* __restrict__ wqkvh,
                   const float* __restrict__ wo,    __half* __restrict__ woh)
{
    const float* in;
    __half* out;
    long long blk = blockIdx.x;
    if (blk < 2048)       { in = x;    out = xh; }
    else if (blk < 3584)  { in = wqkv; out = wqkvh; blk -= 2048; }
    else                  { in = wo;   out = woh;   blk -= 3584; }
    long long i = (blk * 256 + threadIdx.x) * 8;
    float4 a = *reinterpret_cast<const float4*>(in + i);
    float4 b = *reinterpret_cast<const float4*>(in + i + 4);
    __half2* o = reinterpret_cast<__half2*>(out + i);
    o[0] = __floats2half2_rn(a.x, a.y);
    o[1] = __floats2half2_rn(a.z, a.w);
    o[2] = __floats2half2_rn(b.x, b.y);
    o[3] = __floats2half2_rn(b.z, b.w);
}

// ---------------------------------------------------------------------------
// fp16 GEMM, raw mma.m16n8k16: C = A @ B^T + bias.
// CTA tile 128x128, 256 threads (8 warps: 4M x 2N, warp tile 32x64).
// acc = 64 regs -> ~120 regs/thread -> 2 CTAs/SM = 16 warps/SM (4/SMSP).
// 2-stage cp.async. Same validated LDSM/MMA stream.
// ---------------------------------------------------------------------------
constexpr int BKH = 72;
constexpr int A_ST = 128 * BKH;
constexpr int B_ST = 128 * BKH;
constexpr int STG  = A_ST + B_ST;                  // 18,432 halves
constexpr int GEMM_SMEM = 2 * STG * 2;             // 73,728 B

template <bool OUT_HALF>
__global__ void __launch_bounds__(256, 2)
gemm_bias_f16_kernel(const __half* __restrict__ A, const __half* __restrict__ B,
                     const float* __restrict__ bias, void* __restrict__ Cv,
                     int lda, int ldb, int ldc, int K)
{
    extern __shared__ __half gsm[];

    const int tid  = threadIdx.x;
    const int lane = tid & 31;
    const int warp = tid >> 5;
    const int wm   = warp & 3;        // 0..3 -> 32-row slice
    const int wn   = warp >> 2;       // 0..1 -> 64-col slice
    const int m0   = blockIdx.y * 128;
    const int n0   = blockIdx.x * 128;
    const int g    = lane >> 2;
    const int t    = lane & 3;

    const int NT = K / 64;

    auto load_tile = [&](int kt, int s) {
        __half* As = gsm + s * STG;
        __half* Bs = As + A_ST;
        const int k0 = kt * 64;
        #pragma unroll
        for (int i = 0; i < 4; i++) {                   // A: 128 x 64
            int idx = tid + i * 256;
            int r = idx >> 3, c = (idx & 7) * 8;
            CP_ASYNC16(smem_u32(&As[r * BKH + c]),
                       A + (long long)(m0 + r) * lda + k0 + c);
        }
        #pragma unroll
        for (int i = 0; i < 4; i++) {                   // B: 128 x 64
            int idx = tid + i * 256;
            int r = idx >> 3, c = (idx & 7) * 8;
            CP_ASYNC16(smem_u32(&Bs[r * BKH + c]),
                       B + (long long)(n0 + r) * ldb + k0 + c);
        }
    };

    const int a_row = ((lane >> 3) & 1) * 8 + (lane & 7);
    const int a_col = (lane >> 4) * 8;
    const int b_row = ((lane >> 4) & 1) * 8 + (lane & 7);
    const int b_col = ((lane >> 3) & 1) * 8;

    float acc[2][8][4];
    #pragma unroll
    for (int mi = 0; mi < 2; mi++)
        #pragma unroll
        for (int nj = 0; nj < 8; nj++)
            #pragma unroll
            for (int e = 0; e < 4; e++) acc[mi][nj][e] = 0.0f;

    load_tile(0, 0);
    CP_COMMIT();

    for (int kt = 0; kt < NT; kt++) {
        CP_WAIT(0);
        __syncthreads();
        if (kt + 1 < NT) load_tile(kt + 1, (kt + 1) & 1);
        CP_COMMIT();

        const __half* Asp = gsm + (kt & 1) * STG;
        const __half* Bsp = Asp + A_ST;

        #pragma unroll
        for (int kc = 0; kc < 4; kc++) {
            unsigned af[2][4], bf[4][4];
            #pragma unroll
            for (int mi = 0; mi < 2; mi++) {
                unsigned a = smem_u32(&Asp[(wm * 32 + mi * 16 + a_row) * BKH + kc * 16 + a_col]);
                LDSM_X4(af[mi][0], af[mi][1], af[mi][2], af[mi][3], a);
            }
            #pragma unroll
            for (int njp = 0; njp < 4; njp++) {
                unsigned a = smem_u32(&Bsp[(wn * 64 + njp * 16 + b_row) * BKH + kc * 16 + b_col]);
                LDSM_X4(bf[njp][0], bf[njp][1], bf[njp][2], bf[njp][3], a);
            }
            #pragma unroll
            for (int mi = 0; mi < 2; mi++)
                #pragma unroll
                for (int njp = 0; njp < 4; njp++) {
                    MMA16816(acc[mi][2 * njp],
                             af[mi][0], af[mi][1], af[mi][2], af[mi][3],
                             bf[njp][0], bf[njp][1]);
                    MMA16816(acc[mi][2 * njp + 1],
                             af[mi][0], af[mi][1], af[mi][2], af[mi][3],
                             bf[njp][2], bf[njp][3]);
                }
        }
    }

    // ---- epilogue: bias + direct store from registers ----
    #pragma unroll
    for (int mi = 0; mi < 2; mi++)
        #pragma unroll
        for (int rp = 0; rp < 2; rp++) {
            int row = m0 + wm * 32 + mi * 16 + g + rp * 8;
            #pragma unroll
            for (int nj = 0; nj < 8; nj++) {
                int col = n0 + wn * 64 + nj * 8 + 2 * t;
                float c0 = acc[mi][nj][2 * rp]     + __ldg(bias + col);
                float c1 = acc[mi][nj][2 * rp + 1] + __ldg(bias + col + 1);
                if (OUT_HALF) {
                    __half* C = reinterpret_cast<__half*>(Cv);
                    *reinterpret_cast<unsigned*>(C + (long long)row * ldc + col) =
                        h2_as_u32(__floats2half2_rn(c0, c1));
                } else {
                    float* C = reinterpret_cast<float*>(Cv);
                    float2 v = make_float2(c0, c1);
                    *reinterpret_cast<float2*>(C + (long long)row * ldc + col) = v;
                }
            }
        }
}

// ---------------------------------------------------------------------------
// Flash attention, FA2-style register pipeline, q-tile 64 (UNCHANGED, passing).
// ---------------------------------------------------------------------------
constexpr int QSP = 72;
constexpr int FA_SMEM_BYTES = 5 * 64 * QSP * 2;    // 46,080 B

__global__ void __launch_bounds__(128)
flash_attn_kernel(const __half* __restrict__ qkv, __half* __restrict__ attn)
{
    extern __shared__ char fsm[];
    __half* Qs  = reinterpret_cast<__half*>(fsm);
    __half* Kb0 = Qs + 64 * QSP;
    __half* Kb1 = Kb0 + 64 * QSP;
    __half* Vb0 = Kb1 + 64 * QSP;
    __half* Vb1 = Vb0 + 64 * QSP;

    const int tid  = threadIdx.x;
    const int lane = tid & 31;
    const int warp = tid >> 5;
    const int wr   = warp * 16;
    const int g    = lane >> 2;
    const int t    = lane & 3;

    const int bh = blockIdx.y;
    const int b  = bh >> 4;
    const int h  = bh & 15;
    const int q0 = blockIdx.x * 64;

    const float QSCALE = 0.125f * 1.44269504f;
    const __half* base = qkv + (long long)b * 2048 * 3072 + h * 192;

    #pragma unroll
    for (int i = 0; i < 4; i++) {
        int idx = tid + i * 128;
        int r = idx >> 3, c = (idx & 7) * 8;
        CP_ASYNC16(smem_u32(&Qs[r * QSP + c]),
                   base + (long long)(q0 + r) * 3072 + c);
    }
    #pragma unroll
    for (int i = 0; i < 4; i++) {
        int idx = tid + i * 128;
        int r = idx >> 3, c = (idx & 7) * 8;
        CP_ASYNC16(smem_u32(&Kb0[r * QSP + c]), base + (long long)r * 3072 + 64 + c);
        CP_ASYNC16(smem_u32(&Vb0[r * QSP + c]), base + (long long)r * 3072 + 128 + c);
    }
    CP_COMMIT();
    #pragma unroll
    for (int i = 0; i < 4; i++) {
        int idx = tid + i * 128;
        int r = idx >> 3, c = (idx & 7) * 8;
        CP_ASYNC16(smem_u32(&Kb1[r * QSP + c]),
                   base + (long long)(64 + r) * 3072 + 64 + c);
        CP_ASYNC16(smem_u32(&Vb1[r * QSP + c]),
                   base + (long long)(64 + r) * 3072 + 128 + c);
    }
    CP_COMMIT();
    CP_WAIT(1);
    __syncthreads();

    unsigned qf[4][4];
    {
        int lrow = ((lane >> 3) & 1) * 8 + (lane & 7);
        int lcol = (lane >> 4) * 8;
        #pragma unroll
        for (int kc = 0; kc < 4; kc++) {
            unsigned a = smem_u32(&Qs[(wr + lrow) * QSP + kc * 16 + lcol]);
            LDSM_X4(qf[kc][0], qf[kc][1], qf[kc][2], qf[kc][3], a);
        }
    }

    float of[8][4];
    #pragma unroll
    for (int v = 0; v < 8; v++)
        #pragma unroll
        for (int e = 0; e < 4; e++) of[v][e] = 0.0f;
    float mreg[2] = {-1e30f, -1e30f};
    float lreg[2] = {0.0f, 0.0f};

    const int kb_row = ((lane >> 4) & 1) * 8 + (lane & 7);
    const int kb_col = ((lane >> 3) & 1) * 8;
    const int vb_row = ((lane >> 3) & 1) * 8 + (lane & 7);
    const int vb_col = ((lane >> 4) & 1) * 8;

    for (int kt = 0; kt < 32; kt++) {
        const int pb = kt & 1;
        const __half* Ksp = pb ? Kb1 : Kb0;
        const __half* Vsp = pb ? Vb1 : Vb0;

        if (kt >= 1 && kt + 1 < 32) {
            __half* Kd = pb ? Kb0 : Kb1;
            __half* Vd = pb ? Vb0 : Vb1;
            #pragma unroll
            for (int i = 0; i < 4; i++) {
                int idx = tid + i * 128;
                int r = idx >> 3, c = (idx & 7) * 8;
                const __half* src = base + (long long)((kt + 1) * 64 + r) * 3072;
                CP_ASYNC16(smem_u32(&Kd[r * QSP + c]), src + 64 + c);
                CP_ASYNC16(smem_u32(&Vd[r * QSP + c]), src + 128 + c);
            }
        }
        CP_COMMIT();

        float sf[8][4];
        #pragma unroll
        for (int n = 0; n < 8; n++)
            #pragma unroll
            for (int e = 0; e < 4; e++) sf[n][e] = 0.0f;

        #pragma unroll
        for (int kc = 0; kc < 4; kc++)
            #pragma unroll
            for (int njp = 0; njp < 4; njp++) {
                unsigned r0, r1, r2, r3;
                unsigned a = smem_u32(&Ksp[(njp * 16 + kb_row) * QSP + kc * 16 + kb_col]);
                LDSM_X4(r0, r1, r2, r3, a);
                MMA16816(sf[2 * njp],     qf[kc][0], qf[kc][1], qf[kc][2], qf[kc][3], r0, r1);
                MMA16816(sf[2 * njp + 1], qf[kc][0], qf[kc][1], qf[kc][2], qf[kc][3], r2, r3);
            }

        unsigned ph[8][2];
        #pragma unroll
        for (int rp = 0; rp < 2; rp++) {
            float mold = mreg[rp];
            float mx = -1e30f;
            #pragma unroll
            for (int n = 0; n < 8; n++)
                mx = fmaxf(mx, fmaxf(sf[n][2 * rp], sf[n][2 * rp + 1]));
            mx = fmaxf(mx, __shfl_xor_sync(0xffffffffu, mx, 1));
            mx = fmaxf(mx, __shfl_xor_sync(0xffffffffu, mx, 2));
            float mnew = fmaxf(mold, mx * QSCALE);
            float s = 0.0f;
            #pragma unroll
            for (int n = 0; n < 8; n++) {
                float p0 = fexp2(__fmaf_rn(sf[n][2 * rp], QSCALE, -mnew));
                float p1 = fexp2(__fmaf_rn(sf[n][2 * rp + 1], QSCALE, -mnew));
                s += p0 + p1;
                ph[n][rp] = h2_as_u32(__floats2half2_rn(p0, p1));
            }
            s += __shfl_xor_sync(0xffffffffu, s, 1);
            s += __shfl_xor_sync(0xffffffffu, s, 2);
            float alpha = fexp2(mold - mnew);
            lreg[rp] = lreg[rp] * alpha + s;
            mreg[rp] = mnew;
            #pragma unroll
            for (int v = 0; v < 8; v++) {
                of[v][2 * rp]     *= alpha;
                of[v][2 * rp + 1] *= alpha;
            }
        }

        #pragma unroll
        for (int kc = 0; kc < 4; kc++)
            #pragma unroll
            for (int vjp = 0; vjp < 4; vjp++) {
                unsigned r0, r1, r2, r3;
                unsigned a = smem_u32(&Vsp[(kc * 16 + vb_row) * QSP + vjp * 16 + vb_col]);
                LDSM_X4_T(r0, r1, r2, r3, a);
                MMA16816(of[2 * vjp],
                         ph[2 * kc][0], ph[2 * kc][1],
                         ph[2 * kc + 1][0], ph[2 * kc + 1][1], r0, r1);
                MMA16816(of[2 * vjp + 1],
                         ph[2 * kc][0], ph[2 * kc][1],
                         ph[2 * kc + 1][0], ph[2 * kc + 1][1], r2, r3);
            }

        CP_WAIT(0);
        __syncthreads();
    }

    #pragma unroll
    for (int rp = 0; rp < 2; rp++) {
        float inv = __frcp_rn(lreg[rp]);
        int row = q0 + wr + g + rp * 8;
        __half* dst = attn + (long long)(b * 2048 + row) * 1024 + h * 64;
        #pragma unroll
        for (int v = 0; v < 8; v++) {
            __half2 hv = __floats2half2_rn(of[v][2 * rp] * inv,
                                           of[v][2 * rp + 1] * inv);
            *reinterpret_cast<unsigned*>(dst + v * 8 + 2 * t) = h2_as_u32(hv);
        }
    }
}

// ---------------------------------------------------------------------------
// Orchestration.
// ---------------------------------------------------------------------------
extern "C" void kernel_launch(void* const* d_in, const int* in_sizes, int n_in,
                              void* d_out, int out_size)
{
    (void)in_sizes; (void)n_in; (void)out_size;
    const float* x     = (const float*)d_in[0];
    const float* w_qkv = (const float*)d_in[1];
    const float* b_qkv = (const float*)d_in[2];
    const float* w_o   = (const float*)d_in[3];
    const float* b_o   = (const float*)d_in[4];
    float* out = (float*)d_out;

    __half *xh, *wqkvh, *woh, *qkvh, *attnh;
    cudaGetSymbolAddress((void**)&xh,    g_xh);
    cudaGetSymbolAddress((void**)&wqkvh, g_wqkvh);
    cudaGetSymbolAddress((void**)&woh,   g_woh);
    cudaGetSymbolAddress((void**)&qkvh,  g_qkvh);
    cudaGetSymbolAddress((void**)&attnh, g_attnh);

    cudaFuncSetAttribute(gemm_bias_f16_kernel<true>,
                         cudaFuncAttributeMaxDynamicSharedMemorySize, GEMM_SMEM);
    cudaFuncSetAttribute(gemm_bias_f16_kernel<false>,
                         cudaFuncAttributeMaxDynamicSharedMemorySize, GEMM_SMEM);
    cudaFuncSetAttribute(flash_attn_kernel,
                         cudaFuncAttributeMaxDynamicSharedMemorySize, FA_SMEM_BYTES);

    // 0) fused fp32->fp16 converts
    convert_all_kernel<<<4096, 256>>>(x, xh, w_qkv, wqkvh, w_o, woh);

    // 1) qkvh = xh @ wqkvh^T + b_qkv   (fp16 out)  grid (3072/128, 4096/128)
    gemm_bias_f16_kernel<true><<<dim3(24, 32), 256, GEMM_SMEM>>>(
        xh, wqkvh, b_qkv, qkvh, 1024, 1024, 3072, 1024);

    // 2) fused attention -> attnh (fp16)  grid (2048/64, B*H)
    flash_attn_kernel<<<dim3(32, 32), 128, FA_SMEM_BYTES>>>(qkvh, attnh);

    // 3) out = attnh @ woh^T + b_o     (fp32 out)  grid (1024/128, 4096/128)
    gemm_bias_f16_kernel<false><<<dim3(8, 32), 256, GEMM_SMEM>>>(
        attnh, woh, b_o, out, 1024, 1024, 1024, 1024);
}

// round 17
// speedup vs baseline: 7.5159x; 1.0243x over previous
#include <cuda_runtime.h>
#include <cuda_fp16.h>

// ---------------------------------------------------------------------------
// B=2, S=2048, D=1024, H=16, hd=64. fp16 datapath, fp32 accumulate.
// ---------------------------------------------------------------------------
__device__ __align__(256) __half g_xh[4096LL * 1024];
__device__ __align__(256) __half g_wqkvh[3072LL * 1024];
__device__ __align__(256) __half g_woh[1024LL * 1024];
__device__ __align__(256) __half g_qkvh[4096LL * 3072];   // per-head [q|k|v]
__device__ __align__(256) __half g_attnh[4096LL * 1024];

__device__ __forceinline__ unsigned h2_as_u32(__half2 h) {
    return *reinterpret_cast<unsigned*>(&h);
}
__device__ __forceinline__ float fexp2(float x) {
    float r;
    asm("ex2.approx.ftz.f32 %0, %1;" : "=f"(r) : "f"(x));
    return r;
}
__device__ __forceinline__ unsigned smem_u32(const void* p) {
    return (unsigned)__cvta_generic_to_shared(p);
}
#define CP_ASYNC16(dst_u32, src_ptr)                                        \
    asm volatile("cp.async.cg.shared.global [%0], [%1], 16;\n" ::           \
                 "r"(dst_u32), "l"(src_ptr))
#define CP_COMMIT() asm volatile("cp.async.commit_group;\n" ::: "memory")
#define CP_WAIT(n)  asm volatile("cp.async.wait_group %0;\n" :: "n"(n) : "memory")

#define LDSM_X4(r0, r1, r2, r3, a)                                           \
    asm volatile("ldmatrix.sync.aligned.m8n8.x4.shared.b16 {%0,%1,%2,%3}, [%4];" \
                 : "=r"(r0), "=r"(r1), "=r"(r2), "=r"(r3) : "r"(a))
#define LDSM_X4_T(r0, r1, r2, r3, a)                                         \
    asm volatile("ldmatrix.sync.aligned.m8n8.x4.trans.shared.b16 {%0,%1,%2,%3}, [%4];" \
                 : "=r"(r0), "=r"(r1), "=r"(r2), "=r"(r3) : "r"(a))
#define MMA16816(c, a0, a1, a2, a3, b0, b1)                                  \
    asm volatile("mma.sync.aligned.m16n8k16.row.col.f32.f16.f16.f32 "        \
                 "{%0,%1,%2,%3},{%4,%5,%6,%7},{%8,%9},{%0,%1,%2,%3};"        \
                 : "+f"((c)[0]), "+f"((c)[1]), "+f"((c)[2]), "+f"((c)[3])    \
                 : "r"(a0), "r"(a1), "r"(a2), "r"(a3), "r"(b0), "r"(b1))

// ---------------------------------------------------------------------------
// Fused fp32 -> fp16 convert for x (2048 blk), w_qkv (1536 blk), w_o (512 blk)
// ---------------------------------------------------------------------------
__global__ void __launch_bounds__(256)
convert_all_kernel(const float* __restrict__ x,     __half* __restrict__ xh,
                   const float* __restrict__ wqkv,  __half* __restrict__ wqkvh,
                   const float* __restrict__ wo,    __half* __restrict__ woh)
{
    const float* in;
    __half* out;
    long long blk = blockIdx.x;
    if (blk < 2048)       { in = x;    out = xh; }
    else if (blk < 3584)  { in = wqkv; out = wqkvh; blk -= 2048; }
    else                  { in = wo;   out = woh;   blk -= 3584; }
    long long i = (blk * 256 + threadIdx.x) * 8;
    float4 a = *reinterpret_cast<const float4*>(in + i);
    float4 b = *reinterpret_cast<const float4*>(in + i + 4);
    __half2* o = reinterpret_cast<__half2*>(out + i);
    o[0] = __floats2half2_rn(a.x, a.y);
    o[1] = __floats2half2_rn(a.z, a.w);
    o[2] = __floats2half2_rn(b.x, b.y);
    o[3] = __floats2half2_rn(b.z, b.w);
}

// ---------------------------------------------------------------------------
// fp16 GEMM, raw mma.m16n8k16: C = A @ B^T + bias.
// CTA tile 128x64, 128 threads (4 warps, warp tile 32x64 = 4M x 1N).
// smem 55.3 KB, ~110 regs -> 4 CTAs/SM = 16 warps/SM in 4 INDEPENDENT CTAs:
// a __syncthreads idles only 25% of the SM's warps (flash's regime).
// 2-stage cp.async, same validated LDSM/MMA stream.
// ---------------------------------------------------------------------------
constexpr int BKH = 72;
constexpr int A_ST = 128 * BKH;                    // A: 128 rows x 64 k
constexpr int B_ST = 64 * BKH;                     // B: 64 rows x 64 k
constexpr int STG  = A_ST + B_ST;                  // 13,824 halves
constexpr int GEMM_SMEM = 2 * STG * 2;             // 55,296 B

template <bool OUT_HALF>
__global__ void __launch_bounds__(128, 4)
gemm_bias_f16_kernel(const __half* __restrict__ A, const __half* __restrict__ B,
                     const float* __restrict__ bias, void* __restrict__ Cv,
                     int lda, int ldb, int ldc, int K)
{
    extern __shared__ __half gsm[];

    const int tid  = threadIdx.x;
    const int lane = tid & 31;
    const int warp = tid >> 5;        // 0..3 -> 32-row slice
    const int m0   = blockIdx.y * 128;
    const int n0   = blockIdx.x * 64;
    const int g    = lane >> 2;
    const int t    = lane & 3;

    const int NT = K / 64;

    auto load_tile = [&](int kt, int s) {
        __half* As = gsm + s * STG;
        __half* Bs = As + A_ST;
        const int k0 = kt * 64;
        #pragma unroll
        for (int i = 0; i < 8; i++) {                   // A: 128 x 64
            int idx = tid + i * 128;
            int r = idx >> 3, c = (idx & 7) * 8;
            CP_ASYNC16(smem_u32(&As[r * BKH + c]),
                       A + (long long)(m0 + r) * lda + k0 + c);
        }
        #pragma unroll
        for (int i = 0; i < 4; i++) {                   // B: 64 x 64
            int idx = tid + i * 128;
            int r = idx >> 3, c = (idx & 7) * 8;
            CP_ASYNC16(smem_u32(&Bs[r * BKH + c]),
                       B + (long long)(n0 + r) * ldb + k0 + c);
        }
    };

    const int a_row = ((lane >> 3) & 1) * 8 + (lane & 7);
    const int a_col = (lane >> 4) * 8;
    const int b_row = ((lane >> 4) & 1) * 8 + (lane & 7);
    const int b_col = ((lane >> 3) & 1) * 8;

    float acc[2][8][4];
    #pragma unroll
    for (int mi = 0; mi < 2; mi++)
        #pragma unroll
        for (int nj = 0; nj < 8; nj++)
            #pragma unroll
            for (int e = 0; e < 4; e++) acc[mi][nj][e] = 0.0f;

    load_tile(0, 0);
    CP_COMMIT();

    for (int kt = 0; kt < NT; kt++) {
        CP_WAIT(0);
        __syncthreads();
        if (kt + 1 < NT) load_tile(kt + 1, (kt + 1) & 1);
        CP_COMMIT();

        const __half* Asp = gsm + (kt & 1) * STG;
        const __half* Bsp = Asp + A_ST;

        #pragma unroll
        for (int kc = 0; kc < 4; kc++) {
            unsigned af[2][4], bf[4][4];
            #pragma unroll
            for (int mi = 0; mi < 2; mi++) {
                unsigned a = smem_u32(&Asp[(warp * 32 + mi * 16 + a_row) * BKH + kc * 16 + a_col]);
                LDSM_X4(af[mi][0], af[mi][1], af[mi][2], af[mi][3], a);
            }
            #pragma unroll
            for (int njp = 0; njp < 4; njp++) {
                unsigned a = smem_u32(&Bsp[(njp * 16 + b_row) * BKH + kc * 16 + b_col]);
                LDSM_X4(bf[njp][0], bf[njp][1], bf[njp][2], bf[njp][3], a);
            }
            #pragma unroll
            for (int mi = 0; mi < 2; mi++)
                #pragma unroll
                for (int njp = 0; njp < 4; njp++) {
                    MMA16816(acc[mi][2 * njp],
                             af[mi][0], af[mi][1], af[mi][2], af[mi][3],
                             bf[njp][0], bf[njp][1]);
                    MMA16816(acc[mi][2 * njp + 1],
                             af[mi][0], af[mi][1], af[mi][2], af[mi][3],
                             bf[njp][2], bf[njp][3]);
                }
        }
    }

    // ---- epilogue: bias + direct store from registers ----
    #pragma unroll
    for (int mi = 0; mi < 2; mi++)
        #pragma unroll
        for (int rp = 0; rp < 2; rp++) {
            int row = m0 + warp * 32 + mi * 16 + g + rp * 8;
            #pragma unroll
            for (int nj = 0; nj < 8; nj++) {
                int col = n0 + nj * 8 + 2 * t;
                float c0 = acc[mi][nj][2 * rp]     + __ldg(bias + col);
                float c1 = acc[mi][nj][2 * rp + 1] + __ldg(bias + col + 1);
                if (OUT_HALF) {
                    __half* C = reinterpret_cast<__half*>(Cv);
                    *reinterpret_cast<unsigned*>(C + (long long)row * ldc + col) =
                        h2_as_u32(__floats2half2_rn(c0, c1));
                } else {
                    float* C = reinterpret_cast<float*>(Cv);
                    float2 v = make_float2(c0, c1);
                    *reinterpret_cast<float2*>(C + (long long)row * ldc + col) = v;
                }
            }
        }
}

// ---------------------------------------------------------------------------
// Flash attention, FA2-style register pipeline, q-tile 64 (UNCHANGED, passing).
// ---------------------------------------------------------------------------
constexpr int QSP = 72;
constexpr int FA_SMEM_BYTES = 5 * 64 * QSP * 2;    // 46,080 B

__global__ void __launch_bounds__(128)
flash_attn_kernel(const __half* __restrict__ qkv, __half* __restrict__ attn)
{
    extern __shared__ char fsm[];
    __half* Qs  = reinterpret_cast<__half*>(fsm);
    __half* Kb0 = Qs + 64 * QSP;
    __half* Kb1 = Kb0 + 64 * QSP;
    __half* Vb0 = Kb1 + 64 * QSP;
    __half* Vb1 = Vb0 + 64 * QSP;

    const int tid  = threadIdx.x;
    const int lane = tid & 31;
    const int warp = tid >> 5;
    const int wr   = warp * 16;
    const int g    = lane >> 2;
    const int t    = lane & 3;

    const int bh = blockIdx.y;
    const int b  = bh >> 4;
    const int h  = bh & 15;
    const int q0 = blockIdx.x * 64;

    const float QSCALE = 0.125f * 1.44269504f;
    const __half* base = qkv + (long long)b * 2048 * 3072 + h * 192;

    #pragma unroll
    for (int i = 0; i < 4; i++) {
        int idx = tid + i * 128;
        int r = idx >> 3, c = (idx & 7) * 8;
        CP_ASYNC16(smem_u32(&Qs[r * QSP + c]),
                   base + (long long)(q0 + r) * 3072 + c);
    }
    #pragma unroll
    for (int i = 0; i < 4; i++) {
        int idx = tid + i * 128;
        int r = idx >> 3, c = (idx & 7) * 8;
        CP_ASYNC16(smem_u32(&Kb0[r * QSP + c]), base + (long long)r * 3072 + 64 + c);
        CP_ASYNC16(smem_u32(&Vb0[r * QSP + c]), base + (long long)r * 3072 + 128 + c);
    }
    CP_COMMIT();
    #pragma unroll
    for (int i = 0; i < 4; i++) {
        int idx = tid + i * 128;
        int r = idx >> 3, c = (idx & 7) * 8;
        CP_ASYNC16(smem_u32(&Kb1[r * QSP + c]),
                   base + (long long)(64 + r) * 3072 + 64 + c);
        CP_ASYNC16(smem_u32(&Vb1[r * QSP + c]),
                   base + (long long)(64 + r) * 3072 + 128 + c);
    }
    CP_COMMIT();
    CP_WAIT(1);
    __syncthreads();

    unsigned qf[4][4];
    {
        int lrow = ((lane >> 3) & 1) * 8 + (lane & 7);
        int lcol = (lane >> 4) * 8;
        #pragma unroll
        for (int kc = 0; kc < 4; kc++) {
            unsigned a = smem_u32(&Qs[(wr + lrow) * QSP + kc * 16 + lcol]);
            LDSM_X4(qf[kc][0], qf[kc][1], qf[kc][2], qf[kc][3], a);
        }
    }

    float of[8][4];
    #pragma unroll
    for (int v = 0; v < 8; v++)
        #pragma unroll
        for (int e = 0; e < 4; e++) of[v][e] = 0.0f;
    float mreg[2] = {-1e30f, -1e30f};
    float lreg[2] = {0.0f, 0.0f};

    const int kb_row = ((lane >> 4) & 1) * 8 + (lane & 7);
    const int kb_col = ((lane >> 3) & 1) * 8;
    const int vb_row = ((lane >> 3) & 1) * 8 + (lane & 7);
    const int vb_col = ((lane >> 4) & 1) * 8;

    for (int kt = 0; kt < 32; kt++) {
        const int pb = kt & 1;
        const __half* Ksp = pb ? Kb1 : Kb0;
        const __half* Vsp = pb ? Vb1 : Vb0;

        if (kt >= 1 && kt + 1 < 32) {
            __half* Kd = pb ? Kb0 : Kb1;
            __half* Vd = pb ? Vb0 : Vb1;
            #pragma unroll
            for (int i = 0; i < 4; i++) {
                int idx = tid + i * 128;
                int r = idx >> 3, c = (idx & 7) * 8;
                const __half* src = base + (long long)((kt + 1) * 64 + r) * 3072;
                CP_ASYNC16(smem_u32(&Kd[r * QSP + c]), src + 64 + c);
                CP_ASYNC16(smem_u32(&Vd[r * QSP + c]), src + 128 + c);
            }
        }
        CP_COMMIT();

        float sf[8][4];
        #pragma unroll
        for (int n = 0; n < 8; n++)
            #pragma unroll
            for (int e = 0; e < 4; e++) sf[n][e] = 0.0f;

        #pragma unroll
        for (int kc = 0; kc < 4; kc++)
            #pragma unroll
            for (int njp = 0; njp < 4; njp++) {
                unsigned r0, r1, r2, r3;
                unsigned a = smem_u32(&Ksp[(njp * 16 + kb_row) * QSP + kc * 16 + kb_col]);
                LDSM_X4(r0, r1, r2, r3, a);
                MMA16816(sf[2 * njp],     qf[kc][0], qf[kc][1], qf[kc][2], qf[kc][3], r0, r1);
                MMA16816(sf[2 * njp + 1], qf[kc][0], qf[kc][1], qf[kc][2], qf[kc][3], r2, r3);
            }

        unsigned ph[8][2];
        #pragma unroll
        for (int rp = 0; rp < 2; rp++) {
            float mold = mreg[rp];
            float mx = -1e30f;
            #pragma unroll
            for (int n = 0; n < 8; n++)
                mx = fmaxf(mx, fmaxf(sf[n][2 * rp], sf[n][2 * rp + 1]));
            mx = fmaxf(mx, __shfl_xor_sync(0xffffffffu, mx, 1));
            mx = fmaxf(mx, __shfl_xor_sync(0xffffffffu, mx, 2));
            float mnew = fmaxf(mold, mx * QSCALE);
            float s = 0.0f;
            #pragma unroll
            for (int n = 0; n < 8; n++) {
                float p0 = fexp2(__fmaf_rn(sf[n][2 * rp], QSCALE, -mnew));
                float p1 = fexp2(__fmaf_rn(sf[n][2 * rp + 1], QSCALE, -mnew));
                s += p0 + p1;
                ph[n][rp] = h2_as_u32(__floats2half2_rn(p0, p1));
            }
            s += __shfl_xor_sync(0xffffffffu, s, 1);
            s += __shfl_xor_sync(0xffffffffu, s, 2);
            float alpha = fexp2(mold - mnew);
            lreg[rp] = lreg[rp] * alpha + s;
            mreg[rp] = mnew;
            #pragma unroll
            for (int v = 0; v < 8; v++) {
                of[v][2 * rp]     *= alpha;
                of[v][2 * rp + 1] *= alpha;
            }
        }

        #pragma unroll
        for (int kc = 0; kc < 4; kc++)
            #pragma unroll
            for (int vjp = 0; vjp < 4; vjp++) {
                unsigned r0, r1, r2, r3;
                unsigned a = smem_u32(&Vsp[(kc * 16 + vb_row) * QSP + vjp * 16 + vb_col]);
                LDSM_X4_T(r0, r1, r2, r3, a);
                MMA16816(of[2 * vjp],
                         ph[2 * kc][0], ph[2 * kc][1],
                         ph[2 * kc + 1][0], ph[2 * kc + 1][1], r0, r1);
                MMA16816(of[2 * vjp + 1],
                         ph[2 * kc][0], ph[2 * kc][1],
                         ph[2 * kc + 1][0], ph[2 * kc + 1][1], r2, r3);
            }

        CP_WAIT(0);
        __syncthreads();
    }

    #pragma unroll
    for (int rp = 0; rp < 2; rp++) {
        float inv = __frcp_rn(lreg[rp]);
        int row = q0 + wr + g + rp * 8;
        __half* dst = attn + (long long)(b * 2048 + row) * 1024 + h * 64;
        #pragma unroll
        for (int v = 0; v < 8; v++) {
            __half2 hv = __floats2half2_rn(of[v][2 * rp] * inv,
                                           of[v][2 * rp + 1] * inv);
            *reinterpret_cast<unsigned*>(dst + v * 8 + 2 * t) = h2_as_u32(hv);
        }
    }
}

// ---------------------------------------------------------------------------
// Orchestration.
// ---------------------------------------------------------------------------
extern "C" void kernel_launch(void* const* d_in, const int* in_sizes, int n_in,
                              void* d_out, int out_size)
{
    (void)in_sizes; (void)n_in; (void)out_size;
    const float* x     = (const float*)d_in[0];
    const float* w_qkv = (const float*)d_in[1];
    const float* b_qkv = (const float*)d_in[2];
    const float* w_o   = (const float*)d_in[3];
    const float* b_o   = (const float*)d_in[4];
    float* out = (float*)d_out;

    __half *xh, *wqkvh, *woh, *qkvh, *attnh;
    cudaGetSymbolAddress((void**)&xh,    g_xh);
    cudaGetSymbolAddress((void**)&wqkvh, g_wqkvh);
    cudaGetSymbolAddress((void**)&woh,   g_woh);
    cudaGetSymbolAddress((void**)&qkvh,  g_qkvh);
    cudaGetSymbolAddress((void**)&attnh, g_attnh);

    cudaFuncSetAttribute(gemm_bias_f16_kernel<true>,
                         cudaFuncAttributeMaxDynamicSharedMemorySize, GEMM_SMEM);
    cudaFuncSetAttribute(gemm_bias_f16_kernel<false>,
                         cudaFuncAttributeMaxDynamicSharedMemorySize, GEMM_SMEM);
    cudaFuncSetAttribute(flash_attn_kernel,
                         cudaFuncAttributeMaxDynamicSharedMemorySize, FA_SMEM_BYTES);

    // 0) fused fp32->fp16 converts
    convert_all_kernel<<<4096, 256>>>(x, xh, w_qkv, wqkvh, w_o, woh);

    // 1) qkvh = xh @ wqkvh^T + b_qkv   (fp16 out)  grid (3072/64, 4096/128)
    gemm_bias_f16_kernel<true><<<dim3(48, 32), 128, GEMM_SMEM>>>(
        xh, wqkvh, b_qkv, qkvh, 1024, 1024, 3072, 1024);

    // 2) fused attention -> attnh (fp16)  grid (2048/64, B*H)
    flash_attn_kernel<<<dim3(32, 32), 128, FA_SMEM_BYTES>>>(qkvh, attnh);

    // 3) out = attnh @ woh^T + b_o     (fp32 out)  grid (1024/64, 4096/128)
    gemm_bias_f16_kernel<false><<<dim3(16, 32), 128, GEMM_SMEM>>>(
        attnh, woh, b_o, out, 1024, 1024, 1024, 1024);
}